// round 5
// baseline (speedup 1.0000x reference)
#include <cuda_runtime.h>
#include <cuda_bf16.h>
#include <math.h>
#include <stdint.h>

#define NN    3072
#define H     256
#define NB    4
#define HD    64
#define BH    1024   /* NB*H */

// ---------------- scratch (device globals) ----------------------------------
__device__ float          g_hn[NN * H];                       // 3 MB
__device__ __nv_bfloat16  g_kb_hi [NB * NN * HD];
__device__ __nv_bfloat16  g_kb_lo [NB * NN * HD];
__device__ __nv_bfloat16  g_mub   [NB * NN * HD];
__device__ __nv_bfloat16  g_lsb   [NB * NN * HD];
__device__ __nv_bfloat16  g_hnb_hi[(size_t)NN * H];
__device__ __nv_bfloat16  g_hnb_lo[(size_t)NN * H];
__device__ float          g_att[(size_t)NN * BH];             // 12.6 MB
__device__ double         g_kl;

// ---------------- PTX helpers ------------------------------------------------
__device__ __forceinline__ uint32_t smem_u32(const void* p) {
    uint32_t a;
    asm("{ .reg .u64 t; cvta.to.shared.u64 t, %1; cvt.u32.u64 %0, t; }"
        : "=r"(a) : "l"(p));
    return a;
}
__device__ __forceinline__ void cp16(uint32_t s, const void* g) {
    asm volatile("cp.async.cg.shared.global [%0], [%1], 16;" :: "r"(s), "l"(g));
}
#define CP_COMMIT() asm volatile("cp.async.commit_group;" ::: "memory")
#define CP_WAIT(n)  asm volatile("cp.async.wait_group %0;" :: "n"(n) : "memory")

#define LDSM_X4(r0, r1, r2, r3, addr) \
    asm volatile("ldmatrix.sync.aligned.m8n8.x4.shared.b16 {%0,%1,%2,%3}, [%4];" \
                 : "=r"(r0), "=r"(r1), "=r"(r2), "=r"(r3) : "r"(addr))

#define LDSM_X4_T(r0, r1, r2, r3, addr) \
    asm volatile("ldmatrix.sync.aligned.m8n8.x4.trans.shared.b16 {%0,%1,%2,%3}, [%4];" \
                 : "=r"(r0), "=r"(r1), "=r"(r2), "=r"(r3) : "r"(addr))

#define MMA_BF16(d, a, b0, b1) \
    asm volatile("mma.sync.aligned.m16n8k16.row.col.f32.bf16.bf16.f32 " \
                 "{%0,%1,%2,%3}, {%4,%5,%6,%7}, {%8,%9}, {%0,%1,%2,%3};" \
                 : "+f"((d)[0]), "+f"((d)[1]), "+f"((d)[2]), "+f"((d)[3]) \
                 : "r"((a)[0]), "r"((a)[1]), "r"((a)[2]), "r"((a)[3]), \
                   "r"(b0), "r"(b1))

// ---------------- init ------------------------------------------------------
__global__ void k_init() {
    if (blockIdx.x == 0 && threadIdx.x == 0) g_kl = 0.0;
}

// ---------------- layernorm -------------------------------------------------
__global__ void k_ln(const float* __restrict__ h,
                     const float* __restrict__ gamma,
                     const float* __restrict__ beta) {
    int row = blockIdx.x;
    int tid = threadIdx.x;
    float v = h[row * H + tid];

    __shared__ float red[8];
    float s = v;
    #pragma unroll
    for (int o = 16; o; o >>= 1) s += __shfl_xor_sync(0xffffffffu, s, o);
    if ((tid & 31) == 0) red[tid >> 5] = s;
    __syncthreads();
    float mean = 0.f;
    #pragma unroll
    for (int i = 0; i < 8; i++) mean += red[i];
    mean *= (1.0f / H);

    float d = v - mean;
    float q = d * d;
    #pragma unroll
    for (int o = 16; o; o >>= 1) q += __shfl_xor_sync(0xffffffffu, q, o);
    __syncthreads();
    if ((tid & 31) == 0) red[tid >> 5] = q;
    __syncthreads();
    float var = 0.f;
    #pragma unroll
    for (int i = 0; i < 8; i++) var += red[i];
    var *= (1.0f / H);

    g_hn[row * H + tid] = d * rsqrtf(var + 1e-5f) * gamma[tid] + beta[tid];
}

// ---------------- hn -> bf16 hi/lo split --------------------------------------
__global__ void k_hnb() {
    int i = blockIdx.x * 256 + threadIdx.x;
    float v = g_hn[i];
    __nv_bfloat16 hi = __float2bfloat16(v);
    g_hnb_hi[i] = hi;
    g_hnb_lo[i] = __float2bfloat16(v - __bfloat162float(hi));
}

// ---------------- projections (fp32 SIMT) -------------------------------------
__global__ void __launch_bounds__(256) k_proj(
    const float* __restrict__ Wk, const float* __restrict__ bk,
    const float* __restrict__ Wm, const float* __restrict__ bm,
    const float* __restrict__ Wl, const float* __restrict__ bl)
{
    __shared__ float As[64][68];
    __shared__ float Bs[64][64];

    int mat = blockIdx.y >> 2;
    const float* W    = (mat == 0) ? Wk : (mat == 1) ? Wm : Wl;
    const float* bias = (mat == 0) ? bk : (mat == 1) ? bm : bl;
    float scl = (mat == 0) ? 0.125f : 1.0f;   // fold HD^-0.5 into k

    int m0 = blockIdx.x * 64;
    int j0 = (blockIdx.y & 3) * 64;
    int tid = threadIdx.x;
    int tx = tid & 15, ty = tid >> 4;

    float acc[4][4] = {};

    for (int kk = 0; kk < H; kk += 64) {
        for (int i = tid; i < 64 * 16; i += 256) {
            int r = i >> 4, c = (i & 15) << 2;
            *(float4*)&As[r][c] = *(const float4*)&g_hn[(size_t)(m0 + r) * H + kk + c];
            *(float4*)&Bs[r][c] = *(const float4*)&W[(size_t)(kk + r) * H + j0 + c];
        }
        __syncthreads();
        #pragma unroll 8
        for (int k = 0; k < 64; k++) {
            float a[4], b[4];
            #pragma unroll
            for (int i = 0; i < 4; i++) a[i] = As[ty + 16 * i][k];
            #pragma unroll
            for (int j = 0; j < 4; j++) b[j] = Bs[k][tx + 16 * j];
            #pragma unroll
            for (int i = 0; i < 4; i++)
                #pragma unroll
                for (int j = 0; j < 4; j++)
                    acc[i][j] = fmaf(a[i], b[j], acc[i][j]);
        }
        __syncthreads();
    }

    #pragma unroll
    for (int i = 0; i < 4; i++) {
        int m = m0 + ty + 16 * i;
        #pragma unroll
        for (int j = 0; j < 4; j++) {
            int jc = j0 + tx + 16 * j;
            float v = (acc[i][j] + bias[jc]) * scl;
            int hb = jc & 3, dd = jc >> 2;   // reshape(N, HD, B)
            size_t o = ((size_t)hb * NN + m) * HD + dd;
            if (mat == 0) {
                __nv_bfloat16 hi = __float2bfloat16(v);
                g_kb_hi[o] = hi;
                g_kb_lo[o] = __float2bfloat16(v - __bfloat162float(hi));
            } else if (mat == 1) {
                g_mub[o] = __float2bfloat16(v);
            } else {
                g_lsb[o] = __float2bfloat16(v);
            }
        }
    }
}

// ---------------- FUSED scores+sample+aggregation -----------------------------
// grid (NB, 24): CTA owns (head b, 128 x-rows). Loops 48 y-tiles of 64:
//   scores mma (k split-bf16 x mu/ls bf16) -> softplus/KL/exp -> a bf16 smem
//   -> agg mma (a x hn hi/lo) into persistent fp32 accumulators.
// 256 threads = 8 warps. Scores layout 4m x 2n (warp 32x32). Agg 2m x 4n (64x64).
#define OFF_KH   0
#define OFF_KL   18432
#define OFF_MU0  36864                       /* per buf: mu 9216 + ls 9216 */
#define MU_STRIDE 18432
#define OFF_HN0  73728                       /* per buf: hnh 33792 + hnl 33792 */
#define HN_STRIDE 67584
#define OFF_A    208896                      /* 128*144 */
#define OFF_SDEN 227328                      /* 128 floats */
#define OFF_KRED 227840
#define FUSED_SMEM 227904

__device__ __forceinline__ void fused_load_tile(uint32_t sb, char buf, int yt,
                                                int tid, int b)
{
    const __nv_bfloat16* MU = g_mub + ((size_t)b * NN + yt) * HD;
    const __nv_bfloat16* LS = g_lsb + ((size_t)b * NN + yt) * HD;
    int lc = tid & 7, lr0 = tid >> 3;
    uint32_t mb = sb + OFF_MU0 + buf * MU_STRIDE;
    #pragma unroll
    for (int p = 0; p < 2; p++) {
        int r = lr0 + p * 32;
        cp16(mb + r * 144 + lc * 16,        MU + (size_t)r * HD + lc * 8);
        cp16(mb + 9216 + r * 144 + lc * 16, LS + (size_t)r * HD + lc * 8);
    }
    int lcb = tid & 31, lkr = tid >> 5;
    uint32_t hb = sb + OFF_HN0 + buf * HN_STRIDE;
    #pragma unroll
    for (int p = 0; p < 8; p++) {
        int r = lkr + p * 8;
        cp16(hb + r * 528 + lcb * 16,         g_hnb_hi + (size_t)(yt + r) * H + lcb * 8);
        cp16(hb + 33792 + r * 528 + lcb * 16, g_hnb_lo + (size_t)(yt + r) * H + lcb * 8);
    }
}

__global__ void __launch_bounds__(256, 1) k_fused(const float* __restrict__ diffusion,
                                                  const float* __restrict__ eps)
{
    extern __shared__ char smc[];
    uint32_t sb = smem_u32(smc);

    int tid = threadIdx.x, lane = tid & 31, wid = tid >> 5;
    int b  = blockIdx.x;
    int x0 = blockIdx.y * 128;

    if (tid < 128) *(float*)(smc + OFF_SDEN + tid * 4) = 0.f;

    // ---- prologue: K resident + tile0 ----
    {
        const __nv_bfloat16* Kh = g_kb_hi + ((size_t)b * NN + x0) * HD;
        const __nv_bfloat16* Kl = g_kb_lo + ((size_t)b * NN + x0) * HD;
        int lc = tid & 7, lr0 = tid >> 3;
        #pragma unroll
        for (int p = 0; p < 4; p++) {
            int r = lr0 + p * 32;
            cp16(sb + OFF_KH + r * 144 + lc * 16, Kh + (size_t)r * HD + lc * 8);
            cp16(sb + OFF_KL + r * 144 + lc * 16, Kl + (size_t)r * HD + lc * 8);
        }
        fused_load_tile(sb, 0, 0, tid, b);
        CP_COMMIT();
    }

    // scores warp layout
    int wm = (wid & 3) * 32, wn = (wid >> 2) * 32;
    int rA  = wm + (lane & 15);
    int cA8 = lane >> 4;
    int rB  = wn + (lane & 7) + 8 * ((lane >> 3) & 1);
    int cB8 = lane >> 4;

    // agg warp layout
    int wmA = (wid & 1) * 64, wnA = (wid >> 1) * 64;
    int rowA2 = wmA + (lane & 15);
    int achnk = lane >> 4;
    int kB    = (lane & 7) + 8 * ((lane >> 3) & 1);
    int noffB = (wnA + ((lane >> 4) & 1) * 8) * 2;

    float d[4][8][4] = {};
    float rsum[2][2] = {{0.f, 0.f}, {0.f, 0.f}};
    float klsum = 0.f;

    for (int t = 0; t < 48; t++) {
        __syncthreads();                       // prev iter fully done
        if (t + 1 < 48) fused_load_tile(sb, (t + 1) & 1, (t + 1) * 64, tid, b);
        CP_COMMIT();
        CP_WAIT(1);                            // tile t (and K) resident
        __syncthreads();

        uint32_t mb = sb + OFF_MU0 + (t & 1) * MU_STRIDE;

        // ---- scores: 128x64 tile ----
        float accm[2][4][4] = {}, accl[2][4][4] = {};
        #pragma unroll
        for (int s = 0; s < 4; s++) {
            uint32_t kh[2][4], kl[2][4];
            #pragma unroll
            for (int mi = 0; mi < 2; mi++) {
                uint32_t a = sb + OFF_KH + (rA + mi * 16) * 144 + s * 32 + cA8 * 16;
                LDSM_X4(kh[mi][0], kh[mi][1], kh[mi][2], kh[mi][3], a);
                LDSM_X4(kl[mi][0], kl[mi][1], kl[mi][2], kl[mi][3], a + (OFF_KL - OFF_KH));
            }
            uint32_t mh[2][4], lh[2][4];
            #pragma unroll
            for (int g = 0; g < 2; g++) {
                uint32_t ba = mb + (rB + g * 16) * 144 + s * 32 + cB8 * 16;
                LDSM_X4(mh[g][0], mh[g][1], mh[g][2], mh[g][3], ba);
                LDSM_X4(lh[g][0], lh[g][1], lh[g][2], lh[g][3], ba + 9216);
            }
            #pragma unroll
            for (int mi = 0; mi < 2; mi++)
                #pragma unroll
                for (int g = 0; g < 2; g++)
                    #pragma unroll
                    for (int nn = 0; nn < 2; nn++) {
                        int n8 = g * 2 + nn;
                        MMA_BF16(accm[mi][n8], kh[mi], mh[g][nn], mh[g][nn + 2]);
                        MMA_BF16(accm[mi][n8], kl[mi], mh[g][nn], mh[g][nn + 2]);
                        MMA_BF16(accl[mi][n8], kh[mi], lh[g][nn], lh[g][nn + 2]);
                        MMA_BF16(accl[mi][n8], kl[mi], lh[g][nn], lh[g][nn + 2]);
                    }
        }

        // ---- elementwise -> a bf16 tile ----
        int y0 = t * 64;
        #pragma unroll
        for (int mi = 0; mi < 2; mi++) {
            #pragma unroll
            for (int n8 = 0; n8 < 4; n8++) {
                int yl = wn + n8 * 8 + 2 * (lane & 3);
                #pragma unroll
                for (int hf = 0; hf < 2; hf++) {
                    int xl = wm + mi * 16 + hf * 8 + (lane >> 2);
                    size_t xy = (size_t)(x0 + xl) * NN + (y0 + yl);
                    float2 dif = *(const float2*)&diffusion[xy];
                    float e0 = eps[xy * NB + b];
                    float e1 = eps[(xy + 1) * NB + b];
                    float smu0 = accm[mi][n8][hf * 2],     sls0 = accl[mi][n8][hf * 2];
                    float smu1 = accm[mi][n8][hf * 2 + 1], sls1 = accl[mi][n8][hf * 2 + 1];
                    float sig0 = fmaxf(sls0, 0.f) + log1pf(__expf(-fabsf(sls0)));
                    float sig1 = fmaxf(sls1, 0.f) + log1pf(__expf(-fabsf(sls1)));
                    float kle0 = 0.5f * (sig0 * sig0 + smu0 * smu0) - __logf(sig0) - 0.5f;
                    float kle1 = 0.5f * (sig1 * sig1 + smu1 * smu1) - __logf(sig1) - 0.5f;
                    float sg0 = (dif.x > 0.f) ? 1.f : ((dif.x < 0.f) ? -1.f : 0.f);
                    float sg1 = (dif.y > 0.f) ? 1.f : ((dif.y < 0.f) ? -1.f : 0.f);
                    klsum += kle0 * sg0 + kle1 * sg1;
                    float a0 = __expf(smu0 + sig0 * e0) * dif.x;
                    float a1 = __expf(smu1 + sig1 * e1) * dif.y;
                    rsum[mi][hf] += fabsf(a0) + fabsf(a1);
                    __nv_bfloat162 av;
                    av.x = __float2bfloat16(a0);
                    av.y = __float2bfloat16(a1);
                    *(__nv_bfloat162*)(smc + OFF_A + xl * 144 + yl * 2) = av;
                }
            }
        }

        __syncthreads();   // a tile complete

        // ---- aggregation: d += a @ hn ----
        uint32_t hb = sb + OFF_HN0 + (t & 1) * HN_STRIDE;
        #pragma unroll
        for (int s = 0; s < 4; s++) {
            uint32_t ah[4][4];
            #pragma unroll
            for (int mi = 0; mi < 4; mi++) {
                uint32_t aa = sb + OFF_A + (rowA2 + mi * 16) * 144 + s * 32 + achnk * 16;
                LDSM_X4(ah[mi][0], ah[mi][1], ah[mi][2], ah[mi][3], aa);
            }
            #pragma unroll
            for (int j = 0; j < 4; j++) {
                uint32_t bh[4], bl[4];
                uint32_t ba = hb + (s * 16 + kB) * 528 + noffB + j * 32;
                LDSM_X4_T(bh[0], bh[1], bh[2], bh[3], ba);
                LDSM_X4_T(bl[0], bl[1], bl[2], bl[3], ba + 33792);
                #pragma unroll
                for (int mi = 0; mi < 4; mi++)
                    #pragma unroll
                    for (int nn = 0; nn < 2; nn++) {
                        int j8 = j * 2 + nn, br = nn * 2;
                        MMA_BF16(d[mi][j8], ah[mi], bh[br], bh[br + 1]);
                        MMA_BF16(d[mi][j8], ah[mi], bl[br], bl[br + 1]);
                    }
            }
        }
    }

    // ---- denom reduce (scores layout rows) ----
    float* sden = (float*)(smc + OFF_SDEN);
    __syncthreads();
    #pragma unroll
    for (int mi = 0; mi < 2; mi++)
        #pragma unroll
        for (int hf = 0; hf < 2; hf++) {
            float r = rsum[mi][hf];
            r += __shfl_xor_sync(0xffffffffu, r, 1);
            r += __shfl_xor_sync(0xffffffffu, r, 2);
            if ((lane & 3) == 0)
                atomicAdd(&sden[wm + mi * 16 + hf * 8 + (lane >> 2)], r);
        }

    // ---- KL reduce ----
    #pragma unroll
    for (int o = 16; o; o >>= 1) klsum += __shfl_xor_sync(0xffffffffu, klsum, o);
    if (lane == 0) ((float*)(smc + OFF_KRED))[wid] = klsum;
    __syncthreads();
    if (tid == 0) {
        float s = 0.f;
        #pragma unroll
        for (int i = 0; i < 8; i++) s += ((float*)(smc + OFF_KRED))[i];
        atomicAdd(&g_kl, (double)s);
    }

    // ---- epilogue: normalize + store (agg layout) ----
    #pragma unroll
    for (int mi = 0; mi < 4; mi++) {
        int rl0 = wmA + mi * 16 + (lane >> 2);
        float invd0 = 1.0f / fmaxf(sden[rl0],     1e-12f);
        float invd1 = 1.0f / fmaxf(sden[rl0 + 8], 1e-12f);
        #pragma unroll
        for (int j8 = 0; j8 < 8; j8++) {
            int col = b * 256 + wnA + j8 * 8 + 2 * (lane & 3);
            float2 v0 = make_float2(d[mi][j8][0] * invd0, d[mi][j8][1] * invd0);
            float2 v1 = make_float2(d[mi][j8][2] * invd1, d[mi][j8][3] * invd1);
            *(float2*)&g_att[(size_t)(x0 + rl0) * BH + col]       = v0;
            *(float2*)&g_att[(size_t)(x0 + rl0 + 8) * BH + col]   = v1;
        }
    }
}

// ---------------- fc_v + elu + residual -------------------------------------
__global__ void __launch_bounds__(256) k_fc(const float* __restrict__ Wv,
                                            const float* __restrict__ bv,
                                            const float* __restrict__ h0,
                                            float* __restrict__ out)
{
    extern __shared__ float sm[];
    float (*As)[68]  = (float(*)[68])sm;
    float (*Bs)[128] = (float(*)[128])(sm + 128 * 68);

    int x0 = blockIdx.x * 128;
    int c0 = blockIdx.y * 128;
    int tid = threadIdx.x;
    int tx = tid & 15, ty = tid >> 4;

    float acc[8][8] = {};

    for (int kk = 0; kk < BH; kk += 64) {
        for (int i = tid; i < 128 * 16; i += 256) {
            int r = i >> 4, c = (i & 15) << 2;
            *(float4*)&As[r][c] = *(const float4*)&g_att[(size_t)(x0 + r) * BH + kk + c];
        }
        for (int i = tid; i < 64 * 32; i += 256) {
            int r = i >> 5, c = (i & 31) << 2;
            *(float4*)&Bs[r][c] = *(const float4*)&Wv[(size_t)(kk + r) * H + c0 + c];
        }
        __syncthreads();
        #pragma unroll 4
        for (int k = 0; k < 64; k++) {
            float av[8];
            #pragma unroll
            for (int i = 0; i < 8; i++) av[i] = As[ty * 8 + i][k];
            float4 b0 = *(const float4*)&Bs[k][tx * 4];
            float4 b1 = *(const float4*)&Bs[k][64 + tx * 4];
            #pragma unroll
            for (int i = 0; i < 8; i++) {
                acc[i][0] = fmaf(av[i], b0.x, acc[i][0]);
                acc[i][1] = fmaf(av[i], b0.y, acc[i][1]);
                acc[i][2] = fmaf(av[i], b0.z, acc[i][2]);
                acc[i][3] = fmaf(av[i], b0.w, acc[i][3]);
                acc[i][4] = fmaf(av[i], b1.x, acc[i][4]);
                acc[i][5] = fmaf(av[i], b1.y, acc[i][5]);
                acc[i][6] = fmaf(av[i], b1.z, acc[i][6]);
                acc[i][7] = fmaf(av[i], b1.w, acc[i][7]);
            }
        }
        __syncthreads();
    }

    #pragma unroll
    for (int i = 0; i < 8; i++) {
        int x = x0 + ty * 8 + i;
        #pragma unroll
        for (int half = 0; half < 2; half++) {
            float4 v;
            float* a = &acc[i][half * 4];
            int col = c0 + half * 64 + tx * 4;
            float r0 = a[0] + bv[col + 0];
            float r1 = a[1] + bv[col + 1];
            float r2 = a[2] + bv[col + 2];
            float r3 = a[3] + bv[col + 3];
            r0 = (r0 > 0.f) ? r0 : expm1f(r0);
            r1 = (r1 > 0.f) ? r1 : expm1f(r1);
            r2 = (r2 > 0.f) ? r2 : expm1f(r2);
            r3 = (r3 > 0.f) ? r3 : expm1f(r3);
            v.x = r0 + h0[(size_t)x * H + col + 0];
            v.y = r1 + h0[(size_t)x * H + col + 1];
            v.z = r2 + h0[(size_t)x * H + col + 2];
            v.w = r3 + h0[(size_t)x * H + col + 3];
            *(float4*)&out[(size_t)x * H + col] = v;
        }
    }
}

// ---------------- kl scalar output ------------------------------------------
__global__ void k_klout(float* __restrict__ out, int out_size) {
    if (threadIdx.x == 0 && out_size > NN * H) {
        out[out_size - 1] = (float)(g_kl / (double)((size_t)NN * NN));
    }
}

// ---------------- launch -----------------------------------------------------
extern "C" void kernel_launch(void* const* d_in, const int* in_sizes, int n_in,
                              void* d_out, int out_size)
{
    const float* h     = (const float*)d_in[0];
    const float* gamma = (const float*)d_in[1];
    const float* beta  = (const float*)d_in[2];
    const float* Wk    = (const float*)d_in[3];
    const float* bk    = (const float*)d_in[4];
    const float* Wm    = (const float*)d_in[5];
    const float* bm    = (const float*)d_in[6];
    const float* Wl    = (const float*)d_in[7];
    const float* bl    = (const float*)d_in[8];
    const float* Wv    = (const float*)d_in[9];
    const float* bv    = (const float*)d_in[10];
    const float* diff  = (const float*)d_in[11];
    const float* eps   = (const float*)d_in[12];
    float* out = (float*)d_out;

    const int smem_fc = (128 * 68 + 64 * 128) * 4;
    cudaFuncSetAttribute(k_fused, cudaFuncAttributeMaxDynamicSharedMemorySize, FUSED_SMEM);
    cudaFuncSetAttribute(k_fc,    cudaFuncAttributeMaxDynamicSharedMemorySize, smem_fc);

    k_init<<<1, 32>>>();
    k_ln<<<NN, 256>>>(h, gamma, beta);
    k_hnb<<<NN, 256>>>();
    k_proj<<<dim3(48, 12), 256>>>(Wk, bk, Wm, bm, Wl, bl);
    k_fused<<<dim3(NB, 24), 256, FUSED_SMEM>>>(diff, eps);
    k_fc<<<dim3(24, 2), 256, smem_fc>>>(Wv, bv, h, out);
    k_klout<<<1, 32>>>(out, out_size);
}

// round 6
// speedup vs baseline: 1.4085x; 1.4085x over previous
#include <cuda_runtime.h>
#include <cuda_bf16.h>
#include <math.h>
#include <stdint.h>

#define NN    3072
#define H     256
#define NB    4
#define HD    64
#define BH    1024   /* NB*H */

// ---------------- scratch (device globals) ----------------------------------
__device__ float          g_hn[NN * H];                       // 3 MB
__device__ __nv_bfloat16  g_kb_hi [NB * NN * HD];
__device__ __nv_bfloat16  g_kb_lo [NB * NN * HD];
__device__ __nv_bfloat16  g_mub   [NB * NN * HD];
__device__ __nv_bfloat16  g_lsb   [NB * NN * HD];
__device__ __nv_bfloat16  g_a     [(size_t)NB * NN * NN];     // 75.5 MB
__device__ __nv_bfloat16  g_hnb_hi[(size_t)NN * H];
__device__ __nv_bfloat16  g_hnb_lo[(size_t)NN * H];
__device__ float          g_att[(size_t)NN * BH];             // 12.6 MB
__device__ float          g_denom[NB * NN];
__device__ double         g_kl;

// ---------------- PTX helpers ------------------------------------------------
__device__ __forceinline__ uint32_t smem_u32(const void* p) {
    uint32_t a;
    asm("{ .reg .u64 t; cvta.to.shared.u64 t, %1; cvt.u32.u64 %0, t; }"
        : "=r"(a) : "l"(p));
    return a;
}
__device__ __forceinline__ void cp16(uint32_t s, const void* g) {
    asm volatile("cp.async.cg.shared.global [%0], [%1], 16;" :: "r"(s), "l"(g));
}
#define CP_COMMIT() asm volatile("cp.async.commit_group;" ::: "memory")
#define CP_WAIT(n)  asm volatile("cp.async.wait_group %0;" :: "n"(n) : "memory")

#define LDSM_X4(r0, r1, r2, r3, addr) \
    asm volatile("ldmatrix.sync.aligned.m8n8.x4.shared.b16 {%0,%1,%2,%3}, [%4];" \
                 : "=r"(r0), "=r"(r1), "=r"(r2), "=r"(r3) : "r"(addr))

#define LDSM_X4_T(r0, r1, r2, r3, addr) \
    asm volatile("ldmatrix.sync.aligned.m8n8.x4.trans.shared.b16 {%0,%1,%2,%3}, [%4];" \
                 : "=r"(r0), "=r"(r1), "=r"(r2), "=r"(r3) : "r"(addr))

#define MMA_BF16(d, a, b0, b1) \
    asm volatile("mma.sync.aligned.m16n8k16.row.col.f32.bf16.bf16.f32 " \
                 "{%0,%1,%2,%3}, {%4,%5,%6,%7}, {%8,%9}, {%0,%1,%2,%3};" \
                 : "+f"((d)[0]), "+f"((d)[1]), "+f"((d)[2]), "+f"((d)[3]) \
                 : "r"((a)[0]), "r"((a)[1]), "r"((a)[2]), "r"((a)[3]), \
                   "r"(b0), "r"(b1))

// ---------------- init ------------------------------------------------------
__global__ void k_init() {
    int t = blockIdx.x * 256 + threadIdx.x;
    if (t < NB * NN) g_denom[t] = 0.0f;
    if (t == 0) g_kl = 0.0;
}

// ---------------- layernorm -------------------------------------------------
__global__ void k_ln(const float* __restrict__ h,
                     const float* __restrict__ gamma,
                     const float* __restrict__ beta) {
    int row = blockIdx.x;
    int tid = threadIdx.x;
    float v = h[row * H + tid];

    __shared__ float red[8];
    float s = v;
    #pragma unroll
    for (int o = 16; o; o >>= 1) s += __shfl_xor_sync(0xffffffffu, s, o);
    if ((tid & 31) == 0) red[tid >> 5] = s;
    __syncthreads();
    float mean = 0.f;
    #pragma unroll
    for (int i = 0; i < 8; i++) mean += red[i];
    mean *= (1.0f / H);

    float d = v - mean;
    float q = d * d;
    #pragma unroll
    for (int o = 16; o; o >>= 1) q += __shfl_xor_sync(0xffffffffu, q, o);
    __syncthreads();
    if ((tid & 31) == 0) red[tid >> 5] = q;
    __syncthreads();
    float var = 0.f;
    #pragma unroll
    for (int i = 0; i < 8; i++) var += red[i];
    var *= (1.0f / H);

    g_hn[row * H + tid] = d * rsqrtf(var + 1e-5f) * gamma[tid] + beta[tid];
}

// ---------------- hn -> bf16 hi/lo split --------------------------------------
__global__ void k_hnb() {
    int i = blockIdx.x * 256 + threadIdx.x;
    float v = g_hn[i];
    __nv_bfloat16 hi = __float2bfloat16(v);
    g_hnb_hi[i] = hi;
    g_hnb_lo[i] = __float2bfloat16(v - __bfloat162float(hi));
}

// ---------------- projections (fp32 SIMT) -------------------------------------
__global__ void __launch_bounds__(256) k_proj(
    const float* __restrict__ Wk, const float* __restrict__ bk,
    const float* __restrict__ Wm, const float* __restrict__ bm,
    const float* __restrict__ Wl, const float* __restrict__ bl)
{
    __shared__ float As[64][68];
    __shared__ float Bs[64][64];

    int mat = blockIdx.y >> 2;
    const float* W    = (mat == 0) ? Wk : (mat == 1) ? Wm : Wl;
    const float* bias = (mat == 0) ? bk : (mat == 1) ? bm : bl;
    float scl = (mat == 0) ? 0.125f : 1.0f;   // fold HD^-0.5 into k

    int m0 = blockIdx.x * 64;
    int j0 = (blockIdx.y & 3) * 64;
    int tid = threadIdx.x;
    int tx = tid & 15, ty = tid >> 4;

    float acc[4][4] = {};

    for (int kk = 0; kk < H; kk += 64) {
        for (int i = tid; i < 64 * 16; i += 256) {
            int r = i >> 4, c = (i & 15) << 2;
            *(float4*)&As[r][c] = *(const float4*)&g_hn[(size_t)(m0 + r) * H + kk + c];
            *(float4*)&Bs[r][c] = *(const float4*)&W[(size_t)(kk + r) * H + j0 + c];
        }
        __syncthreads();
        #pragma unroll 8
        for (int k = 0; k < 64; k++) {
            float a[4], b[4];
            #pragma unroll
            for (int i = 0; i < 4; i++) a[i] = As[ty + 16 * i][k];
            #pragma unroll
            for (int j = 0; j < 4; j++) b[j] = Bs[k][tx + 16 * j];
            #pragma unroll
            for (int i = 0; i < 4; i++)
                #pragma unroll
                for (int j = 0; j < 4; j++)
                    acc[i][j] = fmaf(a[i], b[j], acc[i][j]);
        }
        __syncthreads();
    }

    #pragma unroll
    for (int i = 0; i < 4; i++) {
        int m = m0 + ty + 16 * i;
        #pragma unroll
        for (int j = 0; j < 4; j++) {
            int jc = j0 + tx + 16 * j;
            float v = (acc[i][j] + bias[jc]) * scl;
            int hb = jc & 3, dd = jc >> 2;   // reshape(N, HD, B)
            size_t o = ((size_t)hb * NN + m) * HD + dd;
            if (mat == 0) {
                __nv_bfloat16 hi = __float2bfloat16(v);
                g_kb_hi[o] = hi;
                g_kb_lo[o] = __float2bfloat16(v - __bfloat162float(hi));
            } else if (mat == 1) {
                g_mub[o] = __float2bfloat16(v);
            } else {
                g_lsb[o] = __float2bfloat16(v);
            }
        }
    }
}

// ---------------- scores via tensor cores + elementwise -> a (bf16) ----------
// grid (NB, 48, 48): 64x64 tile per CTA, 128 thr = 4 warps (2m x 2n, warp 32x32)
// smem: K hi/lo (x-tile), MU, LS (y-tile) — 64 rows x 144B each = 4*9216
#define SC_ROW 144
#define SC_HALF (64 * SC_ROW)     /* 9216 */
#define SC_SMEM (4 * SC_HALF)     /* 36864 */

__global__ void __launch_bounds__(128) k_scores_mma(const float* __restrict__ diffusion,
                                                    const float* __restrict__ eps)
{
    extern __shared__ char smc[];
    uint32_t sb = smem_u32(smc);

    int b  = blockIdx.x;
    int x0 = blockIdx.y * 64;
    int y0 = blockIdx.z * 64;
    int tid = threadIdx.x, lane = tid & 31, wid = tid >> 5;
    int warp_m = (wid & 1) * 32, warp_n = (wid >> 1) * 32;

    const __nv_bfloat16* Kh = g_kb_hi + ((size_t)b * NN + x0) * HD;
    const __nv_bfloat16* Kl = g_kb_lo + ((size_t)b * NN + x0) * HD;
    const __nv_bfloat16* MU = g_mub   + ((size_t)b * NN + y0) * HD;
    const __nv_bfloat16* LS = g_lsb   + ((size_t)b * NN + y0) * HD;

    {
        int lc = tid & 7, lr = tid >> 3;      // chunk 0-7 (128B/row), row 0-15
        #pragma unroll
        for (int p = 0; p < 4; p++) {
            int r = lr + p * 16;
            uint32_t so = r * SC_ROW + lc * 16;
            size_t  go = (size_t)r * HD + lc * 8;
            cp16(sb + 0 * SC_HALF + so, Kh + go);
            cp16(sb + 1 * SC_HALF + so, Kl + go);
            cp16(sb + 2 * SC_HALF + so, MU + go);
            cp16(sb + 3 * SC_HALF + so, LS + go);
        }
    }
    CP_COMMIT(); CP_WAIT(0);
    __syncthreads();

    float accm[2][4][4] = {}, accl[2][4][4] = {};
    int rA  = warp_m + (lane & 15);
    int cA8 = lane >> 4;
    int rB  = warp_n + (lane & 7) + 8 * ((lane >> 3) & 1);
    int cB8 = lane >> 4;

    #pragma unroll
    for (int s = 0; s < 4; s++) {
        uint32_t kh[2][4], kl[2][4];
        #pragma unroll
        for (int mi = 0; mi < 2; mi++) {
            uint32_t a = sb + (rA + mi * 16) * SC_ROW + s * 32 + cA8 * 16;
            LDSM_X4(kh[mi][0], kh[mi][1], kh[mi][2], kh[mi][3], a);
            LDSM_X4(kl[mi][0], kl[mi][1], kl[mi][2], kl[mi][3], a + SC_HALF);
        }
        uint32_t mh[2][4], lh[2][4];
        #pragma unroll
        for (int g = 0; g < 2; g++) {
            uint32_t bm = sb + 2 * SC_HALF + (rB + g * 16) * SC_ROW + s * 32 + cB8 * 16;
            LDSM_X4(mh[g][0], mh[g][1], mh[g][2], mh[g][3], bm);
            LDSM_X4(lh[g][0], lh[g][1], lh[g][2], lh[g][3], bm + SC_HALF);
        }
        #pragma unroll
        for (int mi = 0; mi < 2; mi++)
            #pragma unroll
            for (int g = 0; g < 2; g++)
                #pragma unroll
                for (int nn = 0; nn < 2; nn++) {
                    int n8 = g * 2 + nn;
                    MMA_BF16(accm[mi][n8], kh[mi], mh[g][nn], mh[g][nn + 2]);
                    MMA_BF16(accm[mi][n8], kl[mi], mh[g][nn], mh[g][nn + 2]);
                    MMA_BF16(accl[mi][n8], kh[mi], lh[g][nn], lh[g][nn + 2]);
                    MMA_BF16(accl[mi][n8], kl[mi], lh[g][nn], lh[g][nn + 2]);
                }
    }

    __syncthreads();   // tiles dead — reuse [0, SC_HALF) as bf16 staging

    float klsum = 0.f;
    float rsum[2][2] = {{0.f, 0.f}, {0.f, 0.f}};

    #pragma unroll
    for (int mi = 0; mi < 2; mi++) {
        int xl0 = warp_m + mi * 16 + (lane >> 2);
        #pragma unroll
        for (int n8 = 0; n8 < 4; n8++) {
            int yl = warp_n + n8 * 8 + 2 * (lane & 3);
            #pragma unroll
            for (int hf = 0; hf < 2; hf++) {
                int xl = xl0 + hf * 8;
                size_t xy = (size_t)(x0 + xl) * NN + (y0 + yl);
                float2 dif = *(const float2*)&diffusion[xy];
                float e0 = eps[xy * NB + b];
                float e1 = eps[(xy + 1) * NB + b];
                float smu0 = accm[mi][n8][hf * 2],     sls0 = accl[mi][n8][hf * 2];
                float smu1 = accm[mi][n8][hf * 2 + 1], sls1 = accl[mi][n8][hf * 2 + 1];
                float sig0 = fmaxf(sls0, 0.f) + log1pf(__expf(-fabsf(sls0)));
                float sig1 = fmaxf(sls1, 0.f) + log1pf(__expf(-fabsf(sls1)));
                float kle0 = 0.5f * (sig0 * sig0 + smu0 * smu0) - __logf(sig0) - 0.5f;
                float kle1 = 0.5f * (sig1 * sig1 + smu1 * smu1) - __logf(sig1) - 0.5f;
                float sg0 = (dif.x > 0.f) ? 1.f : ((dif.x < 0.f) ? -1.f : 0.f);
                float sg1 = (dif.y > 0.f) ? 1.f : ((dif.y < 0.f) ? -1.f : 0.f);
                klsum += kle0 * sg0 + kle1 * sg1;
                float a0 = __expf(smu0 + sig0 * e0) * dif.x;
                float a1 = __expf(smu1 + sig1 * e1) * dif.y;
                __nv_bfloat162 av;
                av.x = __float2bfloat16(a0);
                av.y = __float2bfloat16(a1);
                // denom from the ROUNDED values agg will actually sum
                rsum[mi][hf] += fabsf(__bfloat162float(av.x)) + fabsf(__bfloat162float(av.y));
                *(__nv_bfloat162*)(smc + xl * SC_ROW + yl * 2) = av;
            }
        }
    }

    // per-row denominators
    #pragma unroll
    for (int mi = 0; mi < 2; mi++)
        #pragma unroll
        for (int hf = 0; hf < 2; hf++) {
            float r = rsum[mi][hf];
            r += __shfl_xor_sync(0xffffffffu, r, 1);
            r += __shfl_xor_sync(0xffffffffu, r, 2);
            if ((lane & 3) == 0)
                atomicAdd(&g_denom[b * NN + x0 + warp_m + mi * 16 + hf * 8 + (lane >> 2)], r);
        }

    // KL
    #pragma unroll
    for (int o = 16; o; o >>= 1) klsum += __shfl_xor_sync(0xffffffffu, klsum, o);
    __shared__ float kred[4];
    if (lane == 0) kred[wid] = klsum;
    __syncthreads();
    if (tid == 0) {
        atomicAdd(&g_kl, (double)(kred[0] + kred[1] + kred[2] + kred[3]));
    }

    // coalesced copy-out
    __nv_bfloat16* dst = g_a + (size_t)b * NN * NN;
    for (int t = tid; t < 512; t += 128) {
        int r = t >> 3, c = t & 7;
        size_t go = (size_t)(x0 + r) * NN + y0 + c * 8;
        *(float4*)&dst[go] = *(float4*)(smc + r * SC_ROW + c * 16);
    }
}

// ---------------- aggregation: a(bf16) x hn(hi/lo) mma, CTA 128x256 -----------
#define A_BYTES  10240                      /* 128*80 */
#define B_HALF   16896                      /* 32*528 */
#define ST_B_OFF A_BYTES
#define STAGE_BYTES (A_BYTES + 2 * B_HALF)  /* 44032 */
#define NSTAGE   3
#define AGG_SMEM (NSTAGE * STAGE_BYTES)     /* 132096 */

__device__ __forceinline__ void agg_load_stage(
    uint32_t st, int kk, int x0, const __nv_bfloat16* A,
    int lc, int lr, int lcb, int lkr)
{
    #pragma unroll
    for (int p = 0; p < 2; p++) {
        int r = lr + p * 64;
        cp16(st + r * 80 + lc * 16, A + (size_t)(x0 + r) * NN + kk + lc * 8);
    }
    #pragma unroll
    for (int p = 0; p < 4; p++) {
        int kr = lkr + p * 8;
        uint32_t so = kr * 528 + lcb * 16;
        size_t  go = (size_t)(kk + kr) * H + lcb * 8;
        cp16(st + ST_B_OFF + so,          g_hnb_hi + go);
        cp16(st + ST_B_OFF + B_HALF + so, g_hnb_lo + go);
    }
}

__global__ void __launch_bounds__(256, 1) k_agg_mma()
{
    extern __shared__ char smc[];
    uint32_t sbase = smem_u32(smc);

    int tid  = threadIdx.x;
    int lane = tid & 31, wid = tid >> 5;
    int x0 = blockIdx.x * 128;
    int b  = blockIdx.y;

    const __nv_bfloat16* A = g_a + (size_t)b * NN * NN;

    int warp_m = (wid & 1) * 64;
    int warp_n = (wid >> 1) * 64;

    int lc  = tid & 3,  lr  = tid >> 2;    // A loader (64B rows)
    int lcb = tid & 31, lkr = tid >> 5;    // B loader (512B rows)

    int rowA  = warp_m + (lane & 15);
    int achnk = lane >> 4;
    int kB    = (lane & 7) + 8 * ((lane >> 3) & 1);
    int noffB = (warp_n + ((lane >> 4) & 1) * 8) * 2;

    float d[4][8][4] = {};

    #pragma unroll
    for (int pst = 0; pst < NSTAGE - 1; pst++) {
        agg_load_stage(sbase + pst * STAGE_BYTES, pst * 32, x0, A, lc, lr, lcb, lkr);
        CP_COMMIT();
    }

    const int NT = NN / 32;   // 96
    for (int it = 0; it < NT; it++) {
        CP_WAIT(NSTAGE - 2);
        __syncthreads();

        int pf = it + NSTAGE - 1;
        if (pf < NT)
            agg_load_stage(sbase + (pf % NSTAGE) * STAGE_BYTES, pf * 32, x0, A, lc, lr, lcb, lkr);
        CP_COMMIT();

        uint32_t st = sbase + (it % NSTAGE) * STAGE_BYTES;

        #pragma unroll
        for (int s = 0; s < 2; s++) {
            uint32_t ah[4][4];
            #pragma unroll
            for (int mi = 0; mi < 4; mi++) {
                uint32_t aaddr = st + (rowA + mi * 16) * 80 + (s * 2 + achnk) * 16;
                LDSM_X4(ah[mi][0], ah[mi][1], ah[mi][2], ah[mi][3], aaddr);
            }
            #pragma unroll
            for (int j = 0; j < 4; j++) {
                uint32_t bh[4], bl[4];
                uint32_t baddr = st + ST_B_OFF + (s * 16 + kB) * 528 + noffB + j * 32;
                LDSM_X4_T(bh[0], bh[1], bh[2], bh[3], baddr);
                LDSM_X4_T(bl[0], bl[1], bl[2], bl[3], baddr + B_HALF);
                #pragma unroll
                for (int mi = 0; mi < 4; mi++)
                    #pragma unroll
                    for (int nn = 0; nn < 2; nn++) {
                        int j8 = j * 2 + nn, br = nn * 2;
                        MMA_BF16(d[mi][j8], ah[mi], bh[br], bh[br + 1]);
                        MMA_BF16(d[mi][j8], ah[mi], bl[br], bl[br + 1]);
                    }
            }
        }
    }

    // epilogue
    #pragma unroll
    for (int mi = 0; mi < 4; mi++) {
        int row0 = x0 + warp_m + mi * 16 + (lane >> 2);
        float invd0 = 1.0f / fmaxf(g_denom[b * NN + row0],     1e-12f);
        float invd1 = 1.0f / fmaxf(g_denom[b * NN + row0 + 8], 1e-12f);
        #pragma unroll
        for (int j8 = 0; j8 < 8; j8++) {
            int col = b * 256 + warp_n + j8 * 8 + 2 * (lane & 3);
            float2 v0 = make_float2(d[mi][j8][0] * invd0, d[mi][j8][1] * invd0);
            float2 v1 = make_float2(d[mi][j8][2] * invd1, d[mi][j8][3] * invd1);
            *(float2*)&g_att[(size_t)row0 * BH + col]       = v0;
            *(float2*)&g_att[(size_t)(row0 + 8) * BH + col] = v1;
        }
    }
}

// ---------------- fc_v + elu + residual -------------------------------------
__global__ void __launch_bounds__(256) k_fc(const float* __restrict__ Wv,
                                            const float* __restrict__ bv,
                                            const float* __restrict__ h0,
                                            float* __restrict__ out)
{
    extern __shared__ float sm[];
    float (*As)[68]  = (float(*)[68])sm;
    float (*Bs)[128] = (float(*)[128])(sm + 128 * 68);

    int x0 = blockIdx.x * 128;
    int c0 = blockIdx.y * 128;
    int tid = threadIdx.x;
    int tx = tid & 15, ty = tid >> 4;

    float acc[8][8] = {};

    for (int kk = 0; kk < BH; kk += 64) {
        for (int i = tid; i < 128 * 16; i += 256) {
            int r = i >> 4, c = (i & 15) << 2;
            *(float4*)&As[r][c] = *(const float4*)&g_att[(size_t)(x0 + r) * BH + kk + c];
        }
        for (int i = tid; i < 64 * 32; i += 256) {
            int r = i >> 5, c = (i & 31) << 2;
            *(float4*)&Bs[r][c] = *(const float4*)&Wv[(size_t)(kk + r) * H + c0 + c];
        }
        __syncthreads();
        #pragma unroll 4
        for (int k = 0; k < 64; k++) {
            float av[8];
            #pragma unroll
            for (int i = 0; i < 8; i++) av[i] = As[ty * 8 + i][k];
            float4 b0 = *(const float4*)&Bs[k][tx * 4];
            float4 b1 = *(const float4*)&Bs[k][64 + tx * 4];
            #pragma unroll
            for (int i = 0; i < 8; i++) {
                acc[i][0] = fmaf(av[i], b0.x, acc[i][0]);
                acc[i][1] = fmaf(av[i], b0.y, acc[i][1]);
                acc[i][2] = fmaf(av[i], b0.z, acc[i][2]);
                acc[i][3] = fmaf(av[i], b0.w, acc[i][3]);
                acc[i][4] = fmaf(av[i], b1.x, acc[i][4]);
                acc[i][5] = fmaf(av[i], b1.y, acc[i][5]);
                acc[i][6] = fmaf(av[i], b1.z, acc[i][6]);
                acc[i][7] = fmaf(av[i], b1.w, acc[i][7]);
            }
        }
        __syncthreads();
    }

    #pragma unroll
    for (int i = 0; i < 8; i++) {
        int x = x0 + ty * 8 + i;
        #pragma unroll
        for (int half = 0; half < 2; half++) {
            float4 v;
            float* a = &acc[i][half * 4];
            int col = c0 + half * 64 + tx * 4;
            float r0 = a[0] + bv[col + 0];
            float r1 = a[1] + bv[col + 1];
            float r2 = a[2] + bv[col + 2];
            float r3 = a[3] + bv[col + 3];
            r0 = (r0 > 0.f) ? r0 : expm1f(r0);
            r1 = (r1 > 0.f) ? r1 : expm1f(r1);
            r2 = (r2 > 0.f) ? r2 : expm1f(r2);
            r3 = (r3 > 0.f) ? r3 : expm1f(r3);
            v.x = r0 + h0[(size_t)x * H + col + 0];
            v.y = r1 + h0[(size_t)x * H + col + 1];
            v.z = r2 + h0[(size_t)x * H + col + 2];
            v.w = r3 + h0[(size_t)x * H + col + 3];
            *(float4*)&out[(size_t)x * H + col] = v;
        }
    }
}

// ---------------- kl scalar output ------------------------------------------
__global__ void k_klout(float* __restrict__ out, int out_size) {
    if (threadIdx.x == 0 && out_size > NN * H) {
        out[out_size - 1] = (float)(g_kl / (double)((size_t)NN * NN));
    }
}

// ---------------- launch -----------------------------------------------------
extern "C" void kernel_launch(void* const* d_in, const int* in_sizes, int n_in,
                              void* d_out, int out_size)
{
    const float* h     = (const float*)d_in[0];
    const float* gamma = (const float*)d_in[1];
    const float* beta  = (const float*)d_in[2];
    const float* Wk    = (const float*)d_in[3];
    const float* bk    = (const float*)d_in[4];
    const float* Wm    = (const float*)d_in[5];
    const float* bm    = (const float*)d_in[6];
    const float* Wl    = (const float*)d_in[7];
    const float* bl    = (const float*)d_in[8];
    const float* Wv    = (const float*)d_in[9];
    const float* bv    = (const float*)d_in[10];
    const float* diff  = (const float*)d_in[11];
    const float* eps   = (const float*)d_in[12];
    float* out = (float*)d_out;

    const int smem_fc = (128 * 68 + 64 * 128) * 4;
    cudaFuncSetAttribute(k_scores_mma, cudaFuncAttributeMaxDynamicSharedMemorySize, SC_SMEM);
    cudaFuncSetAttribute(k_agg_mma,    cudaFuncAttributeMaxDynamicSharedMemorySize, AGG_SMEM);
    cudaFuncSetAttribute(k_fc,         cudaFuncAttributeMaxDynamicSharedMemorySize, smem_fc);

    k_init<<<48, 256>>>();
    k_ln<<<NN, 256>>>(h, gamma, beta);
    k_hnb<<<NN, 256>>>();
    k_proj<<<dim3(48, 12), 256>>>(Wk, bk, Wm, bm, Wl, bl);
    k_scores_mma<<<dim3(NB, 48, 48), 128, SC_SMEM>>>(diff, eps);
    k_agg_mma<<<dim3(24, NB), 256, AGG_SMEM>>>();
    k_fc<<<dim3(24, 2), 256, smem_fc>>>(Wv, bv, h, out);
    k_klout<<<1, 32>>>(out, out_size);
}

// round 7
// speedup vs baseline: 1.6473x; 1.1695x over previous
#include <cuda_runtime.h>
#include <cuda_fp16.h>
#include <math.h>
#include <stdint.h>

#define NN    3072
#define H     256
#define NB    4
#define HD    64
#define BH    1024   /* NB*H */

// ---------------- scratch (device globals) ----------------------------------
__device__ float   g_hn[NN * H];                       // 3 MB
__device__ __half  g_kh [NB * NN * HD];
__device__ __half  g_mub[NB * NN * HD];
__device__ __half  g_lsb[NB * NN * HD];
__device__ __half  g_a  [(size_t)NB * NN * NN];        // 75.5 MB
__device__ __half  g_hnh[(size_t)NN * H];              // 1.5 MB
__device__ float   g_att[(size_t)NN * BH];             // 12.6 MB
__device__ float   g_denom[NB * NN];
__device__ double  g_kl;

// ---------------- PTX helpers ------------------------------------------------
__device__ __forceinline__ uint32_t smem_u32(const void* p) {
    uint32_t a;
    asm("{ .reg .u64 t; cvta.to.shared.u64 t, %1; cvt.u32.u64 %0, t; }"
        : "=r"(a) : "l"(p));
    return a;
}
__device__ __forceinline__ void cp16(uint32_t s, const void* g) {
    asm volatile("cp.async.cg.shared.global [%0], [%1], 16;" :: "r"(s), "l"(g));
}
#define CP_COMMIT() asm volatile("cp.async.commit_group;" ::: "memory")
#define CP_WAIT(n)  asm volatile("cp.async.wait_group %0;" :: "n"(n) : "memory")

#define LDSM_X4(r0, r1, r2, r3, addr) \
    asm volatile("ldmatrix.sync.aligned.m8n8.x4.shared.b16 {%0,%1,%2,%3}, [%4];" \
                 : "=r"(r0), "=r"(r1), "=r"(r2), "=r"(r3) : "r"(addr))

#define LDSM_X4_T(r0, r1, r2, r3, addr) \
    asm volatile("ldmatrix.sync.aligned.m8n8.x4.trans.shared.b16 {%0,%1,%2,%3}, [%4];" \
                 : "=r"(r0), "=r"(r1), "=r"(r2), "=r"(r3) : "r"(addr))

#define MMA_F16(d, a, b0, b1) \
    asm volatile("mma.sync.aligned.m16n8k16.row.col.f32.f16.f16.f32 " \
                 "{%0,%1,%2,%3}, {%4,%5,%6,%7}, {%8,%9}, {%0,%1,%2,%3};" \
                 : "+f"((d)[0]), "+f"((d)[1]), "+f"((d)[2]), "+f"((d)[3]) \
                 : "r"((a)[0]), "r"((a)[1]), "r"((a)[2]), "r"((a)[3]), \
                   "r"(b0), "r"(b1))

// ---------------- init ------------------------------------------------------
__global__ void k_init() {
    int t = blockIdx.x * 256 + threadIdx.x;
    if (t < NB * NN) g_denom[t] = 0.0f;
    if (t == 0) g_kl = 0.0;
}

// ---------------- layernorm (+ fp16 copy of hn) -------------------------------
__global__ void k_ln(const float* __restrict__ h,
                     const float* __restrict__ gamma,
                     const float* __restrict__ beta) {
    int row = blockIdx.x;
    int tid = threadIdx.x;
    float v = h[row * H + tid];

    __shared__ float red[8];
    float s = v;
    #pragma unroll
    for (int o = 16; o; o >>= 1) s += __shfl_xor_sync(0xffffffffu, s, o);
    if ((tid & 31) == 0) red[tid >> 5] = s;
    __syncthreads();
    float mean = 0.f;
    #pragma unroll
    for (int i = 0; i < 8; i++) mean += red[i];
    mean *= (1.0f / H);

    float d = v - mean;
    float q = d * d;
    #pragma unroll
    for (int o = 16; o; o >>= 1) q += __shfl_xor_sync(0xffffffffu, q, o);
    __syncthreads();
    if ((tid & 31) == 0) red[tid >> 5] = q;
    __syncthreads();
    float var = 0.f;
    #pragma unroll
    for (int i = 0; i < 8; i++) var += red[i];
    var *= (1.0f / H);

    float hn = d * rsqrtf(var + 1e-5f) * gamma[tid] + beta[tid];
    g_hn[row * H + tid]  = hn;
    g_hnh[row * H + tid] = __float2half(hn);
}

// ---------------- projections (fp32 SIMT, fp16 epilogue) ----------------------
__global__ void __launch_bounds__(256) k_proj(
    const float* __restrict__ Wk, const float* __restrict__ bk,
    const float* __restrict__ Wm, const float* __restrict__ bm,
    const float* __restrict__ Wl, const float* __restrict__ bl)
{
    __shared__ float As[64][68];
    __shared__ float Bs[64][64];

    int mat = blockIdx.y >> 2;
    const float* W    = (mat == 0) ? Wk : (mat == 1) ? Wm : Wl;
    const float* bias = (mat == 0) ? bk : (mat == 1) ? bm : bl;
    __half* outp = (mat == 0) ? g_kh : (mat == 1) ? g_mub : g_lsb;
    float scl = (mat == 0) ? 0.125f : 1.0f;   // fold HD^-0.5 into k

    int m0 = blockIdx.x * 64;
    int j0 = (blockIdx.y & 3) * 64;
    int tid = threadIdx.x;
    int tx = tid & 15, ty = tid >> 4;

    float acc[4][4] = {};

    for (int kk = 0; kk < H; kk += 64) {
        for (int i = tid; i < 64 * 16; i += 256) {
            int r = i >> 4, c = (i & 15) << 2;
            *(float4*)&As[r][c] = *(const float4*)&g_hn[(size_t)(m0 + r) * H + kk + c];
            *(float4*)&Bs[r][c] = *(const float4*)&W[(size_t)(kk + r) * H + j0 + c];
        }
        __syncthreads();
        #pragma unroll 8
        for (int k = 0; k < 64; k++) {
            float a[4], b[4];
            #pragma unroll
            for (int i = 0; i < 4; i++) a[i] = As[ty + 16 * i][k];
            #pragma unroll
            for (int j = 0; j < 4; j++) b[j] = Bs[k][tx + 16 * j];
            #pragma unroll
            for (int i = 0; i < 4; i++)
                #pragma unroll
                for (int j = 0; j < 4; j++)
                    acc[i][j] = fmaf(a[i], b[j], acc[i][j]);
        }
        __syncthreads();
    }

    #pragma unroll
    for (int i = 0; i < 4; i++) {
        int m = m0 + ty + 16 * i;
        #pragma unroll
        for (int j = 0; j < 4; j++) {
            int jc = j0 + tx + 16 * j;
            float v = (acc[i][j] + bias[jc]) * scl;
            int hb = jc & 3, dd = jc >> 2;   // reshape(N, HD, B)
            outp[((size_t)hb * NN + m) * HD + dd] = __float2half(v);
        }
    }
}

// ---------------- scores via tensor cores + elementwise -> a (fp16) ----------
// grid (NB, 48, 48): 64x64 tile per CTA, 128 thr = 4 warps (2m x 2n, warp 32x32)
// smem: K (x-tile), MU, LS (y-tile) — 64 rows x 144B each
#define SC_ROW 144
#define SC_HALF (64 * SC_ROW)     /* 9216 */
#define SC_SMEM (3 * SC_HALF)     /* 27648 */

__global__ void __launch_bounds__(128) k_scores_mma(const float* __restrict__ diffusion,
                                                    const float* __restrict__ eps)
{
    extern __shared__ char smc[];
    uint32_t sb = smem_u32(smc);

    int b  = blockIdx.x;
    int x0 = blockIdx.y * 64;
    int y0 = blockIdx.z * 64;
    int tid = threadIdx.x, lane = tid & 31, wid = tid >> 5;
    int warp_m = (wid & 1) * 32, warp_n = (wid >> 1) * 32;

    const __half* K  = g_kh  + ((size_t)b * NN + x0) * HD;
    const __half* MU = g_mub + ((size_t)b * NN + y0) * HD;
    const __half* LS = g_lsb + ((size_t)b * NN + y0) * HD;

    {
        int lc = tid & 7, lr = tid >> 3;      // chunk 0-7 (128B/row), row 0-15
        #pragma unroll
        for (int p = 0; p < 4; p++) {
            int r = lr + p * 16;
            uint32_t so = r * SC_ROW + lc * 16;
            size_t  go = (size_t)r * HD + lc * 8;
            cp16(sb + 0 * SC_HALF + so, K  + go);
            cp16(sb + 1 * SC_HALF + so, MU + go);
            cp16(sb + 2 * SC_HALF + so, LS + go);
        }
    }
    CP_COMMIT(); CP_WAIT(0);
    __syncthreads();

    float accm[2][4][4] = {}, accl[2][4][4] = {};
    int rA  = warp_m + (lane & 15);
    int cA8 = lane >> 4;
    int rB  = warp_n + (lane & 7) + 8 * ((lane >> 3) & 1);
    int cB8 = lane >> 4;

    #pragma unroll
    for (int s = 0; s < 4; s++) {
        uint32_t kh[2][4];
        #pragma unroll
        for (int mi = 0; mi < 2; mi++) {
            uint32_t a = sb + (rA + mi * 16) * SC_ROW + s * 32 + cA8 * 16;
            LDSM_X4(kh[mi][0], kh[mi][1], kh[mi][2], kh[mi][3], a);
        }
        uint32_t mh[2][4], lh[2][4];
        #pragma unroll
        for (int g = 0; g < 2; g++) {
            uint32_t bm = sb + SC_HALF + (rB + g * 16) * SC_ROW + s * 32 + cB8 * 16;
            LDSM_X4(mh[g][0], mh[g][1], mh[g][2], mh[g][3], bm);
            LDSM_X4(lh[g][0], lh[g][1], lh[g][2], lh[g][3], bm + SC_HALF);
        }
        #pragma unroll
        for (int mi = 0; mi < 2; mi++)
            #pragma unroll
            for (int g = 0; g < 2; g++)
                #pragma unroll
                for (int nn = 0; nn < 2; nn++) {
                    int n8 = g * 2 + nn;
                    MMA_F16(accm[mi][n8], kh[mi], mh[g][nn], mh[g][nn + 2]);
                    MMA_F16(accl[mi][n8], kh[mi], lh[g][nn], lh[g][nn + 2]);
                }
    }

    __syncthreads();   // tiles dead — reuse [0, SC_HALF) as fp16 staging

    float klsum = 0.f;
    float rsum[2][2] = {{0.f, 0.f}, {0.f, 0.f}};

    #pragma unroll
    for (int mi = 0; mi < 2; mi++) {
        int xl0 = warp_m + mi * 16 + (lane >> 2);
        #pragma unroll
        for (int n8 = 0; n8 < 4; n8++) {
            int yl = warp_n + n8 * 8 + 2 * (lane & 3);
            #pragma unroll
            for (int hf = 0; hf < 2; hf++) {
                int xl = xl0 + hf * 8;
                size_t xy = (size_t)(x0 + xl) * NN + (y0 + yl);
                float2 dif = *(const float2*)&diffusion[xy];
                float e0 = eps[xy * NB + b];
                float e1 = eps[(xy + 1) * NB + b];
                float smu0 = accm[mi][n8][hf * 2],     sls0 = accl[mi][n8][hf * 2];
                float smu1 = accm[mi][n8][hf * 2 + 1], sls1 = accl[mi][n8][hf * 2 + 1];
                float sig0 = fmaxf(sls0, 0.f) + __logf(1.f + __expf(-fabsf(sls0)));
                float sig1 = fmaxf(sls1, 0.f) + __logf(1.f + __expf(-fabsf(sls1)));
                float kle0 = 0.5f * (sig0 * sig0 + smu0 * smu0) - __logf(sig0) - 0.5f;
                float kle1 = 0.5f * (sig1 * sig1 + smu1 * smu1) - __logf(sig1) - 0.5f;
                float sg0 = (dif.x > 0.f) ? 1.f : ((dif.x < 0.f) ? -1.f : 0.f);
                float sg1 = (dif.y > 0.f) ? 1.f : ((dif.y < 0.f) ? -1.f : 0.f);
                klsum += kle0 * sg0 + kle1 * sg1;
                float a0 = __expf(smu0 + sig0 * e0) * dif.x;
                float a1 = __expf(smu1 + sig1 * e1) * dif.y;
                __half2 av;
                av.x = __float2half(a0);
                av.y = __float2half(a1);
                // denom from the ROUNDED values agg will actually sum
                rsum[mi][hf] += fabsf(__half2float(av.x)) + fabsf(__half2float(av.y));
                *(__half2*)(smc + xl * SC_ROW + yl * 2) = av;
            }
        }
    }

    // per-row denominators
    #pragma unroll
    for (int mi = 0; mi < 2; mi++)
        #pragma unroll
        for (int hf = 0; hf < 2; hf++) {
            float r = rsum[mi][hf];
            r += __shfl_xor_sync(0xffffffffu, r, 1);
            r += __shfl_xor_sync(0xffffffffu, r, 2);
            if ((lane & 3) == 0)
                atomicAdd(&g_denom[b * NN + x0 + warp_m + mi * 16 + hf * 8 + (lane >> 2)], r);
        }

    // KL
    #pragma unroll
    for (int o = 16; o; o >>= 1) klsum += __shfl_xor_sync(0xffffffffu, klsum, o);
    __shared__ float kred[4];
    if (lane == 0) kred[wid] = klsum;
    __syncthreads();
    if (tid == 0) {
        atomicAdd(&g_kl, (double)(kred[0] + kred[1] + kred[2] + kred[3]));
    }

    // coalesced copy-out
    __half* dst = g_a + (size_t)b * NN * NN;
    for (int t = tid; t < 512; t += 128) {
        int r = t >> 3, c = t & 7;
        size_t go = (size_t)(x0 + r) * NN + y0 + c * 8;
        *(float4*)&dst[go] = *(float4*)(smc + r * SC_ROW + c * 16);
    }
}

// ---------------- aggregation: a(fp16) x hn(fp16) mma, CTA 128x256 ------------
#define A_BYTES  10240                      /* 128*80 */
#define B_BYTES  16896                      /* 32*528 */
#define ST_B_OFF A_BYTES
#define STAGE_BYTES (A_BYTES + B_BYTES)     /* 27136 */
#define NSTAGE   3
#define AGG_SMEM (NSTAGE * STAGE_BYTES)     /* 81408 */

__device__ __forceinline__ void agg_load_stage(
    uint32_t st, int kk, int x0, const __half* A,
    int lc, int lr, int lcb, int lkr)
{
    #pragma unroll
    for (int p = 0; p < 2; p++) {
        int r = lr + p * 64;
        cp16(st + r * 80 + lc * 16, A + (size_t)(x0 + r) * NN + kk + lc * 8);
    }
    #pragma unroll
    for (int p = 0; p < 4; p++) {
        int kr = lkr + p * 8;
        cp16(st + ST_B_OFF + kr * 528 + lcb * 16, g_hnh + (size_t)(kk + kr) * H + lcb * 8);
    }
}

__global__ void __launch_bounds__(256, 1) k_agg_mma()
{
    extern __shared__ char smc[];
    uint32_t sbase = smem_u32(smc);

    int tid  = threadIdx.x;
    int lane = tid & 31, wid = tid >> 5;
    int x0 = blockIdx.x * 128;
    int b  = blockIdx.y;

    const __half* A = g_a + (size_t)b * NN * NN;

    int warp_m = (wid & 1) * 64;
    int warp_n = (wid >> 1) * 64;

    int lc  = tid & 3,  lr  = tid >> 2;    // A loader (64B rows)
    int lcb = tid & 31, lkr = tid >> 5;    // B loader (512B rows)

    int rowA  = warp_m + (lane & 15);
    int achnk = lane >> 4;
    int kB    = (lane & 7) + 8 * ((lane >> 3) & 1);
    int noffB = (warp_n + ((lane >> 4) & 1) * 8) * 2;

    float d[4][8][4] = {};

    #pragma unroll
    for (int pst = 0; pst < NSTAGE - 1; pst++) {
        agg_load_stage(sbase + pst * STAGE_BYTES, pst * 32, x0, A, lc, lr, lcb, lkr);
        CP_COMMIT();
    }

    const int NT = NN / 32;   // 96
    for (int it = 0; it < NT; it++) {
        CP_WAIT(NSTAGE - 2);
        __syncthreads();

        int pf = it + NSTAGE - 1;
        if (pf < NT)
            agg_load_stage(sbase + (pf % NSTAGE) * STAGE_BYTES, pf * 32, x0, A, lc, lr, lcb, lkr);
        CP_COMMIT();

        uint32_t st = sbase + (it % NSTAGE) * STAGE_BYTES;

        #pragma unroll
        for (int s = 0; s < 2; s++) {
            uint32_t ah[4][4];
            #pragma unroll
            for (int mi = 0; mi < 4; mi++) {
                uint32_t aaddr = st + (rowA + mi * 16) * 80 + (s * 2 + achnk) * 16;
                LDSM_X4(ah[mi][0], ah[mi][1], ah[mi][2], ah[mi][3], aaddr);
            }
            #pragma unroll
            for (int j = 0; j < 4; j++) {
                uint32_t bh[4];
                uint32_t baddr = st + ST_B_OFF + (s * 16 + kB) * 528 + noffB + j * 32;
                LDSM_X4_T(bh[0], bh[1], bh[2], bh[3], baddr);
                #pragma unroll
                for (int mi = 0; mi < 4; mi++)
                    #pragma unroll
                    for (int nn = 0; nn < 2; nn++) {
                        int j8 = j * 2 + nn, br = nn * 2;
                        MMA_F16(d[mi][j8], ah[mi], bh[br], bh[br + 1]);
                    }
            }
        }
    }

    // epilogue
    #pragma unroll
    for (int mi = 0; mi < 4; mi++) {
        int row0 = x0 + warp_m + mi * 16 + (lane >> 2);
        float invd0 = 1.0f / fmaxf(g_denom[b * NN + row0],     1e-12f);
        float invd1 = 1.0f / fmaxf(g_denom[b * NN + row0 + 8], 1e-12f);
        #pragma unroll
        for (int j8 = 0; j8 < 8; j8++) {
            int col = b * 256 + warp_n + j8 * 8 + 2 * (lane & 3);
            float2 v0 = make_float2(d[mi][j8][0] * invd0, d[mi][j8][1] * invd0);
            float2 v1 = make_float2(d[mi][j8][2] * invd1, d[mi][j8][3] * invd1);
            *(float2*)&g_att[(size_t)row0 * BH + col]       = v0;
            *(float2*)&g_att[(size_t)(row0 + 8) * BH + col] = v1;
        }
    }
}

// ---------------- fc_v + elu + residual -------------------------------------
__global__ void __launch_bounds__(256) k_fc(const float* __restrict__ Wv,
                                            const float* __restrict__ bv,
                                            const float* __restrict__ h0,
                                            float* __restrict__ out)
{
    extern __shared__ float sm[];
    float (*As)[68]  = (float(*)[68])sm;
    float (*Bs)[128] = (float(*)[128])(sm + 128 * 68);

    int x0 = blockIdx.x * 128;
    int c0 = blockIdx.y * 128;
    int tid = threadIdx.x;
    int tx = tid & 15, ty = tid >> 4;

    float acc[8][8] = {};

    for (int kk = 0; kk < BH; kk += 64) {
        for (int i = tid; i < 128 * 16; i += 256) {
            int r = i >> 4, c = (i & 15) << 2;
            *(float4*)&As[r][c] = *(const float4*)&g_att[(size_t)(x0 + r) * BH + kk + c];
        }
        for (int i = tid; i < 64 * 32; i += 256) {
            int r = i >> 5, c = (i & 31) << 2;
            *(float4*)&Bs[r][c] = *(const float4*)&Wv[(size_t)(kk + r) * H + c0 + c];
        }
        __syncthreads();
        #pragma unroll 4
        for (int k = 0; k < 64; k++) {
            float av[8];
            #pragma unroll
            for (int i = 0; i < 8; i++) av[i] = As[ty * 8 + i][k];
            float4 b0 = *(const float4*)&Bs[k][tx * 4];
            float4 b1 = *(const float4*)&Bs[k][64 + tx * 4];
            #pragma unroll
            for (int i = 0; i < 8; i++) {
                acc[i][0] = fmaf(av[i], b0.x, acc[i][0]);
                acc[i][1] = fmaf(av[i], b0.y, acc[i][1]);
                acc[i][2] = fmaf(av[i], b0.z, acc[i][2]);
                acc[i][3] = fmaf(av[i], b0.w, acc[i][3]);
                acc[i][4] = fmaf(av[i], b1.x, acc[i][4]);
                acc[i][5] = fmaf(av[i], b1.y, acc[i][5]);
                acc[i][6] = fmaf(av[i], b1.z, acc[i][6]);
                acc[i][7] = fmaf(av[i], b1.w, acc[i][7]);
            }
        }
        __syncthreads();
    }

    #pragma unroll
    for (int i = 0; i < 8; i++) {
        int x = x0 + ty * 8 + i;
        #pragma unroll
        for (int half = 0; half < 2; half++) {
            float4 v;
            float* a = &acc[i][half * 4];
            int col = c0 + half * 64 + tx * 4;
            float r0 = a[0] + bv[col + 0];
            float r1 = a[1] + bv[col + 1];
            float r2 = a[2] + bv[col + 2];
            float r3 = a[3] + bv[col + 3];
            r0 = (r0 > 0.f) ? r0 : expm1f(r0);
            r1 = (r1 > 0.f) ? r1 : expm1f(r1);
            r2 = (r2 > 0.f) ? r2 : expm1f(r2);
            r3 = (r3 > 0.f) ? r3 : expm1f(r3);
            v.x = r0 + h0[(size_t)x * H + col + 0];
            v.y = r1 + h0[(size_t)x * H + col + 1];
            v.z = r2 + h0[(size_t)x * H + col + 2];
            v.w = r3 + h0[(size_t)x * H + col + 3];
            *(float4*)&out[(size_t)x * H + col] = v;
        }
    }
}

// ---------------- kl scalar output ------------------------------------------
__global__ void k_klout(float* __restrict__ out, int out_size) {
    if (threadIdx.x == 0 && out_size > NN * H) {
        out[out_size - 1] = (float)(g_kl / (double)((size_t)NN * NN));
    }
}

// ---------------- launch -----------------------------------------------------
extern "C" void kernel_launch(void* const* d_in, const int* in_sizes, int n_in,
                              void* d_out, int out_size)
{
    const float* h     = (const float*)d_in[0];
    const float* gamma = (const float*)d_in[1];
    const float* beta  = (const float*)d_in[2];
    const float* Wk    = (const float*)d_in[3];
    const float* bk    = (const float*)d_in[4];
    const float* Wm    = (const float*)d_in[5];
    const float* bm    = (const float*)d_in[6];
    const float* Wl    = (const float*)d_in[7];
    const float* bl    = (const float*)d_in[8];
    const float* Wv    = (const float*)d_in[9];
    const float* bv    = (const float*)d_in[10];
    const float* diff  = (const float*)d_in[11];
    const float* eps   = (const float*)d_in[12];
    float* out = (float*)d_out;

    const int smem_fc = (128 * 68 + 64 * 128) * 4;
    cudaFuncSetAttribute(k_scores_mma, cudaFuncAttributeMaxDynamicSharedMemorySize, SC_SMEM);
    cudaFuncSetAttribute(k_agg_mma,    cudaFuncAttributeMaxDynamicSharedMemorySize, AGG_SMEM);
    cudaFuncSetAttribute(k_fc,         cudaFuncAttributeMaxDynamicSharedMemorySize, smem_fc);

    k_init<<<48, 256>>>();
    k_ln<<<NN, 256>>>(h, gamma, beta);
    k_proj<<<dim3(48, 12), 256>>>(Wk, bk, Wm, bm, Wl, bl);
    k_scores_mma<<<dim3(NB, 48, 48), 128, SC_SMEM>>>(diff, eps);
    k_agg_mma<<<dim3(24, NB), 256, AGG_SMEM>>>();
    k_fc<<<dim3(24, 2), 256, smem_fc>>>(Wv, bv, h, out);
    k_klout<<<1, 32>>>(out, out_size);
}

// round 8
// speedup vs baseline: 2.3889x; 1.4502x over previous
#include <cuda_runtime.h>
#include <cuda_fp16.h>
#include <math.h>
#include <stdint.h>

#define NN    3072
#define H     256
#define NB    4
#define HD    64
#define BH    1024   /* NB*H */

// ---------------- scratch (device globals) ----------------------------------
__device__ float   g_hn[NN * H];                       // 3 MB
__device__ __half  g_kh [NB * NN * HD];
__device__ __half  g_mub[NB * NN * HD];
__device__ __half  g_lsb[NB * NN * HD];
__device__ __half  g_a  [(size_t)NB * NN * NN];        // 75.5 MB
__device__ __half  g_hnh[(size_t)NN * H];              // 1.5 MB
__device__ __half  g_atth[(size_t)NN * BH];            // 6.3 MB
__device__ __half  g_wvh[BH * H];                      // 0.5 MB
__device__ float   g_denom[NB * NN];
__device__ double  g_kl;

// ---------------- PTX helpers ------------------------------------------------
__device__ __forceinline__ uint32_t smem_u32(const void* p) {
    uint32_t a;
    asm("{ .reg .u64 t; cvta.to.shared.u64 t, %1; cvt.u32.u64 %0, t; }"
        : "=r"(a) : "l"(p));
    return a;
}
__device__ __forceinline__ void cp16(uint32_t s, const void* g) {
    asm volatile("cp.async.cg.shared.global [%0], [%1], 16;" :: "r"(s), "l"(g));
}
__device__ __forceinline__ void cp4(uint32_t s, const void* g) {
    asm volatile("cp.async.ca.shared.global [%0], [%1], 4;" :: "r"(s), "l"(g));
}
#define CP_COMMIT() asm volatile("cp.async.commit_group;" ::: "memory")
#define CP_WAIT(n)  asm volatile("cp.async.wait_group %0;" :: "n"(n) : "memory")

#define LDSM_X4(r0, r1, r2, r3, addr) \
    asm volatile("ldmatrix.sync.aligned.m8n8.x4.shared.b16 {%0,%1,%2,%3}, [%4];" \
                 : "=r"(r0), "=r"(r1), "=r"(r2), "=r"(r3) : "r"(addr))

#define LDSM_X4_T(r0, r1, r2, r3, addr) \
    asm volatile("ldmatrix.sync.aligned.m8n8.x4.trans.shared.b16 {%0,%1,%2,%3}, [%4];" \
                 : "=r"(r0), "=r"(r1), "=r"(r2), "=r"(r3) : "r"(addr))

#define MMA_F16(d, a, b0, b1) \
    asm volatile("mma.sync.aligned.m16n8k16.row.col.f32.f16.f16.f32 " \
                 "{%0,%1,%2,%3}, {%4,%5,%6,%7}, {%8,%9}, {%0,%1,%2,%3};" \
                 : "+f"((d)[0]), "+f"((d)[1]), "+f"((d)[2]), "+f"((d)[3]) \
                 : "r"((a)[0]), "r"((a)[1]), "r"((a)[2]), "r"((a)[3]), \
                   "r"(b0), "r"(b1))

// ---------------- init ------------------------------------------------------
__global__ void k_init() {
    int t = blockIdx.x * 256 + threadIdx.x;
    if (t < NB * NN) g_denom[t] = 0.0f;
    if (t == 0) g_kl = 0.0;
}

// ---------------- layernorm (+ fp16 copy of hn) -------------------------------
__global__ void k_ln(const float* __restrict__ h,
                     const float* __restrict__ gamma,
                     const float* __restrict__ beta) {
    int row = blockIdx.x;
    int tid = threadIdx.x;
    float v = h[row * H + tid];

    __shared__ float red[8];
    float s = v;
    #pragma unroll
    for (int o = 16; o; o >>= 1) s += __shfl_xor_sync(0xffffffffu, s, o);
    if ((tid & 31) == 0) red[tid >> 5] = s;
    __syncthreads();
    float mean = 0.f;
    #pragma unroll
    for (int i = 0; i < 8; i++) mean += red[i];
    mean *= (1.0f / H);

    float d = v - mean;
    float q = d * d;
    #pragma unroll
    for (int o = 16; o; o >>= 1) q += __shfl_xor_sync(0xffffffffu, q, o);
    __syncthreads();
    if ((tid & 31) == 0) red[tid >> 5] = q;
    __syncthreads();
    float var = 0.f;
    #pragma unroll
    for (int i = 0; i < 8; i++) var += red[i];
    var *= (1.0f / H);

    float hn = d * rsqrtf(var + 1e-5f) * gamma[tid] + beta[tid];
    g_hn[row * H + tid]  = hn;
    g_hnh[row * H + tid] = __float2half(hn);
}

// ---------------- Wv -> fp16 --------------------------------------------------
__global__ void k_wvh(const float* __restrict__ Wv) {
    int i = blockIdx.x * 256 + threadIdx.x;
    g_wvh[i] = __float2half(Wv[i]);
}

// ---------------- projections (fp32 SIMT, fp16 epilogue) ----------------------
__global__ void __launch_bounds__(256) k_proj(
    const float* __restrict__ Wk, const float* __restrict__ bk,
    const float* __restrict__ Wm, const float* __restrict__ bm,
    const float* __restrict__ Wl, const float* __restrict__ bl)
{
    __shared__ float As[64][68];
    __shared__ float Bs[64][64];

    int mat = blockIdx.y >> 2;
    const float* W    = (mat == 0) ? Wk : (mat == 1) ? Wm : Wl;
    const float* bias = (mat == 0) ? bk : (mat == 1) ? bm : bl;
    __half* outp = (mat == 0) ? g_kh : (mat == 1) ? g_mub : g_lsb;
    float scl = (mat == 0) ? 0.125f : 1.0f;   // fold HD^-0.5 into k

    int m0 = blockIdx.x * 64;
    int j0 = (blockIdx.y & 3) * 64;
    int tid = threadIdx.x;
    int tx = tid & 15, ty = tid >> 4;

    float acc[4][4] = {};

    for (int kk = 0; kk < H; kk += 64) {
        for (int i = tid; i < 64 * 16; i += 256) {
            int r = i >> 4, c = (i & 15) << 2;
            *(float4*)&As[r][c] = *(const float4*)&g_hn[(size_t)(m0 + r) * H + kk + c];
            *(float4*)&Bs[r][c] = *(const float4*)&W[(size_t)(kk + r) * H + j0 + c];
        }
        __syncthreads();
        #pragma unroll 8
        for (int k = 0; k < 64; k++) {
            float a[4], b[4];
            #pragma unroll
            for (int i = 0; i < 4; i++) a[i] = As[ty + 16 * i][k];
            #pragma unroll
            for (int j = 0; j < 4; j++) b[j] = Bs[k][tx + 16 * j];
            #pragma unroll
            for (int i = 0; i < 4; i++)
                #pragma unroll
                for (int j = 0; j < 4; j++)
                    acc[i][j] = fmaf(a[i], b[j], acc[i][j]);
        }
        __syncthreads();
    }

    #pragma unroll
    for (int i = 0; i < 4; i++) {
        int m = m0 + ty + 16 * i;
        #pragma unroll
        for (int j = 0; j < 4; j++) {
            int jc = j0 + tx + 16 * j;
            float v = (acc[i][j] + bias[jc]) * scl;
            int hb = jc & 3, dd = jc >> 2;   // reshape(N, HD, B)
            outp[((size_t)hb * NN + m) * HD + dd] = __float2half(v);
        }
    }
}

// ---------------- scores: mma + prefetched eps/diff + elementwise -> a --------
// grid (NB, 48, 48): 64x64 tile per CTA, 128 thr = 4 warps (2m x 2n, warp 32x32)
#define SC_ROW 144
#define SC_HALF (64 * SC_ROW)     /* 9216 */
#define OFF_EPS (3 * SC_HALF)     /* 27648, 16384 bytes */
#define OFF_DIF (OFF_EPS + 16384) /* 44032, 16384 bytes */
#define SC_SMEM (OFF_DIF + 16384) /* 60416 */

__global__ void __launch_bounds__(128) k_scores_mma(const float* __restrict__ diffusion,
                                                    const float* __restrict__ eps)
{
    extern __shared__ char smc[];
    uint32_t sb = smem_u32(smc);

    int b  = blockIdx.x;
    int x0 = blockIdx.y * 64;
    int y0 = blockIdx.z * 64;
    int tid = threadIdx.x, lane = tid & 31, wid = tid >> 5;
    int warp_m = (wid & 1) * 32, warp_n = (wid >> 1) * 32;

    const __half* K  = g_kh  + ((size_t)b * NN + x0) * HD;
    const __half* MU = g_mub + ((size_t)b * NN + y0) * HD;
    const __half* LS = g_lsb + ((size_t)b * NN + y0) * HD;

    // group A: K/MU/LS tiles
    {
        int lc = tid & 7, lr = tid >> 3;      // chunk 0-7 (128B/row), row 0-15
        #pragma unroll
        for (int p = 0; p < 4; p++) {
            int r = lr + p * 16;
            uint32_t so = r * SC_ROW + lc * 16;
            size_t  go = (size_t)r * HD + lc * 8;
            cp16(sb + 0 * SC_HALF + so, K  + go);
            cp16(sb + 1 * SC_HALF + so, MU + go);
            cp16(sb + 2 * SC_HALF + so, LS + go);
        }
    }
    CP_COMMIT();

    // group B: eps (4B strided) + diffusion (16B) tiles — overlapped with MMAs
    {
        #pragma unroll
        for (int i = 0; i < 32; i++) {
            int idx = tid + i * 128;
            int xl = idx >> 6, yl = idx & 63;
            cp4(sb + OFF_EPS + idx * 4,
                eps + ((size_t)(x0 + xl) * NN + y0 + yl) * NB + b);
        }
        #pragma unroll
        for (int i = 0; i < 8; i++) {
            int idx = tid + i * 128;
            int xl = idx >> 4, c = idx & 15;
            cp16(sb + OFF_DIF + xl * 256 + c * 16,
                 diffusion + (size_t)(x0 + xl) * NN + y0 + c * 4);
        }
    }
    CP_COMMIT();

    CP_WAIT(1);          // group A resident
    __syncthreads();

    float accm[2][4][4] = {}, accl[2][4][4] = {};
    int rA  = warp_m + (lane & 15);
    int cA8 = lane >> 4;
    int rB  = warp_n + (lane & 7) + 8 * ((lane >> 3) & 1);
    int cB8 = lane >> 4;

    #pragma unroll
    for (int s = 0; s < 4; s++) {
        uint32_t kh[2][4];
        #pragma unroll
        for (int mi = 0; mi < 2; mi++) {
            uint32_t a = sb + (rA + mi * 16) * SC_ROW + s * 32 + cA8 * 16;
            LDSM_X4(kh[mi][0], kh[mi][1], kh[mi][2], kh[mi][3], a);
        }
        uint32_t mh[2][4], lh[2][4];
        #pragma unroll
        for (int g = 0; g < 2; g++) {
            uint32_t bm = sb + SC_HALF + (rB + g * 16) * SC_ROW + s * 32 + cB8 * 16;
            LDSM_X4(mh[g][0], mh[g][1], mh[g][2], mh[g][3], bm);
            LDSM_X4(lh[g][0], lh[g][1], lh[g][2], lh[g][3], bm + SC_HALF);
        }
        #pragma unroll
        for (int mi = 0; mi < 2; mi++)
            #pragma unroll
            for (int g = 0; g < 2; g++)
                #pragma unroll
                for (int nn = 0; nn < 2; nn++) {
                    int n8 = g * 2 + nn;
                    MMA_F16(accm[mi][n8], kh[mi], mh[g][nn], mh[g][nn + 2]);
                    MMA_F16(accl[mi][n8], kh[mi], lh[g][nn], lh[g][nn + 2]);
                }
    }

    CP_WAIT(0);          // eps/diff resident
    __syncthreads();     // tiles dead — reuse [0, SC_HALF) as fp16 staging

    const float* eps_s = (const float*)(smc + OFF_EPS);
    const float* dif_s = (const float*)(smc + OFF_DIF);

    float klsum = 0.f;
    float rsum[2][2] = {{0.f, 0.f}, {0.f, 0.f}};

    #pragma unroll
    for (int mi = 0; mi < 2; mi++) {
        int xl0 = warp_m + mi * 16 + (lane >> 2);
        #pragma unroll
        for (int n8 = 0; n8 < 4; n8++) {
            int yl = warp_n + n8 * 8 + 2 * (lane & 3);
            #pragma unroll
            for (int hf = 0; hf < 2; hf++) {
                int xl = xl0 + hf * 8;
                float2 dif = *(const float2*)&dif_s[xl * 64 + yl];
                float e0 = eps_s[xl * 64 + yl];
                float e1 = eps_s[xl * 64 + yl + 1];
                float smu0 = accm[mi][n8][hf * 2],     sls0 = accl[mi][n8][hf * 2];
                float smu1 = accm[mi][n8][hf * 2 + 1], sls1 = accl[mi][n8][hf * 2 + 1];
                float sig0 = fmaxf(sls0, 0.f) + __logf(1.f + __expf(-fabsf(sls0)));
                float sig1 = fmaxf(sls1, 0.f) + __logf(1.f + __expf(-fabsf(sls1)));
                float kle0 = 0.5f * (sig0 * sig0 + smu0 * smu0) - __logf(sig0) - 0.5f;
                float kle1 = 0.5f * (sig1 * sig1 + smu1 * smu1) - __logf(sig1) - 0.5f;
                float sg0 = (dif.x > 0.f) ? 1.f : ((dif.x < 0.f) ? -1.f : 0.f);
                float sg1 = (dif.y > 0.f) ? 1.f : ((dif.y < 0.f) ? -1.f : 0.f);
                klsum += kle0 * sg0 + kle1 * sg1;
                float a0 = __expf(smu0 + sig0 * e0) * dif.x;
                float a1 = __expf(smu1 + sig1 * e1) * dif.y;
                __half2 av;
                av.x = __float2half(a0);
                av.y = __float2half(a1);
                rsum[mi][hf] += fabsf(__half2float(av.x)) + fabsf(__half2float(av.y));
                *(__half2*)(smc + xl * SC_ROW + yl * 2) = av;
            }
        }
    }

    // per-row denominators
    #pragma unroll
    for (int mi = 0; mi < 2; mi++)
        #pragma unroll
        for (int hf = 0; hf < 2; hf++) {
            float r = rsum[mi][hf];
            r += __shfl_xor_sync(0xffffffffu, r, 1);
            r += __shfl_xor_sync(0xffffffffu, r, 2);
            if ((lane & 3) == 0)
                atomicAdd(&g_denom[b * NN + x0 + warp_m + mi * 16 + hf * 8 + (lane >> 2)], r);
        }

    // KL
    #pragma unroll
    for (int o = 16; o; o >>= 1) klsum += __shfl_xor_sync(0xffffffffu, klsum, o);
    __shared__ float kred[4];
    if (lane == 0) kred[wid] = klsum;
    __syncthreads();
    if (tid == 0) {
        atomicAdd(&g_kl, (double)(kred[0] + kred[1] + kred[2] + kred[3]));
    }

    // coalesced copy-out
    __half* dst = g_a + (size_t)b * NN * NN;
    for (int t = tid; t < 512; t += 128) {
        int r = t >> 3, c = t & 7;
        size_t go = (size_t)(x0 + r) * NN + y0 + c * 8;
        *(float4*)&dst[go] = *(float4*)(smc + r * SC_ROW + c * 16);
    }
}

// ---------------- aggregation: a(fp16) x hn(fp16) mma, CTA 128x256 ------------
#define A_BYTES  10240                      /* 128*80 */
#define B_BYTES  16896                      /* 32*528 */
#define ST_B_OFF A_BYTES
#define STAGE_BYTES (A_BYTES + B_BYTES)     /* 27136 */
#define NSTAGE   3
#define AGG_SMEM (NSTAGE * STAGE_BYTES)     /* 81408 */

__device__ __forceinline__ void agg_load_stage(
    uint32_t st, int kk, int x0, const __half* A,
    int lc, int lr, int lcb, int lkr)
{
    #pragma unroll
    for (int p = 0; p < 2; p++) {
        int r = lr + p * 64;
        cp16(st + r * 80 + lc * 16, A + (size_t)(x0 + r) * NN + kk + lc * 8);
    }
    #pragma unroll
    for (int p = 0; p < 4; p++) {
        int kr = lkr + p * 8;
        cp16(st + ST_B_OFF + kr * 528 + lcb * 16, g_hnh + (size_t)(kk + kr) * H + lcb * 8);
    }
}

__global__ void __launch_bounds__(256, 1) k_agg_mma()
{
    extern __shared__ char smc[];
    uint32_t sbase = smem_u32(smc);

    int tid  = threadIdx.x;
    int lane = tid & 31, wid = tid >> 5;
    int x0 = blockIdx.x * 128;
    int b  = blockIdx.y;

    const __half* A = g_a + (size_t)b * NN * NN;

    int warp_m = (wid & 1) * 64;
    int warp_n = (wid >> 1) * 64;

    int lc  = tid & 3,  lr  = tid >> 2;    // A loader (64B rows)
    int lcb = tid & 31, lkr = tid >> 5;    // B loader (512B rows)

    int rowA  = warp_m + (lane & 15);
    int achnk = lane >> 4;
    int kB    = (lane & 7) + 8 * ((lane >> 3) & 1);
    int noffB = (warp_n + ((lane >> 4) & 1) * 8) * 2;

    float d[4][8][4] = {};

    #pragma unroll
    for (int pst = 0; pst < NSTAGE - 1; pst++) {
        agg_load_stage(sbase + pst * STAGE_BYTES, pst * 32, x0, A, lc, lr, lcb, lkr);
        CP_COMMIT();
    }

    const int NT = NN / 32;   // 96
    for (int it = 0; it < NT; it++) {
        CP_WAIT(NSTAGE - 2);
        __syncthreads();

        int pf = it + NSTAGE - 1;
        if (pf < NT)
            agg_load_stage(sbase + (pf % NSTAGE) * STAGE_BYTES, pf * 32, x0, A, lc, lr, lcb, lkr);
        CP_COMMIT();

        uint32_t st = sbase + (it % NSTAGE) * STAGE_BYTES;

        #pragma unroll
        for (int s = 0; s < 2; s++) {
            uint32_t ah[4][4];
            #pragma unroll
            for (int mi = 0; mi < 4; mi++) {
                uint32_t aaddr = st + (rowA + mi * 16) * 80 + (s * 2 + achnk) * 16;
                LDSM_X4(ah[mi][0], ah[mi][1], ah[mi][2], ah[mi][3], aaddr);
            }
            #pragma unroll
            for (int j = 0; j < 4; j++) {
                uint32_t bh[4];
                uint32_t baddr = st + ST_B_OFF + (s * 16 + kB) * 528 + noffB + j * 32;
                LDSM_X4_T(bh[0], bh[1], bh[2], bh[3], baddr);
                #pragma unroll
                for (int mi = 0; mi < 4; mi++)
                    #pragma unroll
                    for (int nn = 0; nn < 2; nn++) {
                        int j8 = j * 2 + nn, br = nn * 2;
                        MMA_F16(d[mi][j8], ah[mi], bh[br], bh[br + 1]);
                    }
            }
        }
    }

    // epilogue: normalize, store att as fp16
    #pragma unroll
    for (int mi = 0; mi < 4; mi++) {
        int row0 = x0 + warp_m + mi * 16 + (lane >> 2);
        float invd0 = 1.0f / fmaxf(g_denom[b * NN + row0],     1e-12f);
        float invd1 = 1.0f / fmaxf(g_denom[b * NN + row0 + 8], 1e-12f);
        #pragma unroll
        for (int j8 = 0; j8 < 8; j8++) {
            int col = b * 256 + warp_n + j8 * 8 + 2 * (lane & 3);
            __half2 v0, v1;
            v0.x = __float2half(d[mi][j8][0] * invd0);
            v0.y = __float2half(d[mi][j8][1] * invd0);
            v1.x = __float2half(d[mi][j8][2] * invd1);
            v1.y = __float2half(d[mi][j8][3] * invd1);
            *(__half2*)&g_atth[(size_t)row0 * BH + col]       = v0;
            *(__half2*)&g_atth[(size_t)(row0 + 8) * BH + col] = v1;
        }
    }
}

// ---------------- fc_v via fp16 mma + elu + residual --------------------------
// grid (48): CTA = 64 rows x 256 cols, K = 1024. 8 warps (2m x 4n, warp 32x64).
#define FC_A_BYTES 5120                     /* 64*80 */
#define FC_B_BYTES 16896                    /* 32*528 */
#define FC_B_OFF   FC_A_BYTES
#define FC_STAGE (FC_A_BYTES + FC_B_BYTES)  /* 22016 */
#define FC_SMEM  (NSTAGE * FC_STAGE)        /* 66048 */

__device__ __forceinline__ void fc_load_stage(uint32_t st, int kk, int x0,
                                              int lc, int lr, int lcb, int lkr)
{
    cp16(st + lr * 80 + lc * 16, g_atth + (size_t)(x0 + lr) * BH + kk + lc * 8);
    #pragma unroll
    for (int p = 0; p < 4; p++) {
        int kr = lkr + p * 8;
        cp16(st + FC_B_OFF + kr * 528 + lcb * 16, g_wvh + (size_t)(kk + kr) * H + lcb * 8);
    }
}

__global__ void __launch_bounds__(256, 1) k_fc_mma(const float* __restrict__ bv,
                                                   const float* __restrict__ h0,
                                                   float* __restrict__ out)
{
    extern __shared__ char smc[];
    uint32_t sbase = smem_u32(smc);

    int tid  = threadIdx.x;
    int lane = tid & 31, wid = tid >> 5;
    int x0 = blockIdx.x * 64;

    int warp_m = (wid & 1) * 32;
    int warp_n = (wid >> 1) * 64;

    int lc  = tid & 3,  lr  = tid >> 2;    // A: 64 rows x 4 chunks
    int lcb = tid & 31, lkr = tid >> 5;    // B: 32 rows x 32 chunks

    int rowA  = warp_m + (lane & 15);
    int achnk = lane >> 4;
    int kB    = (lane & 7) + 8 * ((lane >> 3) & 1);
    int noffB = (warp_n + ((lane >> 4) & 1) * 8) * 2;

    float d[2][8][4] = {};

    #pragma unroll
    for (int pst = 0; pst < NSTAGE - 1; pst++) {
        fc_load_stage(sbase + pst * FC_STAGE, pst * 32, x0, lc, lr, lcb, lkr);
        CP_COMMIT();
    }

    const int NT = BH / 32;   // 32
    for (int it = 0; it < NT; it++) {
        CP_WAIT(NSTAGE - 2);
        __syncthreads();

        int pf = it + NSTAGE - 1;
        if (pf < NT)
            fc_load_stage(sbase + (pf % NSTAGE) * FC_STAGE, pf * 32, x0, lc, lr, lcb, lkr);
        CP_COMMIT();

        uint32_t st = sbase + (it % NSTAGE) * FC_STAGE;

        #pragma unroll
        for (int s = 0; s < 2; s++) {
            uint32_t ah[2][4];
            #pragma unroll
            for (int mi = 0; mi < 2; mi++) {
                uint32_t aaddr = st + (rowA + mi * 16) * 80 + (s * 2 + achnk) * 16;
                LDSM_X4(ah[mi][0], ah[mi][1], ah[mi][2], ah[mi][3], aaddr);
            }
            #pragma unroll
            for (int j = 0; j < 4; j++) {
                uint32_t bh[4];
                uint32_t baddr = st + FC_B_OFF + (s * 16 + kB) * 528 + noffB + j * 32;
                LDSM_X4_T(bh[0], bh[1], bh[2], bh[3], baddr);
                #pragma unroll
                for (int mi = 0; mi < 2; mi++)
                    #pragma unroll
                    for (int nn = 0; nn < 2; nn++) {
                        int j8 = j * 2 + nn, br = nn * 2;
                        MMA_F16(d[mi][j8], ah[mi], bh[br], bh[br + 1]);
                    }
            }
        }
    }

    // epilogue: bias + elu + residual
    #pragma unroll
    for (int mi = 0; mi < 2; mi++) {
        int row0 = x0 + warp_m + mi * 16 + (lane >> 2);
        #pragma unroll
        for (int j8 = 0; j8 < 8; j8++) {
            int col = warp_n + j8 * 8 + 2 * (lane & 3);
            float bv0 = bv[col], bv1 = bv[col + 1];
            #pragma unroll
            for (int hf = 0; hf < 2; hf++) {
                int row = row0 + hf * 8;
                float r0 = d[mi][j8][hf * 2]     + bv0;
                float r1 = d[mi][j8][hf * 2 + 1] + bv1;
                r0 = (r0 > 0.f) ? r0 : expm1f(r0);
                r1 = (r1 > 0.f) ? r1 : expm1f(r1);
                float2 v;
                v.x = r0 + h0[(size_t)row * H + col];
                v.y = r1 + h0[(size_t)row * H + col + 1];
                *(float2*)&out[(size_t)row * H + col] = v;
            }
        }
    }
}

// ---------------- kl scalar output ------------------------------------------
__global__ void k_klout(float* __restrict__ out, int out_size) {
    if (threadIdx.x == 0 && out_size > NN * H) {
        out[out_size - 1] = (float)(g_kl / (double)((size_t)NN * NN));
    }
}

// ---------------- launch -----------------------------------------------------
extern "C" void kernel_launch(void* const* d_in, const int* in_sizes, int n_in,
                              void* d_out, int out_size)
{
    const float* h     = (const float*)d_in[0];
    const float* gamma = (const float*)d_in[1];
    const float* beta  = (const float*)d_in[2];
    const float* Wk    = (const float*)d_in[3];
    const float* bk    = (const float*)d_in[4];
    const float* Wm    = (const float*)d_in[5];
    const float* bm    = (const float*)d_in[6];
    const float* Wl    = (const float*)d_in[7];
    const float* bl    = (const float*)d_in[8];
    const float* Wv    = (const float*)d_in[9];
    const float* bv    = (const float*)d_in[10];
    const float* diff  = (const float*)d_in[11];
    const float* eps   = (const float*)d_in[12];
    float* out = (float*)d_out;

    cudaFuncSetAttribute(k_scores_mma, cudaFuncAttributeMaxDynamicSharedMemorySize, SC_SMEM);
    cudaFuncSetAttribute(k_agg_mma,    cudaFuncAttributeMaxDynamicSharedMemorySize, AGG_SMEM);
    cudaFuncSetAttribute(k_fc_mma,     cudaFuncAttributeMaxDynamicSharedMemorySize, FC_SMEM);

    k_init<<<48, 256>>>();
    k_ln<<<NN, 256>>>(h, gamma, beta);
    k_wvh<<<BH * H / 256, 256>>>(Wv);
    k_proj<<<dim3(48, 12), 256>>>(Wk, bk, Wm, bm, Wl, bl);
    k_scores_mma<<<dim3(NB, 48, 48), 128, SC_SMEM>>>(diff, eps);
    k_agg_mma<<<dim3(24, NB), 256, AGG_SMEM>>>();
    k_fc_mma<<<48, 256, FC_SMEM>>>(bv, h, out);
    k_klout<<<1, 32>>>(out, out_size);
}

// round 9
// speedup vs baseline: 2.6557x; 1.1117x over previous
#include <cuda_runtime.h>
#include <cuda_fp16.h>
#include <math.h>
#include <stdint.h>

#define NN    3072
#define H     256
#define NB    4
#define HD    64
#define BH    1024   /* NB*H */

// ---------------- scratch (device globals) ----------------------------------
__device__ float   g_hn[NN * H];                       // 3 MB
__device__ __half  g_kh [NB * NN * HD];
__device__ __half  g_mub[NB * NN * HD];
__device__ __half  g_lsb[NB * NN * HD];
__device__ __half  g_a  [(size_t)NB * NN * NN];        // 75.5 MB
__device__ __half  g_hnh[(size_t)NN * H];              // 1.5 MB
__device__ __half  g_atth[(size_t)NN * BH];            // 6.3 MB
__device__ __half  g_wh[3 * H * H];                    // Wk,Wm,Wl fp16
__device__ __half  g_wvh[BH * H];                      // 0.5 MB
__device__ float   g_denom[NB * NN];
__device__ double  g_kl;

// ---------------- PTX helpers ------------------------------------------------
__device__ __forceinline__ uint32_t smem_u32(const void* p) {
    uint32_t a;
    asm("{ .reg .u64 t; cvta.to.shared.u64 t, %1; cvt.u32.u64 %0, t; }"
        : "=r"(a) : "l"(p));
    return a;
}
__device__ __forceinline__ void cp16(uint32_t s, const void* g) {
    asm volatile("cp.async.cg.shared.global [%0], [%1], 16;" :: "r"(s), "l"(g));
}
__device__ __forceinline__ void cp4(uint32_t s, const void* g) {
    asm volatile("cp.async.ca.shared.global [%0], [%1], 4;" :: "r"(s), "l"(g));
}
#define CP_COMMIT() asm volatile("cp.async.commit_group;" ::: "memory")
#define CP_WAIT(n)  asm volatile("cp.async.wait_group %0;" :: "n"(n) : "memory")

#define LDSM_X4(r0, r1, r2, r3, addr) \
    asm volatile("ldmatrix.sync.aligned.m8n8.x4.shared.b16 {%0,%1,%2,%3}, [%4];" \
                 : "=r"(r0), "=r"(r1), "=r"(r2), "=r"(r3) : "r"(addr))

#define LDSM_X4_T(r0, r1, r2, r3, addr) \
    asm volatile("ldmatrix.sync.aligned.m8n8.x4.trans.shared.b16 {%0,%1,%2,%3}, [%4];" \
                 : "=r"(r0), "=r"(r1), "=r"(r2), "=r"(r3) : "r"(addr))

#define MMA_F16(d, a, b0, b1) \
    asm volatile("mma.sync.aligned.m16n8k16.row.col.f32.f16.f16.f32 " \
                 "{%0,%1,%2,%3}, {%4,%5,%6,%7}, {%8,%9}, {%0,%1,%2,%3};" \
                 : "+f"((d)[0]), "+f"((d)[1]), "+f"((d)[2]), "+f"((d)[3]) \
                 : "r"((a)[0]), "r"((a)[1]), "r"((a)[2]), "r"((a)[3]), \
                   "r"(b0), "r"(b1))

// ---------------- weights -> fp16 + init --------------------------------------
// grid 1792 x 256: i < 3*65536 -> Wk/Wm/Wl ; else Wv. Also zero denom/kl.
__global__ void k_wh(const float* __restrict__ Wk, const float* __restrict__ Wm,
                     const float* __restrict__ Wl, const float* __restrict__ Wv)
{
    int i = blockIdx.x * 256 + threadIdx.x;
    const int PW = 3 * H * H;   // 196608
    if (i < PW) {
        int mat = i / (H * H), off = i % (H * H);
        const float* W = (mat == 0) ? Wk : (mat == 1) ? Wm : Wl;
        g_wh[i] = __float2half(W[off]);
    } else {
        g_wvh[i - PW] = __float2half(Wv[i - PW]);
    }
    if (i < NB * NN) g_denom[i] = 0.0f;
    if (i == 0) g_kl = 0.0;
}

// ---------------- layernorm (+ fp16 copy of hn) -------------------------------
__global__ void k_ln(const float* __restrict__ h,
                     const float* __restrict__ gamma,
                     const float* __restrict__ beta) {
    int row = blockIdx.x;
    int tid = threadIdx.x;
    float v = h[row * H + tid];

    __shared__ float red[8];
    float s = v;
    #pragma unroll
    for (int o = 16; o; o >>= 1) s += __shfl_xor_sync(0xffffffffu, s, o);
    if ((tid & 31) == 0) red[tid >> 5] = s;
    __syncthreads();
    float mean = 0.f;
    #pragma unroll
    for (int i = 0; i < 8; i++) mean += red[i];
    mean *= (1.0f / H);

    float d = v - mean;
    float q = d * d;
    #pragma unroll
    for (int o = 16; o; o >>= 1) q += __shfl_xor_sync(0xffffffffu, q, o);
    __syncthreads();
    if ((tid & 31) == 0) red[tid >> 5] = q;
    __syncthreads();
    float var = 0.f;
    #pragma unroll
    for (int i = 0; i < 8; i++) var += red[i];
    var *= (1.0f / H);

    float hn = d * rsqrtf(var + 1e-5f) * gamma[tid] + beta[tid];
    g_hn[row * H + tid]  = hn;
    g_hnh[row * H + tid] = __float2half(hn);
}

// ---------------- projections via fp16 mma ------------------------------------
// grid (48, 3): CTA = 64 rows x 256 cols, K = 256. 8 warps (2m x 4n, warp 32x64).
#define PJ_A_BYTES 5120                     /* 64*80 */
#define PJ_B_BYTES 16896                    /* 32*528 */
#define PJ_B_OFF   PJ_A_BYTES
#define PJ_STAGE (PJ_A_BYTES + PJ_B_BYTES)  /* 22016 */
#define NSTAGE   3
#define PJ_SMEM  (NSTAGE * PJ_STAGE)        /* 66048 */

__device__ __forceinline__ void pj_load_stage(uint32_t st, int kk, int x0,
                                              const __half* W,
                                              int lc, int lr, int lcb, int lkr)
{
    cp16(st + lr * 80 + lc * 16, g_hnh + (size_t)(x0 + lr) * H + kk + lc * 8);
    #pragma unroll
    for (int p = 0; p < 4; p++) {
        int kr = lkr + p * 8;
        cp16(st + PJ_B_OFF + kr * 528 + lcb * 16, W + (size_t)(kk + kr) * H + lcb * 8);
    }
}

__global__ void __launch_bounds__(256, 1) k_proj_mma(
    const float* __restrict__ bk, const float* __restrict__ bm,
    const float* __restrict__ bl)
{
    extern __shared__ char smc[];
    uint32_t sbase = smem_u32(smc);

    int tid  = threadIdx.x;
    int lane = tid & 31, wid = tid >> 5;
    int x0  = blockIdx.x * 64;
    int mat = blockIdx.y;

    const __half* W    = g_wh + (size_t)mat * H * H;
    const float*  bias = (mat == 0) ? bk : (mat == 1) ? bm : bl;
    __half* outp = (mat == 0) ? g_kh : (mat == 1) ? g_mub : g_lsb;
    float scl = (mat == 0) ? 0.125f : 1.0f;

    int warp_m = (wid & 1) * 32;
    int warp_n = (wid >> 1) * 64;

    int lc  = tid & 3,  lr  = tid >> 2;
    int lcb = tid & 31, lkr = tid >> 5;

    int rowA  = warp_m + (lane & 15);
    int achnk = lane >> 4;
    int kB    = (lane & 7) + 8 * ((lane >> 3) & 1);
    int noffB = (warp_n + ((lane >> 4) & 1) * 8) * 2;

    float d[2][8][4] = {};

    #pragma unroll
    for (int pst = 0; pst < NSTAGE - 1; pst++) {
        pj_load_stage(sbase + pst * PJ_STAGE, pst * 32, x0, W, lc, lr, lcb, lkr);
        CP_COMMIT();
    }

    const int NT = H / 32;   // 8
    for (int it = 0; it < NT; it++) {
        CP_WAIT(NSTAGE - 2);
        __syncthreads();

        int pf = it + NSTAGE - 1;
        if (pf < NT)
            pj_load_stage(sbase + (pf % NSTAGE) * PJ_STAGE, pf * 32, x0, W, lc, lr, lcb, lkr);
        CP_COMMIT();

        uint32_t st = sbase + (it % NSTAGE) * PJ_STAGE;

        #pragma unroll
        for (int s = 0; s < 2; s++) {
            uint32_t ah[2][4];
            #pragma unroll
            for (int mi = 0; mi < 2; mi++) {
                uint32_t aaddr = st + (rowA + mi * 16) * 80 + (s * 2 + achnk) * 16;
                LDSM_X4(ah[mi][0], ah[mi][1], ah[mi][2], ah[mi][3], aaddr);
            }
            #pragma unroll
            for (int j = 0; j < 4; j++) {
                uint32_t bh[4];
                uint32_t baddr = st + PJ_B_OFF + (s * 16 + kB) * 528 + noffB + j * 32;
                LDSM_X4_T(bh[0], bh[1], bh[2], bh[3], baddr);
                #pragma unroll
                for (int mi = 0; mi < 2; mi++)
                    #pragma unroll
                    for (int nn = 0; nn < 2; nn++) {
                        int j8 = j * 2 + nn, br = nn * 2;
                        MMA_F16(d[mi][j8], ah[mi], bh[br], bh[br + 1]);
                    }
            }
        }
    }

    // epilogue: bias + scale, scatter to head-major fp16
    #pragma unroll
    for (int mi = 0; mi < 2; mi++) {
        int row0 = x0 + warp_m + mi * 16 + (lane >> 2);
        #pragma unroll
        for (int j8 = 0; j8 < 8; j8++) {
            int col = warp_n + j8 * 8 + 2 * (lane & 3);
            float b0 = bias[col], b1 = bias[col + 1];
            int hb0 = col & 3,       dd0 = col >> 2;
            int hb1 = (col + 1) & 3, dd1 = (col + 1) >> 2;
            #pragma unroll
            for (int hf = 0; hf < 2; hf++) {
                int m = row0 + hf * 8;
                outp[((size_t)hb0 * NN + m) * HD + dd0] =
                    __float2half((d[mi][j8][hf * 2]     + b0) * scl);
                outp[((size_t)hb1 * NN + m) * HD + dd1] =
                    __float2half((d[mi][j8][hf * 2 + 1] + b1) * scl);
            }
        }
    }
}

// ---------------- scores: mma + prefetched eps/diff + elementwise -> a --------
// grid (NB, 48, 48): 64x64 tile per CTA, 128 thr = 4 warps (2m x 2n, warp 32x32)
#define SC_ROW 144
#define SC_HALF (64 * SC_ROW)     /* 9216 */
#define OFF_EPS (3 * SC_HALF)     /* 27648, 16384 bytes */
#define OFF_DIF (OFF_EPS + 16384) /* 44032, 16384 bytes */
#define SC_SMEM (OFF_DIF + 16384) /* 60416 */

__global__ void __launch_bounds__(128) k_scores_mma(const float* __restrict__ diffusion,
                                                    const float* __restrict__ eps)
{
    extern __shared__ char smc[];
    uint32_t sb = smem_u32(smc);

    int b  = blockIdx.x;
    int x0 = blockIdx.y * 64;
    int y0 = blockIdx.z * 64;
    int tid = threadIdx.x, lane = tid & 31, wid = tid >> 5;
    int warp_m = (wid & 1) * 32, warp_n = (wid >> 1) * 32;

    const __half* K  = g_kh  + ((size_t)b * NN + x0) * HD;
    const __half* MU = g_mub + ((size_t)b * NN + y0) * HD;
    const __half* LS = g_lsb + ((size_t)b * NN + y0) * HD;

    // group A: K/MU/LS tiles
    {
        int lc = tid & 7, lr = tid >> 3;
        #pragma unroll
        for (int p = 0; p < 4; p++) {
            int r = lr + p * 16;
            uint32_t so = r * SC_ROW + lc * 16;
            size_t  go = (size_t)r * HD + lc * 8;
            cp16(sb + 0 * SC_HALF + so, K  + go);
            cp16(sb + 1 * SC_HALF + so, MU + go);
            cp16(sb + 2 * SC_HALF + so, LS + go);
        }
    }
    CP_COMMIT();

    // group B: eps (4B strided) + diffusion (16B) tiles — overlapped with MMAs
    {
        #pragma unroll
        for (int i = 0; i < 32; i++) {
            int idx = tid + i * 128;
            int xl = idx >> 6, yl = idx & 63;
            cp4(sb + OFF_EPS + idx * 4,
                eps + ((size_t)(x0 + xl) * NN + y0 + yl) * NB + b);
        }
        #pragma unroll
        for (int i = 0; i < 8; i++) {
            int idx = tid + i * 128;
            int xl = idx >> 4, c = idx & 15;
            cp16(sb + OFF_DIF + xl * 256 + c * 16,
                 diffusion + (size_t)(x0 + xl) * NN + y0 + c * 4);
        }
    }
    CP_COMMIT();

    CP_WAIT(1);
    __syncthreads();

    float accm[2][4][4] = {}, accl[2][4][4] = {};
    int rA  = warp_m + (lane & 15);
    int cA8 = lane >> 4;
    int rB  = warp_n + (lane & 7) + 8 * ((lane >> 3) & 1);
    int cB8 = lane >> 4;

    #pragma unroll
    for (int s = 0; s < 4; s++) {
        uint32_t kh[2][4];
        #pragma unroll
        for (int mi = 0; mi < 2; mi++) {
            uint32_t a = sb + (rA + mi * 16) * SC_ROW + s * 32 + cA8 * 16;
            LDSM_X4(kh[mi][0], kh[mi][1], kh[mi][2], kh[mi][3], a);
        }
        uint32_t mh[2][4], lh[2][4];
        #pragma unroll
        for (int g = 0; g < 2; g++) {
            uint32_t bm = sb + SC_HALF + (rB + g * 16) * SC_ROW + s * 32 + cB8 * 16;
            LDSM_X4(mh[g][0], mh[g][1], mh[g][2], mh[g][3], bm);
            LDSM_X4(lh[g][0], lh[g][1], lh[g][2], lh[g][3], bm + SC_HALF);
        }
        #pragma unroll
        for (int mi = 0; mi < 2; mi++)
            #pragma unroll
            for (int g = 0; g < 2; g++)
                #pragma unroll
                for (int nn = 0; nn < 2; nn++) {
                    int n8 = g * 2 + nn;
                    MMA_F16(accm[mi][n8], kh[mi], mh[g][nn], mh[g][nn + 2]);
                    MMA_F16(accl[mi][n8], kh[mi], lh[g][nn], lh[g][nn + 2]);
                }
    }

    CP_WAIT(0);
    __syncthreads();

    const float* eps_s = (const float*)(smc + OFF_EPS);
    const float* dif_s = (const float*)(smc + OFF_DIF);

    float klsum = 0.f;
    float rsum[2][2] = {{0.f, 0.f}, {0.f, 0.f}};

    #pragma unroll
    for (int mi = 0; mi < 2; mi++) {
        int xl0 = warp_m + mi * 16 + (lane >> 2);
        #pragma unroll
        for (int n8 = 0; n8 < 4; n8++) {
            int yl = warp_n + n8 * 8 + 2 * (lane & 3);
            #pragma unroll
            for (int hf = 0; hf < 2; hf++) {
                int xl = xl0 + hf * 8;
                float2 dif = *(const float2*)&dif_s[xl * 64 + yl];
                float e0 = eps_s[xl * 64 + yl];
                float e1 = eps_s[xl * 64 + yl + 1];
                float smu0 = accm[mi][n8][hf * 2],     sls0 = accl[mi][n8][hf * 2];
                float smu1 = accm[mi][n8][hf * 2 + 1], sls1 = accl[mi][n8][hf * 2 + 1];
                float sig0 = fmaxf(sls0, 0.f) + __logf(1.f + __expf(-fabsf(sls0)));
                float sig1 = fmaxf(sls1, 0.f) + __logf(1.f + __expf(-fabsf(sls1)));
                float kle0 = 0.5f * (sig0 * sig0 + smu0 * smu0) - __logf(sig0) - 0.5f;
                float kle1 = 0.5f * (sig1 * sig1 + smu1 * smu1) - __logf(sig1) - 0.5f;
                float sg0 = (dif.x > 0.f) ? 1.f : ((dif.x < 0.f) ? -1.f : 0.f);
                float sg1 = (dif.y > 0.f) ? 1.f : ((dif.y < 0.f) ? -1.f : 0.f);
                klsum += kle0 * sg0 + kle1 * sg1;
                float a0 = __expf(smu0 + sig0 * e0) * dif.x;
                float a1 = __expf(smu1 + sig1 * e1) * dif.y;
                __half2 av;
                av.x = __float2half(a0);
                av.y = __float2half(a1);
                rsum[mi][hf] += fabsf(__half2float(av.x)) + fabsf(__half2float(av.y));
                *(__half2*)(smc + xl * SC_ROW + yl * 2) = av;
            }
        }
    }

    // per-row denominators
    #pragma unroll
    for (int mi = 0; mi < 2; mi++)
        #pragma unroll
        for (int hf = 0; hf < 2; hf++) {
            float r = rsum[mi][hf];
            r += __shfl_xor_sync(0xffffffffu, r, 1);
            r += __shfl_xor_sync(0xffffffffu, r, 2);
            if ((lane & 3) == 0)
                atomicAdd(&g_denom[b * NN + x0 + warp_m + mi * 16 + hf * 8 + (lane >> 2)], r);
        }

    // KL
    #pragma unroll
    for (int o = 16; o; o >>= 1) klsum += __shfl_xor_sync(0xffffffffu, klsum, o);
    __shared__ float kred[4];
    if (lane == 0) kred[wid] = klsum;
    __syncthreads();
    if (tid == 0) {
        atomicAdd(&g_kl, (double)(kred[0] + kred[1] + kred[2] + kred[3]));
    }

    // coalesced copy-out
    __half* dst = g_a + (size_t)b * NN * NN;
    for (int t = tid; t < 512; t += 128) {
        int r = t >> 3, c = t & 7;
        size_t go = (size_t)(x0 + r) * NN + y0 + c * 8;
        *(float4*)&dst[go] = *(float4*)(smc + r * SC_ROW + c * 16);
    }
}

// ---------------- aggregation: a(fp16) x hn(fp16) mma, CTA 128x256 ------------
#define A_BYTES  10240                      /* 128*80 */
#define B_BYTES  16896                      /* 32*528 */
#define ST_B_OFF A_BYTES
#define STAGE_BYTES (A_BYTES + B_BYTES)     /* 27136 */
#define AGG_SMEM (NSTAGE * STAGE_BYTES)     /* 81408 */

__device__ __forceinline__ void agg_load_stage(
    uint32_t st, int kk, int x0, const __half* A,
    int lc, int lr, int lcb, int lkr)
{
    #pragma unroll
    for (int p = 0; p < 2; p++) {
        int r = lr + p * 64;
        cp16(st + r * 80 + lc * 16, A + (size_t)(x0 + r) * NN + kk + lc * 8);
    }
    #pragma unroll
    for (int p = 0; p < 4; p++) {
        int kr = lkr + p * 8;
        cp16(st + ST_B_OFF + kr * 528 + lcb * 16, g_hnh + (size_t)(kk + kr) * H + lcb * 8);
    }
}

__global__ void __launch_bounds__(256, 1) k_agg_mma()
{
    extern __shared__ char smc[];
    uint32_t sbase = smem_u32(smc);

    int tid  = threadIdx.x;
    int lane = tid & 31, wid = tid >> 5;
    int x0 = blockIdx.x * 128;
    int b  = blockIdx.y;

    const __half* A = g_a + (size_t)b * NN * NN;

    int warp_m = (wid & 1) * 64;
    int warp_n = (wid >> 1) * 64;

    int lc  = tid & 3,  lr  = tid >> 2;
    int lcb = tid & 31, lkr = tid >> 5;

    int rowA  = warp_m + (lane & 15);
    int achnk = lane >> 4;
    int kB    = (lane & 7) + 8 * ((lane >> 3) & 1);
    int noffB = (warp_n + ((lane >> 4) & 1) * 8) * 2;

    float d[4][8][4] = {};

    #pragma unroll
    for (int pst = 0; pst < NSTAGE - 1; pst++) {
        agg_load_stage(sbase + pst * STAGE_BYTES, pst * 32, x0, A, lc, lr, lcb, lkr);
        CP_COMMIT();
    }

    const int NT = NN / 32;   // 96
    for (int it = 0; it < NT; it++) {
        CP_WAIT(NSTAGE - 2);
        __syncthreads();

        int pf = it + NSTAGE - 1;
        if (pf < NT)
            agg_load_stage(sbase + (pf % NSTAGE) * STAGE_BYTES, pf * 32, x0, A, lc, lr, lcb, lkr);
        CP_COMMIT();

        uint32_t st = sbase + (it % NSTAGE) * STAGE_BYTES;

        #pragma unroll
        for (int s = 0; s < 2; s++) {
            uint32_t ah[4][4];
            #pragma unroll
            for (int mi = 0; mi < 4; mi++) {
                uint32_t aaddr = st + (rowA + mi * 16) * 80 + (s * 2 + achnk) * 16;
                LDSM_X4(ah[mi][0], ah[mi][1], ah[mi][2], ah[mi][3], aaddr);
            }
            #pragma unroll
            for (int j = 0; j < 4; j++) {
                uint32_t bh[4];
                uint32_t baddr = st + ST_B_OFF + (s * 16 + kB) * 528 + noffB + j * 32;
                LDSM_X4_T(bh[0], bh[1], bh[2], bh[3], baddr);
                #pragma unroll
                for (int mi = 0; mi < 4; mi++)
                    #pragma unroll
                    for (int nn = 0; nn < 2; nn++) {
                        int j8 = j * 2 + nn, br = nn * 2;
                        MMA_F16(d[mi][j8], ah[mi], bh[br], bh[br + 1]);
                    }
            }
        }
    }

    // epilogue: normalize, store att as fp16
    #pragma unroll
    for (int mi = 0; mi < 4; mi++) {
        int row0 = x0 + warp_m + mi * 16 + (lane >> 2);
        float invd0 = 1.0f / fmaxf(g_denom[b * NN + row0],     1e-12f);
        float invd1 = 1.0f / fmaxf(g_denom[b * NN + row0 + 8], 1e-12f);
        #pragma unroll
        for (int j8 = 0; j8 < 8; j8++) {
            int col = b * 256 + warp_n + j8 * 8 + 2 * (lane & 3);
            __half2 v0, v1;
            v0.x = __float2half(d[mi][j8][0] * invd0);
            v0.y = __float2half(d[mi][j8][1] * invd0);
            v1.x = __float2half(d[mi][j8][2] * invd1);
            v1.y = __float2half(d[mi][j8][3] * invd1);
            *(__half2*)&g_atth[(size_t)row0 * BH + col]       = v0;
            *(__half2*)&g_atth[(size_t)(row0 + 8) * BH + col] = v1;
        }
    }
}

// ---------------- fc_v via fp16 mma + elu + residual --------------------------
// grid (48): CTA = 64 rows x 256 cols, K = 1024. 8 warps (2m x 4n, warp 32x64).
#define FC_A_BYTES 5120
#define FC_B_BYTES 16896
#define FC_B_OFF   FC_A_BYTES
#define FC_STAGE (FC_A_BYTES + FC_B_BYTES)
#define FC_SMEM  (NSTAGE * FC_STAGE)

__device__ __forceinline__ void fc_load_stage(uint32_t st, int kk, int x0,
                                              int lc, int lr, int lcb, int lkr)
{
    cp16(st + lr * 80 + lc * 16, g_atth + (size_t)(x0 + lr) * BH + kk + lc * 8);
    #pragma unroll
    for (int p = 0; p < 4; p++) {
        int kr = lkr + p * 8;
        cp16(st + FC_B_OFF + kr * 528 + lcb * 16, g_wvh + (size_t)(kk + kr) * H + lcb * 8);
    }
}

__global__ void __launch_bounds__(256, 1) k_fc_mma(const float* __restrict__ bv,
                                                   const float* __restrict__ h0,
                                                   float* __restrict__ out)
{
    extern __shared__ char smc[];
    uint32_t sbase = smem_u32(smc);

    int tid  = threadIdx.x;
    int lane = tid & 31, wid = tid >> 5;
    int x0 = blockIdx.x * 64;

    int warp_m = (wid & 1) * 32;
    int warp_n = (wid >> 1) * 64;

    int lc  = tid & 3,  lr  = tid >> 2;
    int lcb = tid & 31, lkr = tid >> 5;

    int rowA  = warp_m + (lane & 15);
    int achnk = lane >> 4;
    int kB    = (lane & 7) + 8 * ((lane >> 3) & 1);
    int noffB = (warp_n + ((lane >> 4) & 1) * 8) * 2;

    float d[2][8][4] = {};

    #pragma unroll
    for (int pst = 0; pst < NSTAGE - 1; pst++) {
        fc_load_stage(sbase + pst * FC_STAGE, pst * 32, x0, lc, lr, lcb, lkr);
        CP_COMMIT();
    }

    const int NT = BH / 32;   // 32
    for (int it = 0; it < NT; it++) {
        CP_WAIT(NSTAGE - 2);
        __syncthreads();

        int pf = it + NSTAGE - 1;
        if (pf < NT)
            fc_load_stage(sbase + (pf % NSTAGE) * FC_STAGE, pf * 32, x0, lc, lr, lcb, lkr);
        CP_COMMIT();

        uint32_t st = sbase + (it % NSTAGE) * FC_STAGE;

        #pragma unroll
        for (int s = 0; s < 2; s++) {
            uint32_t ah[2][4];
            #pragma unroll
            for (int mi = 0; mi < 2; mi++) {
                uint32_t aaddr = st + (rowA + mi * 16) * 80 + (s * 2 + achnk) * 16;
                LDSM_X4(ah[mi][0], ah[mi][1], ah[mi][2], ah[mi][3], aaddr);
            }
            #pragma unroll
            for (int j = 0; j < 4; j++) {
                uint32_t bh[4];
                uint32_t baddr = st + FC_B_OFF + (s * 16 + kB) * 528 + noffB + j * 32;
                LDSM_X4_T(bh[0], bh[1], bh[2], bh[3], baddr);
                #pragma unroll
                for (int mi = 0; mi < 2; mi++)
                    #pragma unroll
                    for (int nn = 0; nn < 2; nn++) {
                        int j8 = j * 2 + nn, br = nn * 2;
                        MMA_F16(d[mi][j8], ah[mi], bh[br], bh[br + 1]);
                    }
            }
        }
    }

    // epilogue: bias + elu + residual
    #pragma unroll
    for (int mi = 0; mi < 2; mi++) {
        int row0 = x0 + warp_m + mi * 16 + (lane >> 2);
        #pragma unroll
        for (int j8 = 0; j8 < 8; j8++) {
            int col = warp_n + j8 * 8 + 2 * (lane & 3);
            float bv0 = bv[col], bv1 = bv[col + 1];
            #pragma unroll
            for (int hf = 0; hf < 2; hf++) {
                int row = row0 + hf * 8;
                float r0 = d[mi][j8][hf * 2]     + bv0;
                float r1 = d[mi][j8][hf * 2 + 1] + bv1;
                r0 = (r0 > 0.f) ? r0 : expm1f(r0);
                r1 = (r1 > 0.f) ? r1 : expm1f(r1);
                float2 v;
                v.x = r0 + h0[(size_t)row * H + col];
                v.y = r1 + h0[(size_t)row * H + col + 1];
                *(float2*)&out[(size_t)row * H + col] = v;
            }
        }
    }
}

// ---------------- kl scalar output ------------------------------------------
__global__ void k_klout(float* __restrict__ out, int out_size) {
    if (threadIdx.x == 0 && out_size > NN * H) {
        out[out_size - 1] = (float)(g_kl / (double)((size_t)NN * NN));
    }
}

// ---------------- launch -----------------------------------------------------
extern "C" void kernel_launch(void* const* d_in, const int* in_sizes, int n_in,
                              void* d_out, int out_size)
{
    const float* h     = (const float*)d_in[0];
    const float* gamma = (const float*)d_in[1];
    const float* beta  = (const float*)d_in[2];
    const float* Wk    = (const float*)d_in[3];
    const float* bk    = (const float*)d_in[4];
    const float* Wm    = (const float*)d_in[5];
    const float* bm    = (const float*)d_in[6];
    const float* Wl    = (const float*)d_in[7];
    const float* bl    = (const float*)d_in[8];
    const float* Wv    = (const float*)d_in[9];
    const float* bv    = (const float*)d_in[10];
    const float* diff  = (const float*)d_in[11];
    const float* eps   = (const float*)d_in[12];
    float* out = (float*)d_out;

    cudaFuncSetAttribute(k_proj_mma,   cudaFuncAttributeMaxDynamicSharedMemorySize, PJ_SMEM);
    cudaFuncSetAttribute(k_scores_mma, cudaFuncAttributeMaxDynamicSharedMemorySize, SC_SMEM);
    cudaFuncSetAttribute(k_agg_mma,    cudaFuncAttributeMaxDynamicSharedMemorySize, AGG_SMEM);
    cudaFuncSetAttribute(k_fc_mma,     cudaFuncAttributeMaxDynamicSharedMemorySize, FC_SMEM);

    k_wh<<<(3 * H * H + BH * H) / 256, 256>>>(Wk, Wm, Wl, Wv);
    k_ln<<<NN, 256>>>(h, gamma, beta);
    k_proj_mma<<<dim3(48, 3), 256, PJ_SMEM>>>(bk, bm, bl);
    k_scores_mma<<<dim3(NB, 48, 48), 128, SC_SMEM>>>(diff, eps);
    k_agg_mma<<<dim3(24, NB), 256, AGG_SMEM>>>();
    k_fc_mma<<<48, 256, FC_SMEM>>>(bv, h, out);
    k_klout<<<1, 32>>>(out, out_size);
}

// round 10
// speedup vs baseline: 2.7160x; 1.0227x over previous
#include <cuda_runtime.h>
#include <cuda_fp16.h>
#include <math.h>
#include <stdint.h>

#define NN    3072
#define H     256
#define NB    4
#define HD    64
#define BH    1024   /* NB*H */

// ---------------- scratch (device globals) ----------------------------------
__device__ float   g_hn[NN * H];                       // 3 MB
__device__ __half  g_kh [NB * NN * HD];
__device__ __half  g_mub[NB * NN * HD];
__device__ __half  g_lsb[NB * NN * HD];
__device__ __half  g_a  [(size_t)NB * NN * NN];        // 75.5 MB
__device__ __half  g_hnh[(size_t)NN * H];              // 1.5 MB
__device__ __half  g_atth[(size_t)NN * BH];            // 6.3 MB
__device__ __half  g_wh[3 * H * H];                    // Wk,Wm,Wl fp16
__device__ __half  g_wvh[BH * H];                      // 0.5 MB
__device__ float   g_denom[NB * NN];
__device__ double  g_kl;

// ---------------- PTX helpers ------------------------------------------------
__device__ __forceinline__ uint32_t smem_u32(const void* p) {
    uint32_t a;
    asm("{ .reg .u64 t; cvta.to.shared.u64 t, %1; cvt.u32.u64 %0, t; }"
        : "=r"(a) : "l"(p));
    return a;
}
__device__ __forceinline__ void cp16(uint32_t s, const void* g) {
    asm volatile("cp.async.cg.shared.global [%0], [%1], 16;" :: "r"(s), "l"(g));
}
__device__ __forceinline__ void cp4(uint32_t s, const void* g) {
    asm volatile("cp.async.ca.shared.global [%0], [%1], 4;" :: "r"(s), "l"(g));
}
#define CP_COMMIT() asm volatile("cp.async.commit_group;" ::: "memory")
#define CP_WAIT(n)  asm volatile("cp.async.wait_group %0;" :: "n"(n) : "memory")

#define LDSM_X4(r0, r1, r2, r3, addr) \
    asm volatile("ldmatrix.sync.aligned.m8n8.x4.shared.b16 {%0,%1,%2,%3}, [%4];" \
                 : "=r"(r0), "=r"(r1), "=r"(r2), "=r"(r3) : "r"(addr))

#define LDSM_X4_T(r0, r1, r2, r3, addr) \
    asm volatile("ldmatrix.sync.aligned.m8n8.x4.trans.shared.b16 {%0,%1,%2,%3}, [%4];" \
                 : "=r"(r0), "=r"(r1), "=r"(r2), "=r"(r3) : "r"(addr))

#define MMA_F16(d, a, b0, b1) \
    asm volatile("mma.sync.aligned.m16n8k16.row.col.f32.f16.f16.f32 " \
                 "{%0,%1,%2,%3}, {%4,%5,%6,%7}, {%8,%9}, {%0,%1,%2,%3};" \
                 : "+f"((d)[0]), "+f"((d)[1]), "+f"((d)[2]), "+f"((d)[3]) \
                 : "r"((a)[0]), "r"((a)[1]), "r"((a)[2]), "r"((a)[3]), \
                   "r"(b0), "r"(b1))

// ---------------- weights -> fp16 + init --------------------------------------
__global__ void k_wh(const float* __restrict__ Wk, const float* __restrict__ Wm,
                     const float* __restrict__ Wl, const float* __restrict__ Wv)
{
    int i = blockIdx.x * 256 + threadIdx.x;
    const int PW = 3 * H * H;   // 196608
    if (i < PW) {
        int mat = i / (H * H), off = i % (H * H);
        const float* W = (mat == 0) ? Wk : (mat == 1) ? Wm : Wl;
        g_wh[i] = __float2half(W[off]);
    } else {
        g_wvh[i - PW] = __float2half(Wv[i - PW]);
    }
    if (i < NB * NN) g_denom[i] = 0.0f;
    if (i == 0) g_kl = 0.0;
}

// ---------------- layernorm (+ fp16 copy of hn) -------------------------------
__global__ void k_ln(const float* __restrict__ h,
                     const float* __restrict__ gamma,
                     const float* __restrict__ beta) {
    int row = blockIdx.x;
    int tid = threadIdx.x;
    float v = h[row * H + tid];

    __shared__ float red[8];
    float s = v;
    #pragma unroll
    for (int o = 16; o; o >>= 1) s += __shfl_xor_sync(0xffffffffu, s, o);
    if ((tid & 31) == 0) red[tid >> 5] = s;
    __syncthreads();
    float mean = 0.f;
    #pragma unroll
    for (int i = 0; i < 8; i++) mean += red[i];
    mean *= (1.0f / H);

    float d = v - mean;
    float q = d * d;
    #pragma unroll
    for (int o = 16; o; o >>= 1) q += __shfl_xor_sync(0xffffffffu, q, o);
    __syncthreads();
    if ((tid & 31) == 0) red[tid >> 5] = q;
    __syncthreads();
    float var = 0.f;
    #pragma unroll
    for (int i = 0; i < 8; i++) var += red[i];
    var *= (1.0f / H);

    float hn = d * rsqrtf(var + 1e-5f) * gamma[tid] + beta[tid];
    g_hn[row * H + tid]  = hn;
    g_hnh[row * H + tid] = __float2half(hn);
}

// ---------------- projections via fp16 mma ------------------------------------
#define PJ_A_BYTES 5120
#define PJ_B_BYTES 16896
#define PJ_B_OFF   PJ_A_BYTES
#define PJ_STAGE (PJ_A_BYTES + PJ_B_BYTES)
#define NSTAGE   3
#define PJ_SMEM  (NSTAGE * PJ_STAGE)

__device__ __forceinline__ void pj_load_stage(uint32_t st, int kk, int x0,
                                              const __half* W,
                                              int lc, int lr, int lcb, int lkr)
{
    cp16(st + lr * 80 + lc * 16, g_hnh + (size_t)(x0 + lr) * H + kk + lc * 8);
    #pragma unroll
    for (int p = 0; p < 4; p++) {
        int kr = lkr + p * 8;
        cp16(st + PJ_B_OFF + kr * 528 + lcb * 16, W + (size_t)(kk + kr) * H + lcb * 8);
    }
}

__global__ void __launch_bounds__(256, 1) k_proj_mma(
    const float* __restrict__ bk, const float* __restrict__ bm,
    const float* __restrict__ bl)
{
    extern __shared__ char smc[];
    uint32_t sbase = smem_u32(smc);

    int tid  = threadIdx.x;
    int lane = tid & 31, wid = tid >> 5;
    int x0  = blockIdx.x * 64;
    int mat = blockIdx.y;

    const __half* W    = g_wh + (size_t)mat * H * H;
    const float*  bias = (mat == 0) ? bk : (mat == 1) ? bm : bl;
    __half* outp = (mat == 0) ? g_kh : (mat == 1) ? g_mub : g_lsb;
    float scl = (mat == 0) ? 0.125f : 1.0f;

    int warp_m = (wid & 1) * 32;
    int warp_n = (wid >> 1) * 64;

    int lc  = tid & 3,  lr  = tid >> 2;
    int lcb = tid & 31, lkr = tid >> 5;

    int rowA  = warp_m + (lane & 15);
    int achnk = lane >> 4;
    int kB    = (lane & 7) + 8 * ((lane >> 3) & 1);
    int noffB = (warp_n + ((lane >> 4) & 1) * 8) * 2;

    float d[2][8][4] = {};

    #pragma unroll
    for (int pst = 0; pst < NSTAGE - 1; pst++) {
        pj_load_stage(sbase + pst * PJ_STAGE, pst * 32, x0, W, lc, lr, lcb, lkr);
        CP_COMMIT();
    }

    const int NT = H / 32;   // 8
    for (int it = 0; it < NT; it++) {
        CP_WAIT(NSTAGE - 2);
        __syncthreads();

        int pf = it + NSTAGE - 1;
        if (pf < NT)
            pj_load_stage(sbase + (pf % NSTAGE) * PJ_STAGE, pf * 32, x0, W, lc, lr, lcb, lkr);
        CP_COMMIT();

        uint32_t st = sbase + (it % NSTAGE) * PJ_STAGE;

        #pragma unroll
        for (int s = 0; s < 2; s++) {
            uint32_t ah[2][4];
            #pragma unroll
            for (int mi = 0; mi < 2; mi++) {
                uint32_t aaddr = st + (rowA + mi * 16) * 80 + (s * 2 + achnk) * 16;
                LDSM_X4(ah[mi][0], ah[mi][1], ah[mi][2], ah[mi][3], aaddr);
            }
            #pragma unroll
            for (int j = 0; j < 4; j++) {
                uint32_t bh[4];
                uint32_t baddr = st + PJ_B_OFF + (s * 16 + kB) * 528 + noffB + j * 32;
                LDSM_X4_T(bh[0], bh[1], bh[2], bh[3], baddr);
                #pragma unroll
                for (int mi = 0; mi < 2; mi++)
                    #pragma unroll
                    for (int nn = 0; nn < 2; nn++) {
                        int j8 = j * 2 + nn, br = nn * 2;
                        MMA_F16(d[mi][j8], ah[mi], bh[br], bh[br + 1]);
                    }
            }
        }
    }

    #pragma unroll
    for (int mi = 0; mi < 2; mi++) {
        int row0 = x0 + warp_m + mi * 16 + (lane >> 2);
        #pragma unroll
        for (int j8 = 0; j8 < 8; j8++) {
            int col = warp_n + j8 * 8 + 2 * (lane & 3);
            float b0 = bias[col], b1 = bias[col + 1];
            int hb0 = col & 3,       dd0 = col >> 2;
            int hb1 = (col + 1) & 3, dd1 = (col + 1) >> 2;
            #pragma unroll
            for (int hf = 0; hf < 2; hf++) {
                int m = row0 + hf * 8;
                outp[((size_t)hb0 * NN + m) * HD + dd0] =
                    __float2half((d[mi][j8][hf * 2]     + b0) * scl);
                outp[((size_t)hb1 * NN + m) * HD + dd1] =
                    __float2half((d[mi][j8][hf * 2 + 1] + b1) * scl);
            }
        }
    }
}

// ---------------- scores: 256 thr, 64x64 tile, warp 32x16 ---------------------
// grid (NB, 48, 48). 8 warps = 2m x 4n. Same smem, double the warps/SM.
#define SC_ROW 144
#define SC_HALF (64 * SC_ROW)     /* 9216 */
#define OFF_EPS (3 * SC_HALF)     /* 27648, 16384 bytes */
#define OFF_DIF (OFF_EPS + 16384) /* 44032, 16384 bytes */
#define SC_SMEM (OFF_DIF + 16384) /* 60416 */

__global__ void __launch_bounds__(256) k_scores_mma(const float* __restrict__ diffusion,
                                                    const float* __restrict__ eps)
{
    extern __shared__ char smc[];
    uint32_t sb = smem_u32(smc);

    int b  = blockIdx.x;
    int x0 = blockIdx.y * 64;
    int y0 = blockIdx.z * 64;
    int tid = threadIdx.x, lane = tid & 31, wid = tid >> 5;
    int warp_m = (wid & 1) * 32, warp_n = (wid >> 1) * 16;

    const __half* K  = g_kh  + ((size_t)b * NN + x0) * HD;
    const __half* MU = g_mub + ((size_t)b * NN + y0) * HD;
    const __half* LS = g_lsb + ((size_t)b * NN + y0) * HD;

    // group A: K/MU/LS tiles (64 rows x 8 chunks each, 256 threads)
    {
        int lc = tid & 7, lr = tid >> 3;   // chunk 0-7, row 0-31
        #pragma unroll
        for (int p = 0; p < 2; p++) {
            int r = lr + p * 32;
            uint32_t so = r * SC_ROW + lc * 16;
            size_t  go = (size_t)r * HD + lc * 8;
            cp16(sb + 0 * SC_HALF + so, K  + go);
            cp16(sb + 1 * SC_HALF + so, MU + go);
            cp16(sb + 2 * SC_HALF + so, LS + go);
        }
    }
    CP_COMMIT();

    // group B: eps (4B strided) + diffusion (16B) — overlapped with MMAs
    {
        #pragma unroll
        for (int i = 0; i < 16; i++) {
            int idx = tid + i * 256;
            int xl = idx >> 6, yl = idx & 63;
            cp4(sb + OFF_EPS + idx * 4,
                eps + ((size_t)(x0 + xl) * NN + y0 + yl) * NB + b);
        }
        #pragma unroll
        for (int i = 0; i < 4; i++) {
            int idx = tid + i * 256;
            int xl = idx >> 4, c = idx & 15;
            cp16(sb + OFF_DIF + xl * 256 + c * 16,
                 diffusion + (size_t)(x0 + xl) * NN + y0 + c * 4);
        }
    }
    CP_COMMIT();

    CP_WAIT(1);          // group A resident
    __syncthreads();

    float accm[2][2][4] = {}, accl[2][2][4] = {};
    int rA  = warp_m + (lane & 15);
    int cA8 = lane >> 4;
    int rB  = warp_n + (lane & 7) + 8 * ((lane >> 3) & 1);
    int cB8 = lane >> 4;

    #pragma unroll
    for (int s = 0; s < 4; s++) {
        uint32_t kh[2][4];
        #pragma unroll
        for (int mi = 0; mi < 2; mi++) {
            uint32_t a = sb + (rA + mi * 16) * SC_ROW + s * 32 + cA8 * 16;
            LDSM_X4(kh[mi][0], kh[mi][1], kh[mi][2], kh[mi][3], a);
        }
        uint32_t mh[4], lh[4];
        {
            uint32_t bm = sb + SC_HALF + rB * SC_ROW + s * 32 + cB8 * 16;
            LDSM_X4(mh[0], mh[1], mh[2], mh[3], bm);
            LDSM_X4(lh[0], lh[1], lh[2], lh[3], bm + SC_HALF);
        }
        #pragma unroll
        for (int mi = 0; mi < 2; mi++)
            #pragma unroll
            for (int nn = 0; nn < 2; nn++) {
                MMA_F16(accm[mi][nn], kh[mi], mh[nn], mh[nn + 2]);
                MMA_F16(accl[mi][nn], kh[mi], lh[nn], lh[nn + 2]);
            }
    }

    CP_WAIT(0);          // eps/diff resident
    __syncthreads();     // tiles dead — reuse [0, SC_HALF) as fp16 staging

    const float* eps_s = (const float*)(smc + OFF_EPS);
    const float* dif_s = (const float*)(smc + OFF_DIF);

    float klsum = 0.f;
    float rsum[2][2] = {{0.f, 0.f}, {0.f, 0.f}};

    #pragma unroll
    for (int mi = 0; mi < 2; mi++) {
        int xl0 = warp_m + mi * 16 + (lane >> 2);
        #pragma unroll
        for (int nn = 0; nn < 2; nn++) {
            int yl = warp_n + nn * 8 + 2 * (lane & 3);
            #pragma unroll
            for (int hf = 0; hf < 2; hf++) {
                int xl = xl0 + hf * 8;
                float2 dif = *(const float2*)&dif_s[xl * 64 + yl];
                float e0 = eps_s[xl * 64 + yl];
                float e1 = eps_s[xl * 64 + yl + 1];
                float smu0 = accm[mi][nn][hf * 2],     sls0 = accl[mi][nn][hf * 2];
                float smu1 = accm[mi][nn][hf * 2 + 1], sls1 = accl[mi][nn][hf * 2 + 1];
                float sig0 = fmaxf(sls0, 0.f) + __logf(1.f + __expf(-fabsf(sls0)));
                float sig1 = fmaxf(sls1, 0.f) + __logf(1.f + __expf(-fabsf(sls1)));
                float kle0 = 0.5f * (sig0 * sig0 + smu0 * smu0) - __logf(sig0) - 0.5f;
                float kle1 = 0.5f * (sig1 * sig1 + smu1 * smu1) - __logf(sig1) - 0.5f;
                float sg0 = (dif.x > 0.f) ? 1.f : ((dif.x < 0.f) ? -1.f : 0.f);
                float sg1 = (dif.y > 0.f) ? 1.f : ((dif.y < 0.f) ? -1.f : 0.f);
                klsum += kle0 * sg0 + kle1 * sg1;
                float a0 = __expf(smu0 + sig0 * e0) * dif.x;
                float a1 = __expf(smu1 + sig1 * e1) * dif.y;
                __half2 av;
                av.x = __float2half(a0);
                av.y = __float2half(a1);
                rsum[mi][hf] += fabsf(__half2float(av.x)) + fabsf(__half2float(av.y));
                *(__half2*)(smc + xl * SC_ROW + yl * 2) = av;
            }
        }
    }

    // per-row denominators (each warp covers 16 cols of the row)
    #pragma unroll
    for (int mi = 0; mi < 2; mi++)
        #pragma unroll
        for (int hf = 0; hf < 2; hf++) {
            float r = rsum[mi][hf];
            r += __shfl_xor_sync(0xffffffffu, r, 1);
            r += __shfl_xor_sync(0xffffffffu, r, 2);
            if ((lane & 3) == 0)
                atomicAdd(&g_denom[b * NN + x0 + warp_m + mi * 16 + hf * 8 + (lane >> 2)], r);
        }

    // KL
    #pragma unroll
    for (int o = 16; o; o >>= 1) klsum += __shfl_xor_sync(0xffffffffu, klsum, o);
    __shared__ float kred[8];
    if (lane == 0) kred[wid] = klsum;
    __syncthreads();
    if (tid == 0) {
        float s = 0.f;
        #pragma unroll
        for (int i = 0; i < 8; i++) s += kred[i];
        atomicAdd(&g_kl, (double)s);
    }

    // coalesced copy-out (512 float4 over 256 threads)
    __half* dst = g_a + (size_t)b * NN * NN;
    #pragma unroll
    for (int i = 0; i < 2; i++) {
        int t = tid + i * 256;
        int r = t >> 3, c = t & 7;
        size_t go = (size_t)(x0 + r) * NN + y0 + c * 8;
        *(float4*)&dst[go] = *(float4*)(smc + r * SC_ROW + c * 16);
    }
}

// ---------------- aggregation: a(fp16) x hn(fp16) mma, CTA 128x256 ------------
#define A_BYTES  10240
#define B_BYTES  16896
#define ST_B_OFF A_BYTES
#define STAGE_BYTES (A_BYTES + B_BYTES)
#define AGG_SMEM (NSTAGE * STAGE_BYTES)

__device__ __forceinline__ void agg_load_stage(
    uint32_t st, int kk, int x0, const __half* A,
    int lc, int lr, int lcb, int lkr)
{
    #pragma unroll
    for (int p = 0; p < 2; p++) {
        int r = lr + p * 64;
        cp16(st + r * 80 + lc * 16, A + (size_t)(x0 + r) * NN + kk + lc * 8);
    }
    #pragma unroll
    for (int p = 0; p < 4; p++) {
        int kr = lkr + p * 8;
        cp16(st + ST_B_OFF + kr * 528 + lcb * 16, g_hnh + (size_t)(kk + kr) * H + lcb * 8);
    }
}

__global__ void __launch_bounds__(256, 1) k_agg_mma()
{
    extern __shared__ char smc[];
    uint32_t sbase = smem_u32(smc);

    int tid  = threadIdx.x;
    int lane = tid & 31, wid = tid >> 5;
    int x0 = blockIdx.x * 128;
    int b  = blockIdx.y;

    const __half* A = g_a + (size_t)b * NN * NN;

    int warp_m = (wid & 1) * 64;
    int warp_n = (wid >> 1) * 64;

    int lc  = tid & 3,  lr  = tid >> 2;
    int lcb = tid & 31, lkr = tid >> 5;

    int rowA  = warp_m + (lane & 15);
    int achnk = lane >> 4;
    int kB    = (lane & 7) + 8 * ((lane >> 3) & 1);
    int noffB = (warp_n + ((lane >> 4) & 1) * 8) * 2;

    float d[4][8][4] = {};

    #pragma unroll
    for (int pst = 0; pst < NSTAGE - 1; pst++) {
        agg_load_stage(sbase + pst * STAGE_BYTES, pst * 32, x0, A, lc, lr, lcb, lkr);
        CP_COMMIT();
    }

    const int NT = NN / 32;   // 96
    for (int it = 0; it < NT; it++) {
        CP_WAIT(NSTAGE - 2);
        __syncthreads();

        int pf = it + NSTAGE - 1;
        if (pf < NT)
            agg_load_stage(sbase + (pf % NSTAGE) * STAGE_BYTES, pf * 32, x0, A, lc, lr, lcb, lkr);
        CP_COMMIT();

        uint32_t st = sbase + (it % NSTAGE) * STAGE_BYTES;

        #pragma unroll
        for (int s = 0; s < 2; s++) {
            uint32_t ah[4][4];
            #pragma unroll
            for (int mi = 0; mi < 4; mi++) {
                uint32_t aaddr = st + (rowA + mi * 16) * 80 + (s * 2 + achnk) * 16;
                LDSM_X4(ah[mi][0], ah[mi][1], ah[mi][2], ah[mi][3], aaddr);
            }
            #pragma unroll
            for (int j = 0; j < 4; j++) {
                uint32_t bh[4];
                uint32_t baddr = st + ST_B_OFF + (s * 16 + kB) * 528 + noffB + j * 32;
                LDSM_X4_T(bh[0], bh[1], bh[2], bh[3], baddr);
                #pragma unroll
                for (int mi = 0; mi < 4; mi++)
                    #pragma unroll
                    for (int nn = 0; nn < 2; nn++) {
                        int j8 = j * 2 + nn, br = nn * 2;
                        MMA_F16(d[mi][j8], ah[mi], bh[br], bh[br + 1]);
                    }
            }
        }
    }

    #pragma unroll
    for (int mi = 0; mi < 4; mi++) {
        int row0 = x0 + warp_m + mi * 16 + (lane >> 2);
        float invd0 = 1.0f / fmaxf(g_denom[b * NN + row0],     1e-12f);
        float invd1 = 1.0f / fmaxf(g_denom[b * NN + row0 + 8], 1e-12f);
        #pragma unroll
        for (int j8 = 0; j8 < 8; j8++) {
            int col = b * 256 + warp_n + j8 * 8 + 2 * (lane & 3);
            __half2 v0, v1;
            v0.x = __float2half(d[mi][j8][0] * invd0);
            v0.y = __float2half(d[mi][j8][1] * invd0);
            v1.x = __float2half(d[mi][j8][2] * invd1);
            v1.y = __float2half(d[mi][j8][3] * invd1);
            *(__half2*)&g_atth[(size_t)row0 * BH + col]       = v0;
            *(__half2*)&g_atth[(size_t)(row0 + 8) * BH + col] = v1;
        }
    }
}

// ---------------- fc_v via fp16 mma + elu + residual (+ kl store) -------------
#define FC_A_BYTES 5120
#define FC_B_BYTES 16896
#define FC_B_OFF   FC_A_BYTES
#define FC_STAGE (FC_A_BYTES + FC_B_BYTES)
#define FC_SMEM  (NSTAGE * FC_STAGE)

__device__ __forceinline__ void fc_load_stage(uint32_t st, int kk, int x0,
                                              int lc, int lr, int lcb, int lkr)
{
    cp16(st + lr * 80 + lc * 16, g_atth + (size_t)(x0 + lr) * BH + kk + lc * 8);
    #pragma unroll
    for (int p = 0; p < 4; p++) {
        int kr = lkr + p * 8;
        cp16(st + FC_B_OFF + kr * 528 + lcb * 16, g_wvh + (size_t)(kk + kr) * H + lcb * 8);
    }
}

__global__ void __launch_bounds__(256, 1) k_fc_mma(const float* __restrict__ bv,
                                                   const float* __restrict__ h0,
                                                   float* __restrict__ out,
                                                   int out_size)
{
    extern __shared__ char smc[];
    uint32_t sbase = smem_u32(smc);

    int tid  = threadIdx.x;
    int lane = tid & 31, wid = tid >> 5;
    int x0 = blockIdx.x * 64;

    // KL scalar (g_kl final since k_scores_mma; ordered by k_agg_mma between)
    if (blockIdx.x == 0 && tid == 0 && out_size > NN * H)
        out[out_size - 1] = (float)(g_kl / (double)((size_t)NN * NN));

    int warp_m = (wid & 1) * 32;
    int warp_n = (wid >> 1) * 64;

    int lc  = tid & 3,  lr  = tid >> 2;
    int lcb = tid & 31, lkr = tid >> 5;

    int rowA  = warp_m + (lane & 15);
    int achnk = lane >> 4;
    int kB    = (lane & 7) + 8 * ((lane >> 3) & 1);
    int noffB = (warp_n + ((lane >> 4) & 1) * 8) * 2;

    float d[2][8][4] = {};

    #pragma unroll
    for (int pst = 0; pst < NSTAGE - 1; pst++) {
        fc_load_stage(sbase + pst * FC_STAGE, pst * 32, x0, lc, lr, lcb, lkr);
        CP_COMMIT();
    }

    const int NT = BH / 32;   // 32
    for (int it = 0; it < NT; it++) {
        CP_WAIT(NSTAGE - 2);
        __syncthreads();

        int pf = it + NSTAGE - 1;
        if (pf < NT)
            fc_load_stage(sbase + (pf % NSTAGE) * FC_STAGE, pf * 32, x0, lc, lr, lcb, lkr);
        CP_COMMIT();

        uint32_t st = sbase + (it % NSTAGE) * FC_STAGE;

        #pragma unroll
        for (int s = 0; s < 2; s++) {
            uint32_t ah[2][4];
            #pragma unroll
            for (int mi = 0; mi < 2; mi++) {
                uint32_t aaddr = st + (rowA + mi * 16) * 80 + (s * 2 + achnk) * 16;
                LDSM_X4(ah[mi][0], ah[mi][1], ah[mi][2], ah[mi][3], aaddr);
            }
            #pragma unroll
            for (int j = 0; j < 4; j++) {
                uint32_t bh[4];
                uint32_t baddr = st + FC_B_OFF + (s * 16 + kB) * 528 + noffB + j * 32;
                LDSM_X4_T(bh[0], bh[1], bh[2], bh[3], baddr);
                #pragma unroll
                for (int mi = 0; mi < 2; mi++)
                    #pragma unroll
                    for (int nn = 0; nn < 2; nn++) {
                        int j8 = j * 2 + nn, br = nn * 2;
                        MMA_F16(d[mi][j8], ah[mi], bh[br], bh[br + 1]);
                    }
            }
        }
    }

    #pragma unroll
    for (int mi = 0; mi < 2; mi++) {
        int row0 = x0 + warp_m + mi * 16 + (lane >> 2);
        #pragma unroll
        for (int j8 = 0; j8 < 8; j8++) {
            int col = warp_n + j8 * 8 + 2 * (lane & 3);
            float bv0 = bv[col], bv1 = bv[col + 1];
            #pragma unroll
            for (int hf = 0; hf < 2; hf++) {
                int row = row0 + hf * 8;
                float r0 = d[mi][j8][hf * 2]     + bv0;
                float r1 = d[mi][j8][hf * 2 + 1] + bv1;
                r0 = (r0 > 0.f) ? r0 : expm1f(r0);
                r1 = (r1 > 0.f) ? r1 : expm1f(r1);
                float2 v;
                v.x = r0 + h0[(size_t)row * H + col];
                v.y = r1 + h0[(size_t)row * H + col + 1];
                *(float2*)&out[(size_t)row * H + col] = v;
            }
        }
    }
}

// ---------------- launch -----------------------------------------------------
extern "C" void kernel_launch(void* const* d_in, const int* in_sizes, int n_in,
                              void* d_out, int out_size)
{
    const float* h     = (const float*)d_in[0];
    const float* gamma = (const float*)d_in[1];
    const float* beta  = (const float*)d_in[2];
    const float* Wk    = (const float*)d_in[3];
    const float* bk    = (const float*)d_in[4];
    const float* Wm    = (const float*)d_in[5];
    const float* bm    = (const float*)d_in[6];
    const float* Wl    = (const float*)d_in[7];
    const float* bl    = (const float*)d_in[8];
    const float* Wv    = (const float*)d_in[9];
    const float* bv    = (const float*)d_in[10];
    const float* diff  = (const float*)d_in[11];
    const float* eps   = (const float*)d_in[12];
    float* out = (float*)d_out;

    cudaFuncSetAttribute(k_proj_mma,   cudaFuncAttributeMaxDynamicSharedMemorySize, PJ_SMEM);
    cudaFuncSetAttribute(k_scores_mma, cudaFuncAttributeMaxDynamicSharedMemorySize, SC_SMEM);
    cudaFuncSetAttribute(k_agg_mma,    cudaFuncAttributeMaxDynamicSharedMemorySize, AGG_SMEM);
    cudaFuncSetAttribute(k_fc_mma,     cudaFuncAttributeMaxDynamicSharedMemorySize, FC_SMEM);

    k_wh<<<(3 * H * H + BH * H) / 256, 256>>>(Wk, Wm, Wl, Wv);
    k_ln<<<NN, 256>>>(h, gamma, beta);
    k_proj_mma<<<dim3(48, 3), 256, PJ_SMEM>>>(bk, bm, bl);
    k_scores_mma<<<dim3(NB, 48, 48), 256, SC_SMEM>>>(diff, eps);
    k_agg_mma<<<dim3(24, NB), 256, AGG_SMEM>>>();
    k_fc_mma<<<48, 256, FC_SMEM>>>(bv, h, out, out_size);
}

// round 11
// speedup vs baseline: 2.7983x; 1.0303x over previous
#include <cuda_runtime.h>
#include <cuda_fp16.h>
#include <math.h>
#include <stdint.h>

#define NN    3072
#define H     256
#define NB    4
#define HD    64
#define BH    1024   /* NB*H */

// ---------------- scratch (device globals) ----------------------------------
__device__ float   g_hn[NN * H];                       // 3 MB
__device__ __half  g_kh [NB * NN * HD];
__device__ __half  g_mub[NB * NN * HD];
__device__ __half  g_lsb[NB * NN * HD];
__device__ __half  g_a  [(size_t)NB * NN * NN];        // 75.5 MB
__device__ __half  g_hnh[(size_t)NN * H];              // 1.5 MB
__device__ __half  g_atth[(size_t)NN * BH];            // 6.3 MB
__device__ __half  g_wh[3 * H * H];                    // Wk,Wm,Wl fp16
__device__ __half  g_wvh[BH * H];                      // 0.5 MB
__device__ float   g_denom[NB * NN];
__device__ double  g_kl;

// ---------------- PTX helpers ------------------------------------------------
__device__ __forceinline__ uint32_t smem_u32(const void* p) {
    uint32_t a;
    asm("{ .reg .u64 t; cvta.to.shared.u64 t, %1; cvt.u32.u64 %0, t; }"
        : "=r"(a) : "l"(p));
    return a;
}
__device__ __forceinline__ void cp16(uint32_t s, const void* g) {
    asm volatile("cp.async.cg.shared.global [%0], [%1], 16;" :: "r"(s), "l"(g));
}
#define CP_COMMIT() asm volatile("cp.async.commit_group;" ::: "memory")
#define CP_WAIT(n)  asm volatile("cp.async.wait_group %0;" :: "n"(n) : "memory")

#define LDSM_X4(r0, r1, r2, r3, addr) \
    asm volatile("ldmatrix.sync.aligned.m8n8.x4.shared.b16 {%0,%1,%2,%3}, [%4];" \
                 : "=r"(r0), "=r"(r1), "=r"(r2), "=r"(r3) : "r"(addr))

#define LDSM_X4_T(r0, r1, r2, r3, addr) \
    asm volatile("ldmatrix.sync.aligned.m8n8.x4.trans.shared.b16 {%0,%1,%2,%3}, [%4];" \
                 : "=r"(r0), "=r"(r1), "=r"(r2), "=r"(r3) : "r"(addr))

#define MMA_F16(d, a, b0, b1) \
    asm volatile("mma.sync.aligned.m16n8k16.row.col.f32.f16.f16.f32 " \
                 "{%0,%1,%2,%3}, {%4,%5,%6,%7}, {%8,%9}, {%0,%1,%2,%3};" \
                 : "+f"((d)[0]), "+f"((d)[1]), "+f"((d)[2]), "+f"((d)[3]) \
                 : "r"((a)[0]), "r"((a)[1]), "r"((a)[2]), "r"((a)[3]), \
                   "r"(b0), "r"(b1))

// ---------------- weights -> fp16 + init --------------------------------------
__global__ void k_wh(const float* __restrict__ Wk, const float* __restrict__ Wm,
                     const float* __restrict__ Wl, const float* __restrict__ Wv)
{
    int i = blockIdx.x * 256 + threadIdx.x;
    const int PW = 3 * H * H;   // 196608
    if (i < PW) {
        int mat = i / (H * H), off = i % (H * H);
        const float* W = (mat == 0) ? Wk : (mat == 1) ? Wm : Wl;
        g_wh[i] = __float2half(W[off]);
    } else {
        g_wvh[i - PW] = __float2half(Wv[i - PW]);
    }
    if (i < NB * NN) g_denom[i] = 0.0f;
    if (i == 0) g_kl = 0.0;
}

// ---------------- layernorm (+ fp16 copy of hn) -------------------------------
__global__ void k_ln(const float* __restrict__ h,
                     const float* __restrict__ gamma,
                     const float* __restrict__ beta) {
    int row = blockIdx.x;
    int tid = threadIdx.x;
    float v = h[row * H + tid];

    __shared__ float red[8];
    float s = v;
    #pragma unroll
    for (int o = 16; o; o >>= 1) s += __shfl_xor_sync(0xffffffffu, s, o);
    if ((tid & 31) == 0) red[tid >> 5] = s;
    __syncthreads();
    float mean = 0.f;
    #pragma unroll
    for (int i = 0; i < 8; i++) mean += red[i];
    mean *= (1.0f / H);

    float d = v - mean;
    float q = d * d;
    #pragma unroll
    for (int o = 16; o; o >>= 1) q += __shfl_xor_sync(0xffffffffu, q, o);
    __syncthreads();
    if ((tid & 31) == 0) red[tid >> 5] = q;
    __syncthreads();
    float var = 0.f;
    #pragma unroll
    for (int i = 0; i < 8; i++) var += red[i];
    var *= (1.0f / H);

    float hn = d * rsqrtf(var + 1e-5f) * gamma[tid] + beta[tid];
    g_hn[row * H + tid]  = hn;
    g_hnh[row * H + tid] = __float2half(hn);
}

// ---------------- projections via fp16 mma ------------------------------------
#define PJ_A_BYTES 5120
#define PJ_B_BYTES 16896
#define PJ_B_OFF   PJ_A_BYTES
#define PJ_STAGE (PJ_A_BYTES + PJ_B_BYTES)
#define NSTAGE   3
#define PJ_SMEM  (NSTAGE * PJ_STAGE)

__device__ __forceinline__ void pj_load_stage(uint32_t st, int kk, int x0,
                                              const __half* W,
                                              int lc, int lr, int lcb, int lkr)
{
    cp16(st + lr * 80 + lc * 16, g_hnh + (size_t)(x0 + lr) * H + kk + lc * 8);
    #pragma unroll
    for (int p = 0; p < 4; p++) {
        int kr = lkr + p * 8;
        cp16(st + PJ_B_OFF + kr * 528 + lcb * 16, W + (size_t)(kk + kr) * H + lcb * 8);
    }
}

__global__ void __launch_bounds__(256, 1) k_proj_mma(
    const float* __restrict__ bk, const float* __restrict__ bm,
    const float* __restrict__ bl)
{
    extern __shared__ char smc[];
    uint32_t sbase = smem_u32(smc);

    int tid  = threadIdx.x;
    int lane = tid & 31, wid = tid >> 5;
    int x0  = blockIdx.x * 64;
    int mat = blockIdx.y;

    const __half* W    = g_wh + (size_t)mat * H * H;
    const float*  bias = (mat == 0) ? bk : (mat == 1) ? bm : bl;
    __half* outp = (mat == 0) ? g_kh : (mat == 1) ? g_mub : g_lsb;
    float scl = (mat == 0) ? 0.125f : 1.0f;

    int warp_m = (wid & 1) * 32;
    int warp_n = (wid >> 1) * 64;

    int lc  = tid & 3,  lr  = tid >> 2;
    int lcb = tid & 31, lkr = tid >> 5;

    int rowA  = warp_m + (lane & 15);
    int achnk = lane >> 4;
    int kB    = (lane & 7) + 8 * ((lane >> 3) & 1);
    int noffB = (warp_n + ((lane >> 4) & 1) * 8) * 2;

    float d[2][8][4] = {};

    #pragma unroll
    for (int pst = 0; pst < NSTAGE - 1; pst++) {
        pj_load_stage(sbase + pst * PJ_STAGE, pst * 32, x0, W, lc, lr, lcb, lkr);
        CP_COMMIT();
    }

    const int NT = H / 32;   // 8
    for (int it = 0; it < NT; it++) {
        CP_WAIT(NSTAGE - 2);
        __syncthreads();

        int pf = it + NSTAGE - 1;
        if (pf < NT)
            pj_load_stage(sbase + (pf % NSTAGE) * PJ_STAGE, pf * 32, x0, W, lc, lr, lcb, lkr);
        CP_COMMIT();

        uint32_t st = sbase + (it % NSTAGE) * PJ_STAGE;

        #pragma unroll
        for (int s = 0; s < 2; s++) {
            uint32_t ah[2][4];
            #pragma unroll
            for (int mi = 0; mi < 2; mi++) {
                uint32_t aaddr = st + (rowA + mi * 16) * 80 + (s * 2 + achnk) * 16;
                LDSM_X4(ah[mi][0], ah[mi][1], ah[mi][2], ah[mi][3], aaddr);
            }
            #pragma unroll
            for (int j = 0; j < 4; j++) {
                uint32_t bh[4];
                uint32_t baddr = st + PJ_B_OFF + (s * 16 + kB) * 528 + noffB + j * 32;
                LDSM_X4_T(bh[0], bh[1], bh[2], bh[3], baddr);
                #pragma unroll
                for (int mi = 0; mi < 2; mi++)
                    #pragma unroll
                    for (int nn = 0; nn < 2; nn++) {
                        int j8 = j * 2 + nn, br = nn * 2;
                        MMA_F16(d[mi][j8], ah[mi], bh[br], bh[br + 1]);
                    }
            }
        }
    }

    #pragma unroll
    for (int mi = 0; mi < 2; mi++) {
        int row0 = x0 + warp_m + mi * 16 + (lane >> 2);
        #pragma unroll
        for (int j8 = 0; j8 < 8; j8++) {
            int col = warp_n + j8 * 8 + 2 * (lane & 3);
            float b0 = bias[col], b1 = bias[col + 1];
            int hb0 = col & 3,       dd0 = col >> 2;
            int hb1 = (col + 1) & 3, dd1 = (col + 1) >> 2;
            #pragma unroll
            for (int hf = 0; hf < 2; hf++) {
                int m = row0 + hf * 8;
                outp[((size_t)hb0 * NN + m) * HD + dd0] =
                    __float2half((d[mi][j8][hf * 2]     + b0) * scl);
                outp[((size_t)hb1 * NN + m) * HD + dd1] =
                    __float2half((d[mi][j8][hf * 2 + 1] + b1) * scl);
            }
        }
    }
}

// ---------------- scores v3: 4 heads per CTA, 64x64 tile, 512 thr -------------
// grid (48, 48). 16 warps: head = wid>>2, 2x2 warps of 32x32 per head.
// eps loaded as 16B (all 4 heads per (x,y)); diffusion loaded once per tile.
#define SC_ROW  144
#define SC_MAT  (64 * SC_ROW)        /* 9216 per matrix per head */
#define OFF_K   0
#define OFF_MU  (4 * SC_MAT)         /* 36864 */
#define OFF_LS  (8 * SC_MAT)         /* 73728 */
#define OFF_EPS (12 * SC_MAT)        /* 110592, 65536 bytes */
#define OFF_DIF (OFF_EPS + 65536)    /* 176128, 16384 bytes */
#define SC_SMEM (OFF_DIF + 16384)    /* 192512 */

__global__ void __launch_bounds__(512, 1) k_scores_mma(const float* __restrict__ diffusion,
                                                       const float* __restrict__ eps)
{
    extern __shared__ char smc[];
    uint32_t sb = smem_u32(smc);

    int x0 = blockIdx.x * 64;
    int y0 = blockIdx.y * 64;
    int tid = threadIdx.x, lane = tid & 31, wid = tid >> 5;
    int hd = wid >> 2;                       // head 0-3
    int warp_m = ((wid >> 1) & 1) * 32, warp_n = (wid & 1) * 32;

    // group A: K/MU/LS tiles, 4 heads each (12 matrices, 1 op/thread/matrix)
    {
        int lc = tid & 7, lr = tid >> 3;     // chunk 0-7, row 0-63
        uint32_t so = lr * SC_ROW + lc * 16;
        #pragma unroll
        for (int h = 0; h < 4; h++) {
            cp16(sb + OFF_K  + h * SC_MAT + so, g_kh  + ((size_t)h * NN + x0 + lr) * HD + lc * 8);
            cp16(sb + OFF_MU + h * SC_MAT + so, g_mub + ((size_t)h * NN + y0 + lr) * HD + lc * 8);
            cp16(sb + OFF_LS + h * SC_MAT + so, g_lsb + ((size_t)h * NN + y0 + lr) * HD + lc * 8);
        }
    }
    CP_COMMIT();

    // group B: eps 16B per (x,y) covering 4 heads; diffusion 16B
    {
        #pragma unroll
        for (int i = 0; i < 8; i++) {
            int idx = tid + i * 512;
            int xl = idx >> 6, yl = idx & 63;
            cp16(sb + OFF_EPS + idx * 16,
                 eps + ((size_t)(x0 + xl) * NN + y0 + yl) * NB);
        }
        #pragma unroll
        for (int i = 0; i < 2; i++) {
            int idx = tid + i * 512;
            int xl = idx >> 4, c = idx & 15;
            cp16(sb + OFF_DIF + xl * 256 + c * 16,
                 diffusion + (size_t)(x0 + xl) * NN + y0 + c * 4);
        }
    }
    CP_COMMIT();

    CP_WAIT(1);          // group A resident
    __syncthreads();

    float accm[2][4][4] = {}, accl[2][4][4] = {};
    int rA  = warp_m + (lane & 15);
    int cA8 = lane >> 4;
    int rB  = warp_n + (lane & 7) + 8 * ((lane >> 3) & 1);
    int cB8 = lane >> 4;

    uint32_t kbase  = sb + OFF_K  + hd * SC_MAT;
    uint32_t mubase = sb + OFF_MU + hd * SC_MAT;
    uint32_t lsbase = sb + OFF_LS + hd * SC_MAT;

    #pragma unroll
    for (int s = 0; s < 4; s++) {
        uint32_t kh[2][4];
        #pragma unroll
        for (int mi = 0; mi < 2; mi++) {
            uint32_t a = kbase + (rA + mi * 16) * SC_ROW + s * 32 + cA8 * 16;
            LDSM_X4(kh[mi][0], kh[mi][1], kh[mi][2], kh[mi][3], a);
        }
        uint32_t mh[2][4], lh[2][4];
        #pragma unroll
        for (int g = 0; g < 2; g++) {
            uint32_t ro = (rB + g * 16) * SC_ROW + s * 32 + cB8 * 16;
            LDSM_X4(mh[g][0], mh[g][1], mh[g][2], mh[g][3], mubase + ro);
            LDSM_X4(lh[g][0], lh[g][1], lh[g][2], lh[g][3], lsbase + ro);
        }
        #pragma unroll
        for (int mi = 0; mi < 2; mi++)
            #pragma unroll
            for (int g = 0; g < 2; g++)
                #pragma unroll
                for (int nn = 0; nn < 2; nn++) {
                    int n8 = g * 2 + nn;
                    MMA_F16(accm[mi][n8], kh[mi], mh[g][nn], mh[g][nn + 2]);
                    MMA_F16(accl[mi][n8], kh[mi], lh[g][nn], lh[g][nn + 2]);
                }
    }

    CP_WAIT(0);          // eps/diff resident
    __syncthreads();     // K tiles dead — reuse OFF_K area as a-staging per head

    const char*  eps_s = smc + OFF_EPS;
    const float* dif_s = (const float*)(smc + OFF_DIF);
    char* stg = smc + OFF_K + hd * SC_MAT;

    float klsum = 0.f;
    float rsum[2][2] = {{0.f, 0.f}, {0.f, 0.f}};

    #pragma unroll
    for (int mi = 0; mi < 2; mi++) {
        int xl0 = warp_m + mi * 16 + (lane >> 2);
        #pragma unroll
        for (int n8 = 0; n8 < 4; n8++) {
            int yl = warp_n + n8 * 8 + 2 * (lane & 3);
            #pragma unroll
            for (int hf = 0; hf < 2; hf++) {
                int xl = xl0 + hf * 8;
                float2 dif = *(const float2*)&dif_s[xl * 64 + yl];
                float e0 = *(const float*)(eps_s + ((xl * 64 + yl)     << 4) + hd * 4);
                float e1 = *(const float*)(eps_s + ((xl * 64 + yl + 1) << 4) + hd * 4);
                float smu0 = accm[mi][n8][hf * 2],     sls0 = accl[mi][n8][hf * 2];
                float smu1 = accm[mi][n8][hf * 2 + 1], sls1 = accl[mi][n8][hf * 2 + 1];
                float sig0 = fmaxf(sls0, 0.f) + __logf(1.f + __expf(-fabsf(sls0)));
                float sig1 = fmaxf(sls1, 0.f) + __logf(1.f + __expf(-fabsf(sls1)));
                float kle0 = 0.5f * (sig0 * sig0 + smu0 * smu0) - __logf(sig0) - 0.5f;
                float kle1 = 0.5f * (sig1 * sig1 + smu1 * smu1) - __logf(sig1) - 0.5f;
                float sg0 = (dif.x > 0.f) ? 1.f : ((dif.x < 0.f) ? -1.f : 0.f);
                float sg1 = (dif.y > 0.f) ? 1.f : ((dif.y < 0.f) ? -1.f : 0.f);
                klsum += kle0 * sg0 + kle1 * sg1;
                float a0 = __expf(smu0 + sig0 * e0) * dif.x;
                float a1 = __expf(smu1 + sig1 * e1) * dif.y;
                __half2 av;
                av.x = __float2half(a0);
                av.y = __float2half(a1);
                rsum[mi][hf] += fabsf(__half2float(av.x)) + fabsf(__half2float(av.y));
                *(__half2*)(stg + xl * SC_ROW + yl * 2) = av;
            }
        }
    }

    // per-row denominators (2 warps per (head,row))
    #pragma unroll
    for (int mi = 0; mi < 2; mi++)
        #pragma unroll
        for (int hf = 0; hf < 2; hf++) {
            float r = rsum[mi][hf];
            r += __shfl_xor_sync(0xffffffffu, r, 1);
            r += __shfl_xor_sync(0xffffffffu, r, 2);
            if ((lane & 3) == 0)
                atomicAdd(&g_denom[hd * NN + x0 + warp_m + mi * 16 + hf * 8 + (lane >> 2)], r);
        }

    // KL
    #pragma unroll
    for (int o = 16; o; o >>= 1) klsum += __shfl_xor_sync(0xffffffffu, klsum, o);
    __shared__ float kred[16];
    if (lane == 0) kred[wid] = klsum;
    __syncthreads();
    if (tid == 0) {
        float s = 0.f;
        #pragma unroll
        for (int i = 0; i < 16; i++) s += kred[i];
        atomicAdd(&g_kl, (double)s);
    }

    // coalesced copy-out: 4 heads x 512 float4 over 512 threads
    #pragma unroll
    for (int i = 0; i < 4; i++) {
        int t = tid + i * 512;
        int h = t >> 9, idx = t & 511;
        int r = idx >> 3, c = idx & 7;
        size_t go = (size_t)h * NN * NN + (size_t)(x0 + r) * NN + y0 + c * 8;
        *(float4*)&g_a[go] = *(float4*)(smc + OFF_K + h * SC_MAT + r * SC_ROW + c * 16);
    }
}

// ---------------- aggregation: a(fp16) x hn(fp16) mma, CTA 96x256 -------------
// grid (32, NB) = 128 CTAs ~ one full wave. 8 warps (2m x 4n), warp 48x64.
#define A_BYTES  7680                       /* 96*80 */
#define B_BYTES  16896                      /* 32*528 */
#define ST_B_OFF A_BYTES
#define STAGE_BYTES (A_BYTES + B_BYTES)     /* 24576 */
#define AGG_SMEM (NSTAGE * STAGE_BYTES)     /* 73728 */

__device__ __forceinline__ void agg_load_stage(
    uint32_t st, int kk, int x0, const __half* A,
    int tid, int lc, int lr, int lcb, int lkr)
{
    cp16(st + lr * 80 + lc * 16, A + (size_t)(x0 + lr) * NN + kk + lc * 8);
    if (tid < 128) {
        int r = lr + 64;
        cp16(st + r * 80 + lc * 16, A + (size_t)(x0 + r) * NN + kk + lc * 8);
    }
    #pragma unroll
    for (int p = 0; p < 4; p++) {
        int kr = lkr + p * 8;
        cp16(st + ST_B_OFF + kr * 528 + lcb * 16, g_hnh + (size_t)(kk + kr) * H + lcb * 8);
    }
}

__global__ void __launch_bounds__(256, 1) k_agg_mma()
{
    extern __shared__ char smc[];
    uint32_t sbase = smem_u32(smc);

    int tid  = threadIdx.x;
    int lane = tid & 31, wid = tid >> 5;
    int x0 = blockIdx.x * 96;
    int b  = blockIdx.y;

    const __half* A = g_a + (size_t)b * NN * NN;

    int warp_m = (wid & 1) * 48;
    int warp_n = (wid >> 1) * 64;

    int lc  = tid & 3,  lr  = tid >> 2;
    int lcb = tid & 31, lkr = tid >> 5;

    int rowA  = warp_m + (lane & 15);
    int achnk = lane >> 4;
    int kB    = (lane & 7) + 8 * ((lane >> 3) & 1);
    int noffB = (warp_n + ((lane >> 4) & 1) * 8) * 2;

    float d[3][8][4] = {};

    #pragma unroll
    for (int pst = 0; pst < NSTAGE - 1; pst++) {
        agg_load_stage(sbase + pst * STAGE_BYTES, pst * 32, x0, A, tid, lc, lr, lcb, lkr);
        CP_COMMIT();
    }

    const int NT = NN / 32;   // 96
    for (int it = 0; it < NT; it++) {
        CP_WAIT(NSTAGE - 2);
        __syncthreads();

        int pf = it + NSTAGE - 1;
        if (pf < NT)
            agg_load_stage(sbase + (pf % NSTAGE) * STAGE_BYTES, pf * 32, x0, A, tid, lc, lr, lcb, lkr);
        CP_COMMIT();

        uint32_t st = sbase + (it % NSTAGE) * STAGE_BYTES;

        #pragma unroll
        for (int s = 0; s < 2; s++) {
            uint32_t ah[3][4];
            #pragma unroll
            for (int mi = 0; mi < 3; mi++) {
                uint32_t aaddr = st + (rowA + mi * 16) * 80 + (s * 2 + achnk) * 16;
                LDSM_X4(ah[mi][0], ah[mi][1], ah[mi][2], ah[mi][3], aaddr);
            }
            #pragma unroll
            for (int j = 0; j < 4; j++) {
                uint32_t bh[4];
                uint32_t baddr = st + ST_B_OFF + (s * 16 + kB) * 528 + noffB + j * 32;
                LDSM_X4_T(bh[0], bh[1], bh[2], bh[3], baddr);
                #pragma unroll
                for (int mi = 0; mi < 3; mi++)
                    #pragma unroll
                    for (int nn = 0; nn < 2; nn++) {
                        int j8 = j * 2 + nn, br = nn * 2;
                        MMA_F16(d[mi][j8], ah[mi], bh[br], bh[br + 1]);
                    }
            }
        }
    }

    #pragma unroll
    for (int mi = 0; mi < 3; mi++) {
        int row0 = x0 + warp_m + mi * 16 + (lane >> 2);
        float invd0 = 1.0f / fmaxf(g_denom[b * NN + row0],     1e-12f);
        float invd1 = 1.0f / fmaxf(g_denom[b * NN + row0 + 8], 1e-12f);
        #pragma unroll
        for (int j8 = 0; j8 < 8; j8++) {
            int col = b * 256 + warp_n + j8 * 8 + 2 * (lane & 3);
            __half2 v0, v1;
            v0.x = __float2half(d[mi][j8][0] * invd0);
            v0.y = __float2half(d[mi][j8][1] * invd0);
            v1.x = __float2half(d[mi][j8][2] * invd1);
            v1.y = __float2half(d[mi][j8][3] * invd1);
            *(__half2*)&g_atth[(size_t)row0 * BH + col]       = v0;
            *(__half2*)&g_atth[(size_t)(row0 + 8) * BH + col] = v1;
        }
    }
}

// ---------------- fc_v via fp16 mma + elu + residual (+ kl store) -------------
#define FC_A_BYTES 5120
#define FC_B_BYTES 16896
#define FC_B_OFF   FC_A_BYTES
#define FC_STAGE (FC_A_BYTES + FC_B_BYTES)
#define FC_SMEM  (NSTAGE * FC_STAGE)

__device__ __forceinline__ void fc_load_stage(uint32_t st, int kk, int x0,
                                              int lc, int lr, int lcb, int lkr)
{
    cp16(st + lr * 80 + lc * 16, g_atth + (size_t)(x0 + lr) * BH + kk + lc * 8);
    #pragma unroll
    for (int p = 0; p < 4; p++) {
        int kr = lkr + p * 8;
        cp16(st + FC_B_OFF + kr * 528 + lcb * 16, g_wvh + (size_t)(kk + kr) * H + lcb * 8);
    }
}

__global__ void __launch_bounds__(256, 1) k_fc_mma(const float* __restrict__ bv,
                                                   const float* __restrict__ h0,
                                                   float* __restrict__ out,
                                                   int out_size)
{
    extern __shared__ char smc[];
    uint32_t sbase = smem_u32(smc);

    int tid  = threadIdx.x;
    int lane = tid & 31, wid = tid >> 5;
    int x0 = blockIdx.x * 64;

    if (blockIdx.x == 0 && tid == 0 && out_size > NN * H)
        out[out_size - 1] = (float)(g_kl / (double)((size_t)NN * NN));

    int warp_m = (wid & 1) * 32;
    int warp_n = (wid >> 1) * 64;

    int lc  = tid & 3,  lr  = tid >> 2;
    int lcb = tid & 31, lkr = tid >> 5;

    int rowA  = warp_m + (lane & 15);
    int achnk = lane >> 4;
    int kB    = (lane & 7) + 8 * ((lane >> 3) & 1);
    int noffB = (warp_n + ((lane >> 4) & 1) * 8) * 2;

    float d[2][8][4] = {};

    #pragma unroll
    for (int pst = 0; pst < NSTAGE - 1; pst++) {
        fc_load_stage(sbase + pst * FC_STAGE, pst * 32, x0, lc, lr, lcb, lkr);
        CP_COMMIT();
    }

    const int NT = BH / 32;   // 32
    for (int it = 0; it < NT; it++) {
        CP_WAIT(NSTAGE - 2);
        __syncthreads();

        int pf = it + NSTAGE - 1;
        if (pf < NT)
            fc_load_stage(sbase + (pf % NSTAGE) * FC_STAGE, pf * 32, x0, lc, lr, lcb, lkr);
        CP_COMMIT();

        uint32_t st = sbase + (it % NSTAGE) * FC_STAGE;

        #pragma unroll
        for (int s = 0; s < 2; s++) {
            uint32_t ah[2][4];
            #pragma unroll
            for (int mi = 0; mi < 2; mi++) {
                uint32_t aaddr = st + (rowA + mi * 16) * 80 + (s * 2 + achnk) * 16;
                LDSM_X4(ah[mi][0], ah[mi][1], ah[mi][2], ah[mi][3], aaddr);
            }
            #pragma unroll
            for (int j = 0; j < 4; j++) {
                uint32_t bh[4];
                uint32_t baddr = st + FC_B_OFF + (s * 16 + kB) * 528 + noffB + j * 32;
                LDSM_X4_T(bh[0], bh[1], bh[2], bh[3], baddr);
                #pragma unroll
                for (int mi = 0; mi < 2; mi++)
                    #pragma unroll
                    for (int nn = 0; nn < 2; nn++) {
                        int j8 = j * 2 + nn, br = nn * 2;
                        MMA_F16(d[mi][j8], ah[mi], bh[br], bh[br + 1]);
                    }
            }
        }
    }

    #pragma unroll
    for (int mi = 0; mi < 2; mi++) {
        int row0 = x0 + warp_m + mi * 16 + (lane >> 2);
        #pragma unroll
        for (int j8 = 0; j8 < 8; j8++) {
            int col = warp_n + j8 * 8 + 2 * (lane & 3);
            float bv0 = bv[col], bv1 = bv[col + 1];
            #pragma unroll
            for (int hf = 0; hf < 2; hf++) {
                int row = row0 + hf * 8;
                float r0 = d[mi][j8][hf * 2]     + bv0;
                float r1 = d[mi][j8][hf * 2 + 1] + bv1;
                r0 = (r0 > 0.f) ? r0 : expm1f(r0);
                r1 = (r1 > 0.f) ? r1 : expm1f(r1);
                float2 v;
                v.x = r0 + h0[(size_t)row * H + col];
                v.y = r1 + h0[(size_t)row * H + col + 1];
                *(float2*)&out[(size_t)row * H + col] = v;
            }
        }
    }
}

// ---------------- launch -----------------------------------------------------
extern "C" void kernel_launch(void* const* d_in, const int* in_sizes, int n_in,
                              void* d_out, int out_size)
{
    const float* h     = (const float*)d_in[0];
    const float* gamma = (const float*)d_in[1];
    const float* beta  = (const float*)d_in[2];
    const float* Wk    = (const float*)d_in[3];
    const float* bk    = (const float*)d_in[4];
    const float* Wm    = (const float*)d_in[5];
    const float* bm    = (const float*)d_in[6];
    const float* Wl    = (const float*)d_in[7];
    const float* bl    = (const float*)d_in[8];
    const float* Wv    = (const float*)d_in[9];
    const float* bv    = (const float*)d_in[10];
    const float* diff  = (const float*)d_in[11];
    const float* eps   = (const float*)d_in[12];
    float* out = (float*)d_out;

    cudaFuncSetAttribute(k_proj_mma,   cudaFuncAttributeMaxDynamicSharedMemorySize, PJ_SMEM);
    cudaFuncSetAttribute(k_scores_mma, cudaFuncAttributeMaxDynamicSharedMemorySize, SC_SMEM);
    cudaFuncSetAttribute(k_agg_mma,    cudaFuncAttributeMaxDynamicSharedMemorySize, AGG_SMEM);
    cudaFuncSetAttribute(k_fc_mma,     cudaFuncAttributeMaxDynamicSharedMemorySize, FC_SMEM);

    k_wh<<<(3 * H * H + BH * H) / 256, 256>>>(Wk, Wm, Wl, Wv);
    k_ln<<<NN, 256>>>(h, gamma, beta);
    k_proj_mma<<<dim3(48, 3), 256, PJ_SMEM>>>(bk, bm, bl);
    k_scores_mma<<<dim3(48, 48), 512, SC_SMEM>>>(diff, eps);
    k_agg_mma<<<dim3(32, NB), 256, AGG_SMEM>>>();
    k_fc_mma<<<48, 256, FC_SMEM>>>(bv, h, out, out_size);
}

// round 13
// speedup vs baseline: 2.9314x; 1.0476x over previous
#include <cuda_runtime.h>
#include <cuda_fp16.h>
#include <math.h>
#include <stdint.h>

#define NN    3072
#define H     256
#define NB    4
#define HD    64
#define BH    1024   /* NB*H */

// ---------------- scratch (device globals) ----------------------------------
__device__ float   g_hn[NN * H];                       // 3 MB
__device__ __half  g_kh [NB * NN * HD];
__device__ __half  g_mub[NB * NN * HD];
__device__ __half  g_lsb[NB * NN * HD];
__device__ __half  g_a  [(size_t)NB * NN * NN];        // 75.5 MB
__device__ __half  g_hnh[(size_t)NN * H];              // 1.5 MB
__device__ __half  g_atth[(size_t)NN * BH];            // 6.3 MB
__device__ __half  g_wh[3 * H * H];                    // Wk,Wm,Wl fp16
__device__ __half  g_wvh[BH * H];                      // 0.5 MB
__device__ float   g_denom[NB * NN];
__device__ double  g_kl;

// ---------------- PTX helpers ------------------------------------------------
__device__ __forceinline__ uint32_t smem_u32(const void* p) {
    uint32_t a;
    asm("{ .reg .u64 t; cvta.to.shared.u64 t, %1; cvt.u32.u64 %0, t; }"
        : "=r"(a) : "l"(p));
    return a;
}
__device__ __forceinline__ void cp16(uint32_t s, const void* g) {
    asm volatile("cp.async.cg.shared.global [%0], [%1], 16;" :: "r"(s), "l"(g));
}
__device__ __forceinline__ void cp4(uint32_t s, const void* g) {
    asm volatile("cp.async.ca.shared.global [%0], [%1], 4;" :: "r"(s), "l"(g));
}
#define CP_COMMIT() asm volatile("cp.async.commit_group;" ::: "memory")
#define CP_WAIT(n)  asm volatile("cp.async.wait_group %0;" :: "n"(n) : "memory")

#define LDSM_X4(r0, r1, r2, r3, addr) \
    asm volatile("ldmatrix.sync.aligned.m8n8.x4.shared.b16 {%0,%1,%2,%3}, [%4];" \
                 : "=r"(r0), "=r"(r1), "=r"(r2), "=r"(r3) : "r"(addr))

#define LDSM_X4_T(r0, r1, r2, r3, addr) \
    asm volatile("ldmatrix.sync.aligned.m8n8.x4.trans.shared.b16 {%0,%1,%2,%3}, [%4];" \
                 : "=r"(r0), "=r"(r1), "=r"(r2), "=r"(r3) : "r"(addr))

#define MMA_F16(d, a, b0, b1) \
    asm volatile("mma.sync.aligned.m16n8k16.row.col.f32.f16.f16.f32 " \
                 "{%0,%1,%2,%3}, {%4,%5,%6,%7}, {%8,%9}, {%0,%1,%2,%3};" \
                 : "+f"((d)[0]), "+f"((d)[1]), "+f"((d)[2]), "+f"((d)[3]) \
                 : "r"((a)[0]), "r"((a)[1]), "r"((a)[2]), "r"((a)[3]), \
                   "r"(b0), "r"(b1))

// ---------------- weights -> fp16 + init --------------------------------------
__global__ void k_wh(const float* __restrict__ Wk, const float* __restrict__ Wm,
                     const float* __restrict__ Wl, const float* __restrict__ Wv)
{
    int i = blockIdx.x * 256 + threadIdx.x;
    const int PW = 3 * H * H;   // 196608
    if (i < PW) {
        int mat = i / (H * H), off = i % (H * H);
        const float* W = (mat == 0) ? Wk : (mat == 1) ? Wm : Wl;
        g_wh[i] = __float2half(W[off]);
    } else {
        g_wvh[i - PW] = __float2half(Wv[i - PW]);
    }
    if (i < NB * NN) g_denom[i] = 0.0f;
    if (i == 0) g_kl = 0.0;
}

// ---------------- layernorm (+ fp16 copy of hn) -------------------------------
__global__ void k_ln(const float* __restrict__ h,
                     const float* __restrict__ gamma,
                     const float* __restrict__ beta) {
    int row = blockIdx.x;
    int tid = threadIdx.x;
    float v = h[row * H + tid];

    __shared__ float red[8];
    float s = v;
    #pragma unroll
    for (int o = 16; o; o >>= 1) s += __shfl_xor_sync(0xffffffffu, s, o);
    if ((tid & 31) == 0) red[tid >> 5] = s;
    __syncthreads();
    float mean = 0.f;
    #pragma unroll
    for (int i = 0; i < 8; i++) mean += red[i];
    mean *= (1.0f / H);

    float d = v - mean;
    float q = d * d;
    #pragma unroll
    for (int o = 16; o; o >>= 1) q += __shfl_xor_sync(0xffffffffu, q, o);
    __syncthreads();
    if ((tid & 31) == 0) red[tid >> 5] = q;
    __syncthreads();
    float var = 0.f;
    #pragma unroll
    for (int i = 0; i < 8; i++) var += red[i];
    var *= (1.0f / H);

    float hn = d * rsqrtf(var + 1e-5f) * gamma[tid] + beta[tid];
    g_hn[row * H + tid]  = hn;
    g_hnh[row * H + tid] = __float2half(hn);
}

// ---------------- projections via fp16 mma ------------------------------------
#define PJ_A_BYTES 5120
#define PJ_B_BYTES 16896
#define PJ_B_OFF   PJ_A_BYTES
#define PJ_STAGE (PJ_A_BYTES + PJ_B_BYTES)
#define NSTAGE   3
#define PJ_SMEM  (NSTAGE * PJ_STAGE)

__device__ __forceinline__ void pj_load_stage(uint32_t st, int kk, int x0,
                                              const __half* W,
                                              int lc, int lr, int lcb, int lkr)
{
    cp16(st + lr * 80 + lc * 16, g_hnh + (size_t)(x0 + lr) * H + kk + lc * 8);
    #pragma unroll
    for (int p = 0; p < 4; p++) {
        int kr = lkr + p * 8;
        cp16(st + PJ_B_OFF + kr * 528 + lcb * 16, W + (size_t)(kk + kr) * H + lcb * 8);
    }
}

__global__ void __launch_bounds__(256, 1) k_proj_mma(
    const float* __restrict__ bk, const float* __restrict__ bm,
    const float* __restrict__ bl)
{
    extern __shared__ char smc[];
    uint32_t sbase = smem_u32(smc);

    int tid  = threadIdx.x;
    int lane = tid & 31, wid = tid >> 5;
    int x0  = blockIdx.x * 64;
    int mat = blockIdx.y;

    const __half* W    = g_wh + (size_t)mat * H * H;
    const float*  bias = (mat == 0) ? bk : (mat == 1) ? bm : bl;
    __half* outp = (mat == 0) ? g_kh : (mat == 1) ? g_mub : g_lsb;
    float scl = (mat == 0) ? 0.125f : 1.0f;

    int warp_m = (wid & 1) * 32;
    int warp_n = (wid >> 1) * 64;

    int lc  = tid & 3,  lr  = tid >> 2;
    int lcb = tid & 31, lkr = tid >> 5;

    int rowA  = warp_m + (lane & 15);
    int achnk = lane >> 4;
    int kB    = (lane & 7) + 8 * ((lane >> 3) & 1);
    int noffB = (warp_n + ((lane >> 4) & 1) * 8) * 2;

    float d[2][8][4] = {};

    #pragma unroll
    for (int pst = 0; pst < NSTAGE - 1; pst++) {
        pj_load_stage(sbase + pst * PJ_STAGE, pst * 32, x0, W, lc, lr, lcb, lkr);
        CP_COMMIT();
    }

    const int NT = H / 32;   // 8
    for (int it = 0; it < NT; it++) {
        CP_WAIT(NSTAGE - 2);
        __syncthreads();

        int pf = it + NSTAGE - 1;
        if (pf < NT)
            pj_load_stage(sbase + (pf % NSTAGE) * PJ_STAGE, pf * 32, x0, W, lc, lr, lcb, lkr);
        CP_COMMIT();

        uint32_t st = sbase + (it % NSTAGE) * PJ_STAGE;

        #pragma unroll
        for (int s = 0; s < 2; s++) {
            uint32_t ah[2][4];
            #pragma unroll
            for (int mi = 0; mi < 2; mi++) {
                uint32_t aaddr = st + (rowA + mi * 16) * 80 + (s * 2 + achnk) * 16;
                LDSM_X4(ah[mi][0], ah[mi][1], ah[mi][2], ah[mi][3], aaddr);
            }
            #pragma unroll
            for (int j = 0; j < 4; j++) {
                uint32_t bh[4];
                uint32_t baddr = st + PJ_B_OFF + (s * 16 + kB) * 528 + noffB + j * 32;
                LDSM_X4_T(bh[0], bh[1], bh[2], bh[3], baddr);
                #pragma unroll
                for (int mi = 0; mi < 2; mi++)
                    #pragma unroll
                    for (int nn = 0; nn < 2; nn++) {
                        int j8 = j * 2 + nn, br = nn * 2;
                        MMA_F16(d[mi][j8], ah[mi], bh[br], bh[br + 1]);
                    }
            }
        }
    }

    #pragma unroll
    for (int mi = 0; mi < 2; mi++) {
        int row0 = x0 + warp_m + mi * 16 + (lane >> 2);
        #pragma unroll
        for (int j8 = 0; j8 < 8; j8++) {
            int col = warp_n + j8 * 8 + 2 * (lane & 3);
            float b0 = bias[col], b1 = bias[col + 1];
            int hb0 = col & 3,       dd0 = col >> 2;
            int hb1 = (col + 1) & 3, dd1 = (col + 1) >> 2;
            #pragma unroll
            for (int hf = 0; hf < 2; hf++) {
                int m = row0 + hf * 8;
                outp[((size_t)hb0 * NN + m) * HD + dd0] =
                    __float2half((d[mi][j8][hf * 2]     + b0) * scl);
                outp[((size_t)hb1 * NN + m) * HD + dd1] =
                    __float2half((d[mi][j8][hf * 2 + 1] + b1) * scl);
            }
        }
    }
}

// ---------------- scores: 256 thr, 64x64 tile, warp 32x16 (R10 proven) --------
// grid (NB, 48, 48). 8 warps = 2m x 4n. 3 CTAs/SM, 24 warps.
#define SC_ROW 144
#define SC_HALF (64 * SC_ROW)     /* 9216 */
#define OFF_EPS (3 * SC_HALF)     /* 27648, 16384 bytes */
#define OFF_DIF (OFF_EPS + 16384) /* 44032, 16384 bytes */
#define SC_SMEM (OFF_DIF + 16384) /* 60416 */

__global__ void __launch_bounds__(256) k_scores_mma(const float* __restrict__ diffusion,
                                                    const float* __restrict__ eps)
{
    extern __shared__ char smc[];
    uint32_t sb = smem_u32(smc);

    int b  = blockIdx.x;
    int x0 = blockIdx.y * 64;
    int y0 = blockIdx.z * 64;
    int tid = threadIdx.x, lane = tid & 31, wid = tid >> 5;
    int warp_m = (wid & 1) * 32, warp_n = (wid >> 1) * 16;

    const __half* K  = g_kh  + ((size_t)b * NN + x0) * HD;
    const __half* MU = g_mub + ((size_t)b * NN + y0) * HD;
    const __half* LS = g_lsb + ((size_t)b * NN + y0) * HD;

    // group A: K/MU/LS tiles
    {
        int lc = tid & 7, lr = tid >> 3;   // chunk 0-7, row 0-31
        #pragma unroll
        for (int p = 0; p < 2; p++) {
            int r = lr + p * 32;
            uint32_t so = r * SC_ROW + lc * 16;
            size_t  go = (size_t)r * HD + lc * 8;
            cp16(sb + 0 * SC_HALF + so, K  + go);
            cp16(sb + 1 * SC_HALF + so, MU + go);
            cp16(sb + 2 * SC_HALF + so, LS + go);
        }
    }
    CP_COMMIT();

    // group B: eps (4B strided) + diffusion (16B) — overlapped with MMAs
    {
        #pragma unroll
        for (int i = 0; i < 16; i++) {
            int idx = tid + i * 256;
            int xl = idx >> 6, yl = idx & 63;
            cp4(sb + OFF_EPS + idx * 4,
                eps + ((size_t)(x0 + xl) * NN + y0 + yl) * NB + b);
        }
        #pragma unroll
        for (int i = 0; i < 4; i++) {
            int idx = tid + i * 256;
            int xl = idx >> 4, c = idx & 15;
            cp16(sb + OFF_DIF + xl * 256 + c * 16,
                 diffusion + (size_t)(x0 + xl) * NN + y0 + c * 4);
        }
    }
    CP_COMMIT();

    CP_WAIT(1);          // group A resident
    __syncthreads();

    float accm[2][2][4] = {}, accl[2][2][4] = {};
    int rA  = warp_m + (lane & 15);
    int cA8 = lane >> 4;
    int rB  = warp_n + (lane & 7) + 8 * ((lane >> 3) & 1);
    int cB8 = lane >> 4;

    #pragma unroll
    for (int s = 0; s < 4; s++) {
        uint32_t kh[2][4];
        #pragma unroll
        for (int mi = 0; mi < 2; mi++) {
            uint32_t a = sb + (rA + mi * 16) * SC_ROW + s * 32 + cA8 * 16;
            LDSM_X4(kh[mi][0], kh[mi][1], kh[mi][2], kh[mi][3], a);
        }
        uint32_t mh[4], lh[4];
        {
            uint32_t bm = sb + SC_HALF + rB * SC_ROW + s * 32 + cB8 * 16;
            LDSM_X4(mh[0], mh[1], mh[2], mh[3], bm);
            LDSM_X4(lh[0], lh[1], lh[2], lh[3], bm + SC_HALF);
        }
        #pragma unroll
        for (int mi = 0; mi < 2; mi++)
            #pragma unroll
            for (int nn = 0; nn < 2; nn++) {
                MMA_F16(accm[mi][nn], kh[mi], mh[nn], mh[nn + 2]);
                MMA_F16(accl[mi][nn], kh[mi], lh[nn], lh[nn + 2]);
            }
    }

    CP_WAIT(0);          // eps/diff resident
    __syncthreads();     // tiles dead — reuse [0, SC_HALF) as fp16 staging

    const float* eps_s = (const float*)(smc + OFF_EPS);
    const float* dif_s = (const float*)(smc + OFF_DIF);

    float klsum = 0.f;
    float rsum[2][2] = {{0.f, 0.f}, {0.f, 0.f}};

    #pragma unroll
    for (int mi = 0; mi < 2; mi++) {
        int xl0 = warp_m + mi * 16 + (lane >> 2);
        #pragma unroll
        for (int nn = 0; nn < 2; nn++) {
            int yl = warp_n + nn * 8 + 2 * (lane & 3);
            #pragma unroll
            for (int hf = 0; hf < 2; hf++) {
                int xl = xl0 + hf * 8;
                float2 dif = *(const float2*)&dif_s[xl * 64 + yl];
                float e0 = eps_s[xl * 64 + yl];
                float e1 = eps_s[xl * 64 + yl + 1];
                float smu0 = accm[mi][nn][hf * 2],     sls0 = accl[mi][nn][hf * 2];
                float smu1 = accm[mi][nn][hf * 2 + 1], sls1 = accl[mi][nn][hf * 2 + 1];
                float sig0 = fmaxf(sls0, 0.f) + __logf(1.f + __expf(-fabsf(sls0)));
                float sig1 = fmaxf(sls1, 0.f) + __logf(1.f + __expf(-fabsf(sls1)));
                float kle0 = 0.5f * (sig0 * sig0 + smu0 * smu0) - __logf(sig0) - 0.5f;
                float kle1 = 0.5f * (sig1 * sig1 + smu1 * smu1) - __logf(sig1) - 0.5f;
                float sg0 = (dif.x > 0.f) ? 1.f : ((dif.x < 0.f) ? -1.f : 0.f);
                float sg1 = (dif.y > 0.f) ? 1.f : ((dif.y < 0.f) ? -1.f : 0.f);
                klsum += kle0 * sg0 + kle1 * sg1;
                float a0 = __expf(smu0 + sig0 * e0) * dif.x;
                float a1 = __expf(smu1 + sig1 * e1) * dif.y;
                __half2 av;
                av.x = __float2half(a0);
                av.y = __float2half(a1);
                rsum[mi][hf] += fabsf(__half2float(av.x)) + fabsf(__half2float(av.y));
                *(__half2*)(smc + xl * SC_ROW + yl * 2) = av;
            }
        }
    }

    // per-row denominators
    #pragma unroll
    for (int mi = 0; mi < 2; mi++)
        #pragma unroll
        for (int hf = 0; hf < 2; hf++) {
            float r = rsum[mi][hf];
            r += __shfl_xor_sync(0xffffffffu, r, 1);
            r += __shfl_xor_sync(0xffffffffu, r, 2);
            if ((lane & 3) == 0)
                atomicAdd(&g_denom[b * NN + x0 + warp_m + mi * 16 + hf * 8 + (lane >> 2)], r);
        }

    // KL
    #pragma unroll
    for (int o = 16; o; o >>= 1) klsum += __shfl_xor_sync(0xffffffffu, klsum, o);
    __shared__ float kred[8];
    if (lane == 0) kred[wid] = klsum;
    __syncthreads();
    if (tid == 0) {
        float s = 0.f;
        #pragma unroll
        for (int i = 0; i < 8; i++) s += kred[i];
        atomicAdd(&g_kl, (double)s);
    }

    // coalesced copy-out (512 float4 over 256 threads)
    __half* dst = g_a + (size_t)b * NN * NN;
    #pragma unroll
    for (int i = 0; i < 2; i++) {
        int t = tid + i * 256;
        int r = t >> 3, c = t & 7;
        size_t go = (size_t)(x0 + r) * NN + y0 + c * 8;
        *(float4*)&dst[go] = *(float4*)(smc + r * SC_ROW + c * 16);
    }
}

// ---------------- aggregation: a(fp16) x hn(fp16) mma, CTA 96x256 -------------
// grid (32, NB) = 128 CTAs ~ one full wave. 8 warps (2m x 4n), warp 48x64.
#define A_BYTES  7680                       /* 96*80 */
#define B_BYTES  16896                      /* 32*528 */
#define ST_B_OFF A_BYTES
#define STAGE_BYTES (A_BYTES + B_BYTES)     /* 24576 */
#define AGG_SMEM (NSTAGE * STAGE_BYTES)     /* 73728 */

__device__ __forceinline__ void agg_load_stage(
    uint32_t st, int kk, int x0, const __half* A,
    int tid, int lc, int lr, int lcb, int lkr)
{
    cp16(st + lr * 80 + lc * 16, A + (size_t)(x0 + lr) * NN + kk + lc * 8);
    if (tid < 128) {
        int r = lr + 64;
        cp16(st + r * 80 + lc * 16, A + (size_t)(x0 + r) * NN + kk + lc * 8);
    }
    #pragma unroll
    for (int p = 0; p < 4; p++) {
        int kr = lkr + p * 8;
        cp16(st + ST_B_OFF + kr * 528 + lcb * 16, g_hnh + (size_t)(kk + kr) * H + lcb * 8);
    }
}

__global__ void __launch_bounds__(256, 1) k_agg_mma()
{
    extern __shared__ char smc[];
    uint32_t sbase = smem_u32(smc);

    int tid  = threadIdx.x;
    int lane = tid & 31, wid = tid >> 5;
    int x0 = blockIdx.x * 96;
    int b  = blockIdx.y;

    const __half* A = g_a + (size_t)b * NN * NN;

    int warp_m = (wid & 1) * 48;
    int warp_n = (wid >> 1) * 64;

    int lc  = tid & 3,  lr  = tid >> 2;
    int lcb = tid & 31, lkr = tid >> 5;

    int rowA  = warp_m + (lane & 15);
    int achnk = lane >> 4;
    int kB    = (lane & 7) + 8 * ((lane >> 3) & 1);
    int noffB = (warp_n + ((lane >> 4) & 1) * 8) * 2;

    float d[3][8][4] = {};

    #pragma unroll
    for (int pst = 0; pst < NSTAGE - 1; pst++) {
        agg_load_stage(sbase + pst * STAGE_BYTES, pst * 32, x0, A, tid, lc, lr, lcb, lkr);
        CP_COMMIT();
    }

    const int NT = NN / 32;   // 96
    for (int it = 0; it < NT; it++) {
        CP_WAIT(NSTAGE - 2);
        __syncthreads();

        int pf = it + NSTAGE - 1;
        if (pf < NT)
            agg_load_stage(sbase + (pf % NSTAGE) * STAGE_BYTES, pf * 32, x0, A, tid, lc, lr, lcb, lkr);
        CP_COMMIT();

        uint32_t st = sbase + (it % NSTAGE) * STAGE_BYTES;

        #pragma unroll
        for (int s = 0; s < 2; s++) {
            uint32_t ah[3][4];
            #pragma unroll
            for (int mi = 0; mi < 3; mi++) {
                uint32_t aaddr = st + (rowA + mi * 16) * 80 + (s * 2 + achnk) * 16;
                LDSM_X4(ah[mi][0], ah[mi][1], ah[mi][2], ah[mi][3], aaddr);
            }
            #pragma unroll
            for (int j = 0; j < 4; j++) {
                uint32_t bh[4];
                uint32_t baddr = st + ST_B_OFF + (s * 16 + kB) * 528 + noffB + j * 32;
                LDSM_X4_T(bh[0], bh[1], bh[2], bh[3], baddr);
                #pragma unroll
                for (int mi = 0; mi < 3; mi++)
                    #pragma unroll
                    for (int nn = 0; nn < 2; nn++) {
                        int j8 = j * 2 + nn, br = nn * 2;
                        MMA_F16(d[mi][j8], ah[mi], bh[br], bh[br + 1]);
                    }
            }
        }
    }

    #pragma unroll
    for (int mi = 0; mi < 3; mi++) {
        int row0 = x0 + warp_m + mi * 16 + (lane >> 2);
        float invd0 = 1.0f / fmaxf(g_denom[b * NN + row0],     1e-12f);
        float invd1 = 1.0f / fmaxf(g_denom[b * NN + row0 + 8], 1e-12f);
        #pragma unroll
        for (int j8 = 0; j8 < 8; j8++) {
            int col = b * 256 + warp_n + j8 * 8 + 2 * (lane & 3);
            __half2 v0, v1;
            v0.x = __float2half(d[mi][j8][0] * invd0);
            v0.y = __float2half(d[mi][j8][1] * invd0);
            v1.x = __float2half(d[mi][j8][2] * invd1);
            v1.y = __float2half(d[mi][j8][3] * invd1);
            *(__half2*)&g_atth[(size_t)row0 * BH + col]       = v0;
            *(__half2*)&g_atth[(size_t)(row0 + 8) * BH + col] = v1;
        }
    }
}

// ---------------- fc_v via fp16 mma + elu + residual (+ kl store) -------------
#define FC_A_BYTES 5120
#define FC_B_BYTES 16896
#define FC_B_OFF   FC_A_BYTES
#define FC_STAGE (FC_A_BYTES + FC_B_BYTES)
#define FC_SMEM  (NSTAGE * FC_STAGE)

__device__ __forceinline__ void fc_load_stage(uint32_t st, int kk, int x0,
                                              int lc, int lr, int lcb, int lkr)
{
    cp16(st + lr * 80 + lc * 16, g_atth + (size_t)(x0 + lr) * BH + kk + lc * 8);
    #pragma unroll
    for (int p = 0; p < 4; p++) {
        int kr = lkr + p * 8;
        cp16(st + FC_B_OFF + kr * 528 + lcb * 16, g_wvh + (size_t)(kk + kr) * H + lcb * 8);
    }
}

__global__ void __launch_bounds__(256, 1) k_fc_mma(const float* __restrict__ bv,
                                                   const float* __restrict__ h0,
                                                   float* __restrict__ out,
                                                   int out_size)
{
    extern __shared__ char smc[];
    uint32_t sbase = smem_u32(smc);

    int tid  = threadIdx.x;
    int lane = tid & 31, wid = tid >> 5;
    int x0 = blockIdx.x * 64;

    if (blockIdx.x == 0 && tid == 0 && out_size > NN * H)
        out[out_size - 1] = (float)(g_kl / (double)((size_t)NN * NN));

    int warp_m = (wid & 1) * 32;
    int warp_n = (wid >> 1) * 64;

    int lc  = tid & 3,  lr  = tid >> 2;
    int lcb = tid & 31, lkr = tid >> 5;

    int rowA  = warp_m + (lane & 15);
    int achnk = lane >> 4;
    int kB    = (lane & 7) + 8 * ((lane >> 3) & 1);
    int noffB = (warp_n + ((lane >> 4) & 1) * 8) * 2;

    float d[2][8][4] = {};

    #pragma unroll
    for (int pst = 0; pst < NSTAGE - 1; pst++) {
        fc_load_stage(sbase + pst * FC_STAGE, pst * 32, x0, lc, lr, lcb, lkr);
        CP_COMMIT();
    }

    const int NT = BH / 32;   // 32
    for (int it = 0; it < NT; it++) {
        CP_WAIT(NSTAGE - 2);
        __syncthreads();

        int pf = it + NSTAGE - 1;
        if (pf < NT)
            fc_load_stage(sbase + (pf % NSTAGE) * FC_STAGE, pf * 32, x0, lc, lr, lcb, lkr);
        CP_COMMIT();

        uint32_t st = sbase + (it % NSTAGE) * FC_STAGE;

        #pragma unroll
        for (int s = 0; s < 2; s++) {
            uint32_t ah[2][4];
            #pragma unroll
            for (int mi = 0; mi < 2; mi++) {
                uint32_t aaddr = st + (rowA + mi * 16) * 80 + (s * 2 + achnk) * 16;
                LDSM_X4(ah[mi][0], ah[mi][1], ah[mi][2], ah[mi][3], aaddr);
            }
            #pragma unroll
            for (int j = 0; j < 4; j++) {
                uint32_t bh[4];
                uint32_t baddr = st + FC_B_OFF + (s * 16 + kB) * 528 + noffB + j * 32;
                LDSM_X4_T(bh[0], bh[1], bh[2], bh[3], baddr);
                #pragma unroll
                for (int mi = 0; mi < 2; mi++)
                    #pragma unroll
                    for (int nn = 0; nn < 2; nn++) {
                        int j8 = j * 2 + nn, br = nn * 2;
                        MMA_F16(d[mi][j8], ah[mi], bh[br], bh[br + 1]);
                    }
            }
        }
    }

    #pragma unroll
    for (int mi = 0; mi < 2; mi++) {
        int row0 = x0 + warp_m + mi * 16 + (lane >> 2);
        #pragma unroll
        for (int j8 = 0; j8 < 8; j8++) {
            int col = warp_n + j8 * 8 + 2 * (lane & 3);
            float bv0 = bv[col], bv1 = bv[col + 1];
            #pragma unroll
            for (int hf = 0; hf < 2; hf++) {
                int row = row0 + hf * 8;
                float r0 = d[mi][j8][hf * 2]     + bv0;
                float r1 = d[mi][j8][hf * 2 + 1] + bv1;
                r0 = (r0 > 0.f) ? r0 : expm1f(r0);
                r1 = (r1 > 0.f) ? r1 : expm1f(r1);
                float2 v;
                v.x = r0 + h0[(size_t)row * H + col];
                v.y = r1 + h0[(size_t)row * H + col + 1];
                *(float2*)&out[(size_t)row * H + col] = v;
            }
        }
    }
}

// ---------------- launch -----------------------------------------------------
extern "C" void kernel_launch(void* const* d_in, const int* in_sizes, int n_in,
                              void* d_out, int out_size)
{
    const float* h     = (const float*)d_in[0];
    const float* gamma = (const float*)d_in[1];
    const float* beta  = (const float*)d_in[2];
    const float* Wk    = (const float*)d_in[3];
    const float* bk    = (const float*)d_in[4];
    const float* Wm    = (const float*)d_in[5];
    const float* bm    = (const float*)d_in[6];
    const float* Wl    = (const float*)d_in[7];
    const float* bl    = (const float*)d_in[8];
    const float* Wv    = (const float*)d_in[9];
    const float* bv    = (const float*)d_in[10];
    const float* diff  = (const float*)d_in[11];
    const float* eps   = (const float*)d_in[12];
    float* out = (float*)d_out;

    cudaFuncSetAttribute(k_proj_mma,   cudaFuncAttributeMaxDynamicSharedMemorySize, PJ_SMEM);
    cudaFuncSetAttribute(k_scores_mma, cudaFuncAttributeMaxDynamicSharedMemorySize, SC_SMEM);
    cudaFuncSetAttribute(k_agg_mma,    cudaFuncAttributeMaxDynamicSharedMemorySize, AGG_SMEM);
    cudaFuncSetAttribute(k_fc_mma,     cudaFuncAttributeMaxDynamicSharedMemorySize, FC_SMEM);

    k_wh<<<(3 * H * H + BH * H) / 256, 256>>>(Wk, Wm, Wl, Wv);
    k_ln<<<NN, 256>>>(h, gamma, beta);
    k_proj_mma<<<dim3(48, 3), 256, PJ_SMEM>>>(bk, bm, bl);
    k_scores_mma<<<dim3(NB, 48, 48), 256, SC_SMEM>>>(diff, eps);
    k_agg_mma<<<dim3(32, NB), 256, AGG_SMEM>>>();
    k_fc_mma<<<48, 256, FC_SMEM>>>(bv, h, out, out_size);
}